// round 1
// baseline (speedup 1.0000x reference)
#include <cuda_runtime.h>
#include <math.h>

// Problem constants
#define NROWS 65536
#define DK    512
#define HH    256
#define H2    128
#define O3    64
#define NRB   512           // row blocks of 128

// Scratch (device globals — allocation-free per harness rules)
__device__ float g_hraw[2 * NROWS * HH];     // 128 MB : pre-BN activations
__device__ float g_h[2 * NROWS * H2];        //  64 MB : post-GEMM2 activations
__device__ float g_psum[2 * NRB * HH];       // per-rowblock column sums
__device__ float g_psq [2 * NRB * HH];       // per-rowblock column sums of squares
__device__ float g_scale[2 * HH];
__device__ float g_shift[2 * HH];

// ---------------------------------------------------------------------------
// GEMM1: hraw = X @ W1 + b1   (X in {x1,x2}), plus column stat partials.
// 128x128 tile, BK=8, 8x8 per thread, 256 threads.
// ---------------------------------------------------------------------------
__global__ void __launch_bounds__(256) gemm1_kernel(
    const float* __restrict__ x1, const float* __restrict__ x2,
    const float* __restrict__ W1, const float* __restrict__ b1)
{
    const int z   = blockIdx.z;
    const float* __restrict__ X = z ? x2 : x1;
    const int cb  = blockIdx.x;        // 0..1
    const int rb  = blockIdx.y;        // 0..511
    const int row0 = rb * 128;
    const int col0 = cb * 128;
    const int tid = threadIdx.x;
    const int tx  = tid & 15;
    const int ty  = tid >> 4;

    __shared__ float As[8][128];
    __shared__ float Bs[8][128];
    __shared__ float redS[16][128];
    __shared__ float redQ[16][128];

    float acc[8][8];
#pragma unroll
    for (int i = 0; i < 8; i++)
#pragma unroll
        for (int j = 0; j < 8; j++) acc[i][j] = 0.0f;

    const int arow = tid >> 1;
    const int acol = (tid & 1) * 4;
    const int brow = tid >> 5;
    const int bcol = (tid & 31) * 4;

    for (int kk = 0; kk < DK; kk += 8) {
        float4 av = *reinterpret_cast<const float4*>(
            &X[(size_t)(row0 + arow) * DK + kk + acol]);
        As[acol + 0][arow] = av.x;
        As[acol + 1][arow] = av.y;
        As[acol + 2][arow] = av.z;
        As[acol + 3][arow] = av.w;
        *reinterpret_cast<float4*>(&Bs[brow][bcol]) =
            *reinterpret_cast<const float4*>(&W1[(size_t)(kk + brow) * HH + col0 + bcol]);
        __syncthreads();
#pragma unroll
        for (int k = 0; k < 8; k++) {
            float a[8], b[8];
#pragma unroll
            for (int i = 0; i < 8; i++) a[i] = As[k][ty * 8 + i];
#pragma unroll
            for (int j = 0; j < 8; j++) b[j] = Bs[k][tx * 8 + j];
#pragma unroll
            for (int i = 0; i < 8; i++)
#pragma unroll
                for (int j = 0; j < 8; j++)
                    acc[i][j] = fmaf(a[i], b[j], acc[i][j]);
        }
        __syncthreads();
    }

    // Epilogue: +bias, store hraw, column partial stats.
    float bias[8];
#pragma unroll
    for (int j = 0; j < 8; j++) bias[j] = b1[col0 + tx * 8 + j];

    float csum[8], csq[8];
#pragma unroll
    for (int j = 0; j < 8; j++) { csum[j] = 0.0f; csq[j] = 0.0f; }

#pragma unroll
    for (int i = 0; i < 8; i++) {
        const int row = row0 + ty * 8 + i;
        float v[8];
#pragma unroll
        for (int j = 0; j < 8; j++) {
            v[j] = acc[i][j] + bias[j];
            csum[j] += v[j];
            csq[j]  += v[j] * v[j];
        }
        float* dst = &g_hraw[((size_t)z * NROWS + row) * HH + col0 + tx * 8];
        float4 s0 = make_float4(v[0], v[1], v[2], v[3]);
        float4 s1 = make_float4(v[4], v[5], v[6], v[7]);
        *reinterpret_cast<float4*>(dst + 0) = s0;
        *reinterpret_cast<float4*>(dst + 4) = s1;
    }

#pragma unroll
    for (int j = 0; j < 8; j++) {
        redS[ty][tx * 8 + j] = csum[j];
        redQ[ty][tx * 8 + j] = csq[j];
    }
    __syncthreads();
    for (int s = 8; s > 0; s >>= 1) {
        if (ty < s) {
#pragma unroll
            for (int j = 0; j < 8; j++) {
                redS[ty][tx * 8 + j] += redS[ty + s][tx * 8 + j];
                redQ[ty][tx * 8 + j] += redQ[ty + s][tx * 8 + j];
            }
        }
        __syncthreads();
    }
    if (ty == 0) {
#pragma unroll
        for (int j = 0; j < 8; j++) {
            g_psum[((size_t)z * NRB + rb) * HH + col0 + tx * 8 + j] = redS[0][tx * 8 + j];
            g_psq [((size_t)z * NRB + rb) * HH + col0 + tx * 8 + j] = redQ[0][tx * 8 + j];
        }
    }
}

// ---------------------------------------------------------------------------
// Stats: reduce 512 partials per column -> BN scale/shift.
// ---------------------------------------------------------------------------
__global__ void stats_kernel(const float* __restrict__ gamma,
                             const float* __restrict__ beta_bn)
{
    const int idx = blockIdx.x * blockDim.x + threadIdx.x;
    if (idx >= 2 * HH) return;
    const int z = idx / HH;
    const int c = idx % HH;
    float s = 0.0f, q = 0.0f;
    for (int rb = 0; rb < NRB; rb++) {
        s += g_psum[((size_t)z * NRB + rb) * HH + c];
        q += g_psq [((size_t)z * NRB + rb) * HH + c];
    }
    const float mean = s / (float)NROWS;
    const float var  = q / (float)NROWS - mean * mean;
    const float sc   = gamma[c] * rsqrtf(var + 1e-5f);
    g_scale[z * HH + c] = sc;
    g_shift[z * HH + c] = beta_bn[c] - mean * sc;
}

// ---------------------------------------------------------------------------
// GEMM2: h = relu( relu(BN(hraw)) @ W2 + b2 ).  M=65536, N=128, K=256.
// BN+relu applied on the A-tile load.
// ---------------------------------------------------------------------------
__global__ void __launch_bounds__(256) gemm2_kernel(
    const float* __restrict__ W2, const float* __restrict__ b2)
{
    const int z   = blockIdx.z;
    const int rb  = blockIdx.y;
    const int row0 = rb * 128;
    const int tid = threadIdx.x;
    const int tx  = tid & 15;
    const int ty  = tid >> 4;

    __shared__ float As[8][128];
    __shared__ float Bs[8][128];
    __shared__ float scs[HH];
    __shared__ float shs[HH];

    scs[tid] = g_scale[z * HH + tid];
    shs[tid] = g_shift[z * HH + tid];

    float acc[8][8];
#pragma unroll
    for (int i = 0; i < 8; i++)
#pragma unroll
        for (int j = 0; j < 8; j++) acc[i][j] = 0.0f;

    const int arow = tid >> 1;
    const int acol = (tid & 1) * 4;
    const int brow = tid >> 5;
    const int bcol = (tid & 31) * 4;

    for (int kk = 0; kk < HH; kk += 8) {
        float4 av = *reinterpret_cast<const float4*>(
            &g_hraw[((size_t)z * NROWS + row0 + arow) * HH + kk + acol]);
        __syncthreads();   // also covers scs/shs on first iteration
        As[acol + 0][arow] = fmaxf(scs[kk + acol + 0] * av.x + shs[kk + acol + 0], 0.0f);
        As[acol + 1][arow] = fmaxf(scs[kk + acol + 1] * av.y + shs[kk + acol + 1], 0.0f);
        As[acol + 2][arow] = fmaxf(scs[kk + acol + 2] * av.z + shs[kk + acol + 2], 0.0f);
        As[acol + 3][arow] = fmaxf(scs[kk + acol + 3] * av.w + shs[kk + acol + 3], 0.0f);
        *reinterpret_cast<float4*>(&Bs[brow][bcol]) =
            *reinterpret_cast<const float4*>(&W2[(size_t)(kk + brow) * H2 + bcol]);
        __syncthreads();
#pragma unroll
        for (int k = 0; k < 8; k++) {
            float a[8], b[8];
#pragma unroll
            for (int i = 0; i < 8; i++) a[i] = As[k][ty * 8 + i];
#pragma unroll
            for (int j = 0; j < 8; j++) b[j] = Bs[k][tx * 8 + j];
#pragma unroll
            for (int i = 0; i < 8; i++)
#pragma unroll
                for (int j = 0; j < 8; j++)
                    acc[i][j] = fmaf(a[i], b[j], acc[i][j]);
        }
    }

    float bias[8];
#pragma unroll
    for (int j = 0; j < 8; j++) bias[j] = b2[tx * 8 + j];

#pragma unroll
    for (int i = 0; i < 8; i++) {
        const int row = row0 + ty * 8 + i;
        float v[8];
#pragma unroll
        for (int j = 0; j < 8; j++) v[j] = fmaxf(acc[i][j] + bias[j], 0.0f);
        float* dst = &g_h[((size_t)z * NROWS + row) * H2 + tx * 8];
        *reinterpret_cast<float4*>(dst + 0) = make_float4(v[0], v[1], v[2], v[3]);
        *reinterpret_cast<float4*>(dst + 4) = make_float4(v[4], v[5], v[6], v[7]);
    }
}

// ---------------------------------------------------------------------------
// Final head: cosine + combined@W3 -> relu -> @W4 -> sigmoid -> blend -> clip.
// 64-row tile per block, 256 threads (4 threads per row), W3 fully in smem.
// Dynamic smem: h1[64][132] + h2[64][132] + W3[384][64] = 165,888 B.
// ---------------------------------------------------------------------------
#define HPAD 132
#define FINAL_SMEM ((64 * HPAD * 2 + 384 * O3) * (int)sizeof(float))

__global__ void __launch_bounds__(256) final_kernel(
    const float* __restrict__ W3, const float* __restrict__ b3,
    const float* __restrict__ W4, const float* __restrict__ b4,
    const float* __restrict__ alphap, const float* __restrict__ betap,
    float* __restrict__ out)
{
    extern __shared__ float smem[];
    float* h1s = smem;                      // 64 * 132
    float* h2s = h1s + 64 * HPAD;           // 64 * 132
    float* W3s = h2s + 64 * HPAD;           // 384 * 64

    const int rb   = blockIdx.x;
    const int row0 = rb * 64;
    const int tid  = threadIdx.x;

    // Load h1/h2 tiles (64 x 128 each) with float4, padded stride 132.
    for (int i = tid; i < 64 * 32; i += 256) {
        const int r = i >> 5;
        const int c = (i & 31) << 2;
        float4 v1 = *reinterpret_cast<const float4*>(
            &g_h[((size_t)0 * NROWS + row0 + r) * H2 + c]);
        float4 v2 = *reinterpret_cast<const float4*>(
            &g_h[((size_t)1 * NROWS + row0 + r) * H2 + c]);
        *reinterpret_cast<float4*>(&h1s[r * HPAD + c]) = v1;
        *reinterpret_cast<float4*>(&h2s[r * HPAD + c]) = v2;
    }
    // Load W3 (384 x 64 = 6144 float4).
    for (int i = tid; i < 6144; i += 256) {
        reinterpret_cast<float4*>(W3s)[i] =
            reinterpret_cast<const float4*>(W3)[i];
    }
    __syncthreads();

    const int r  = tid >> 2;   // row within tile, 0..63
    const int q  = tid & 3;    // quarter, 0..3
    const int c0 = q * 16;     // 16 GEMM3 columns per thread

    const float* h1r = &h1s[r * HPAD];
    const float* h2r = &h2s[r * HPAD];

    // Cosine partials over k-quarter [q*32, q*32+32).
    float dot = 0.0f, n1 = 0.0f, n2 = 0.0f;
    for (int k = q * 32; k < q * 32 + 32; k += 4) {
        float4 a = *reinterpret_cast<const float4*>(&h1r[k]);
        float4 b = *reinterpret_cast<const float4*>(&h2r[k]);
        dot += a.x * b.x + a.y * b.y + a.z * b.z + a.w * b.w;
        n1  += a.x * a.x + a.y * a.y + a.z * a.z + a.w * a.w;
        n2  += b.x * b.x + b.y * b.y + b.z * b.z + b.w * b.w;
    }
    dot += __shfl_xor_sync(0xffffffffu, dot, 1);
    dot += __shfl_xor_sync(0xffffffffu, dot, 2);
    n1  += __shfl_xor_sync(0xffffffffu, n1, 1);
    n1  += __shfl_xor_sync(0xffffffffu, n1, 2);
    n2  += __shfl_xor_sync(0xffffffffu, n2, 1);
    n2  += __shfl_xor_sync(0xffffffffu, n2, 2);

    // GEMM3: combined[384] @ W3[:, c0:c0+16]
    float w4r[16], acc3[16];
#pragma unroll
    for (int j = 0; j < 16; j++) {
        w4r[j]  = W4[c0 + j];
        acc3[j] = b3[c0 + j];
    }
    for (int k = 0; k < 128; k++) {
        const float a = h1r[k];
        const float b = h2r[k];
        const float cm = a * b;
        const float cd = fabsf(a - b);
        const float cs = a + b;
        const float* w0 = &W3s[(k      ) * O3 + c0];
        const float* w1 = &W3s[(k + 128) * O3 + c0];
        const float* w2 = &W3s[(k + 256) * O3 + c0];
#pragma unroll
        for (int j = 0; j < 16; j++) {
            acc3[j] = fmaf(cm, w0[j], acc3[j]);
            acc3[j] = fmaf(cd, w1[j], acc3[j]);
            acc3[j] = fmaf(cs, w2[j], acc3[j]);
        }
    }

    float sl = 0.0f;
#pragma unroll
    for (int j = 0; j < 16; j++) sl += fmaxf(acc3[j], 0.0f) * w4r[j];
    sl += __shfl_xor_sync(0xffffffffu, sl, 1);
    sl += __shfl_xor_sync(0xffffffffu, sl, 2);

    if (q == 0) {
        const float inv1   = 1.0f / fmaxf(sqrtf(n1), 1e-15f);
        const float inv2   = 1.0f / fmaxf(sqrtf(n2), 1e-15f);
        const float s_math = fminf(fmaxf(dot * inv1 * inv2, 0.0f), 1.0f);
        const float sig    = 1.0f / (1.0f + expf(-(sl + b4[0])));
        const float fin    = alphap[0] * s_math + betap[0] * sig;
        out[row0 + r] = fminf(fmaxf(fin, 0.0f), 1.0f);
    }
}

// ---------------------------------------------------------------------------
extern "C" void kernel_launch(void* const* d_in, const int* in_sizes, int n_in,
                              void* d_out, int out_size)
{
    const float* x1      = (const float*)d_in[0];
    const float* x2      = (const float*)d_in[1];
    const float* W1      = (const float*)d_in[2];
    const float* b1      = (const float*)d_in[3];
    const float* gamma   = (const float*)d_in[4];
    const float* beta_bn = (const float*)d_in[5];
    const float* W2      = (const float*)d_in[6];
    const float* b2      = (const float*)d_in[7];
    const float* W3      = (const float*)d_in[8];
    const float* b3      = (const float*)d_in[9];
    const float* W4      = (const float*)d_in[10];
    const float* b4      = (const float*)d_in[11];
    const float* alphap  = (const float*)d_in[12];
    const float* betap   = (const float*)d_in[13];
    float* out = (float*)d_out;

    cudaFuncSetAttribute(final_kernel,
                         cudaFuncAttributeMaxDynamicSharedMemorySize, FINAL_SMEM);

    dim3 g1(2, NRB, 2);
    gemm1_kernel<<<g1, 256>>>(x1, x2, W1, b1);

    stats_kernel<<<1, 512>>>(gamma, beta_bn);

    dim3 g2(1, NRB, 2);
    gemm2_kernel<<<g2, 256>>>(W2, b2);

    final_kernel<<<NROWS / 64, 256, FINAL_SMEM>>>(W3, b3, W4, b4, alphap, betap, out);
}

// round 3
// speedup vs baseline: 2.5921x; 2.5921x over previous
#include <cuda_runtime.h>
#include <cuda_bf16.h>
#include <cstdint>
#include <math.h>

// ---------------------------------------------------------------------------
// Problem constants
// ---------------------------------------------------------------------------
#define NROWS 65536
#define DK    512
#define HH    256
#define H2    128
#define O3    64
#define NRB   512           // row blocks of 128

// ---------------------------------------------------------------------------
// Scratch (device globals — allocation-free per harness rules)
// ---------------------------------------------------------------------------
__device__ float g_hraw[2 * NROWS * HH];     // 128 MB : pre-BN activations
__device__ float g_h[2 * NROWS * H2];        //  64 MB : post-GEMM2 activations
__device__ float g_psum[2 * NRB * HH];
__device__ float g_psq [2 * NRB * HH];
__device__ float g_scale[2 * HH];
__device__ float g_shift[2 * HH];
// Transposed + bf16-split weights (B operands, [N][K] K-major)
__device__ __align__(16) __nv_bfloat16 g_w1hi[HH * DK];
__device__ __align__(16) __nv_bfloat16 g_w1lo[HH * DK];
__device__ __align__(16) __nv_bfloat16 g_w2hi[H2 * HH];
__device__ __align__(16) __nv_bfloat16 g_w2lo[H2 * HH];

// ---------------------------------------------------------------------------
// Warp-MMA helpers (base PTX — no sm_103a-only features)
// ---------------------------------------------------------------------------
__device__ __forceinline__ uint32_t smem_u32(const void* p) {
    uint32_t a;
    asm("{ .reg .u64 t; cvta.to.shared.u64 t, %1; cvt.u32.u64 %0, t; }"
        : "=r"(a) : "l"(p));
    return a;
}

__device__ __forceinline__ void mma_bf16(float& c0, float& c1, float& c2, float& c3,
                                         uint32_t a0, uint32_t a1, uint32_t a2, uint32_t a3,
                                         uint32_t b0, uint32_t b1) {
    asm volatile(
        "mma.sync.aligned.m16n8k16.row.col.f32.bf16.bf16.f32 "
        "{%0,%1,%2,%3}, {%4,%5,%6,%7}, {%8,%9}, {%0,%1,%2,%3};"
        : "+f"(c0), "+f"(c1), "+f"(c2), "+f"(c3)
        : "r"(a0), "r"(a1), "r"(a2), "r"(a3), "r"(b0), "r"(b1));
}

__device__ __forceinline__ void ldmatrix_x4(uint32_t* r, uint32_t addr) {
    asm volatile("ldmatrix.sync.aligned.m8n8.x4.shared.b16 {%0,%1,%2,%3}, [%4];"
        : "=r"(r[0]), "=r"(r[1]), "=r"(r[2]), "=r"(r[3]) : "r"(addr));
}

__device__ __forceinline__ void ldmatrix_x2(uint32_t* r, uint32_t addr) {
    asm volatile("ldmatrix.sync.aligned.m8n8.x2.shared.b16 {%0,%1}, [%2];"
        : "=r"(r[0]), "=r"(r[1]) : "r"(addr));
}

__device__ __forceinline__ void cpasync16(uint32_t dst, const void* src) {
    asm volatile("cp.async.cg.shared.global [%0], [%1], 16;" :: "r"(dst), "l"(src));
}
__device__ __forceinline__ void cpasync_commit() {
    asm volatile("cp.async.commit_group;" ::: "memory");
}
__device__ __forceinline__ void cpasync_wait0() {
    asm volatile("cp.async.wait_group 0;" ::: "memory");
}

__device__ __forceinline__ uint32_t pack_bf(__nv_bfloat16 a, __nv_bfloat16 b) {
    return (uint32_t)__bfloat16_as_ushort(a) |
           ((uint32_t)__bfloat16_as_ushort(b) << 16);
}

// split (x,y) into packed hi/lo bf16 pairs
__device__ __forceinline__ void split2(float x, float y, uint32_t& hi, uint32_t& lo) {
    __nv_bfloat16 hx = __float2bfloat16(x);
    __nv_bfloat16 hy = __float2bfloat16(y);
    float lx = x - __bfloat162float(hx);
    float ly = y - __bfloat162float(hy);
    hi = pack_bf(hx, hy);
    lo = pack_bf(__float2bfloat16(lx), __float2bfloat16(ly));
}

// ---------------------------------------------------------------------------
// Weight prep: transpose + bf16 split W1 -> [256][512], W2 -> [128][256].
// ---------------------------------------------------------------------------
__global__ void prep_weights(const float* __restrict__ W1,
                             const float* __restrict__ W2)
{
    int i = blockIdx.x * 256 + threadIdx.x;
    if (i < DK * HH) {
        int k = i >> 8, n = i & 255;
        float v = W1[i];
        __nv_bfloat16 h = __float2bfloat16(v);
        g_w1hi[n * DK + k] = h;
        g_w1lo[n * DK + k] = __float2bfloat16(v - __bfloat162float(h));
    } else {
        int j = i - DK * HH;
        if (j < HH * H2) {
            int k = j >> 7, n = j & 127;
            float v = W2[j];
            __nv_bfloat16 h = __float2bfloat16(v);
            g_w2hi[n * HH + k] = h;
            g_w2lo[n * HH + k] = __float2bfloat16(v - __bfloat162float(h));
        }
    }
}

// ---------------------------------------------------------------------------
// GEMM1 (mma.sync bf16 hi/lo split): hraw = X @ W1 + b1, plus column stats.
// CTA 128x256, 8 warps (2m x 4n), warp tile 64x64, K-chunks of 64, 2 stages.
// smem stage: Ahi[128][72] Alo[128][72] Bhi[256][72] Blo[256][72] (bf16)
// ---------------------------------------------------------------------------
#define AST 72
#define G1_ABYTES (128 * AST * 2)            // 18432
#define G1_BBYTES (256 * AST * 2)            // 36864
#define G1_STAGE  (2 * G1_ABYTES + 2 * G1_BBYTES)   // 110592
#define G1_DYN    (2 * G1_STAGE)             // 221184

__global__ void __launch_bounds__(256) gemm1_mma(
    const float* __restrict__ x1, const float* __restrict__ x2,
    const float* __restrict__ b1)
{
    extern __shared__ char dyn[];
    const int z    = blockIdx.y;
    const int rb   = blockIdx.x;
    const int row0 = rb * 128;
    const float* __restrict__ X = z ? x2 : x1;

    const int tid  = threadIdx.x;
    const int lane = tid & 31;
    const int wid  = tid >> 5;
    const int wm   = wid >> 2;       // 0..1
    const int wn   = wid & 3;        // 0..3
    const int g    = lane >> 2;      // 0..7
    const int tg   = lane & 3;       // 0..3
    const int ln16 = lane & 15;
    const int lhalf = (lane >> 4) & 1;

    float acc[4][8][4];
#pragma unroll
    for (int t = 0; t < 4; t++)
#pragma unroll
        for (int u = 0; u < 8; u++)
#pragma unroll
            for (int j = 0; j < 4; j++) acc[t][u][j] = 0.0f;

    float4 aNext[8];

    // ---- helpers (macros to avoid lambdas/regs churn) ----
#define G1_LDA(c) do { \
        const int kk_ = (c) * 64; \
        _Pragma("unroll") \
        for (int it = 0; it < 8; it++) { \
            int idx = tid + it * 256; \
            int r_  = idx >> 4, c4_ = idx & 15; \
            aNext[it] = *reinterpret_cast<const float4*>( \
                X + (size_t)(row0 + r_) * DK + kk_ + c4_ * 4); \
        } \
    } while (0)

#define G1_STA(stg) do { \
        char* sAhi_ = dyn + (stg) * G1_STAGE; \
        char* sAlo_ = sAhi_ + G1_ABYTES; \
        _Pragma("unroll") \
        for (int it = 0; it < 8; it++) { \
            int idx = tid + it * 256; \
            int r_  = idx >> 4, c4_ = idx & 15; \
            uint32_t h0, l0, h1, l1; \
            split2(aNext[it].x, aNext[it].y, h0, l0); \
            split2(aNext[it].z, aNext[it].w, h1, l1); \
            int off = (r_ * AST + c4_ * 4) * 2; \
            *reinterpret_cast<uint2*>(sAhi_ + off) = make_uint2(h0, h1); \
            *reinterpret_cast<uint2*>(sAlo_ + off) = make_uint2(l0, l1); \
        } \
    } while (0)

#define G1_CPB(c, stg) do { \
        const int kk_ = (c) * 64; \
        char* sBhi_ = dyn + (stg) * G1_STAGE + 2 * G1_ABYTES; \
        char* sBlo_ = sBhi_ + G1_BBYTES; \
        uint32_t bhiU = smem_u32(sBhi_), bloU = smem_u32(sBlo_); \
        _Pragma("unroll") \
        for (int it = 0; it < 8; it++) { \
            int idx = tid + it * 256; \
            int n_ = idx >> 3, c8_ = idx & 7; \
            int off = (n_ * AST + c8_ * 8) * 2; \
            cpasync16(bhiU + off, g_w1hi + (size_t)n_ * DK + kk_ + c8_ * 8); \
            cpasync16(bloU + off, g_w1lo + (size_t)n_ * DK + kk_ + c8_ * 8); \
        } \
        cpasync_commit(); \
    } while (0)

    // ---- prologue: chunk 0 ----
    G1_CPB(0, 0);
    G1_LDA(0);
    G1_STA(0);
    cpasync_wait0();
    __syncthreads();

    const int NC = DK / 64;   // 8
    for (int c = 0; c < NC; c++) {
        const int s = c & 1;
        if (c + 1 < NC) {
            G1_CPB(c + 1, s ^ 1);
            G1_LDA(c + 1);
        }

        // ---- compute chunk c from stage s ----
        {
            char* st = dyn + s * G1_STAGE;
            uint32_t sAhiU = smem_u32(st);
            uint32_t sAloU = sAhiU + G1_ABYTES;
            uint32_t sBhiU = sAhiU + 2 * G1_ABYTES;
            uint32_t sBloU = sBhiU + G1_BBYTES;

            // lane-dependent base offsets (bytes)
            const uint32_t aOff = ((wm * 64 + ln16) * AST + lhalf * 8) * 2;
            const uint32_t bOff = (((wn * 64) + (ln16 & 7)) * AST + ((ln16 >> 3) * 8)) * 2;

#pragma unroll
            for (int ks = 0; ks < 4; ks++) {
                const uint32_t ko = ks * 16 * 2;   // bytes
                uint32_t Ah[4][4], Al[4][4], Bh[8][2], Bl[8][2];
#pragma unroll
                for (int t = 0; t < 4; t++)
                    ldmatrix_x4(Ah[t], sAhiU + aOff + (t * 16 * AST) * 2 + ko);
#pragma unroll
                for (int u = 0; u < 8; u++)
                    ldmatrix_x2(Bh[u], sBhiU + bOff + (u * 8 * AST) * 2 + ko);
#pragma unroll
                for (int t = 0; t < 4; t++)
#pragma unroll
                    for (int u = 0; u < 8; u++)
                        mma_bf16(acc[t][u][0], acc[t][u][1], acc[t][u][2], acc[t][u][3],
                                 Ah[t][0], Ah[t][1], Ah[t][2], Ah[t][3],
                                 Bh[u][0], Bh[u][1]);
#pragma unroll
                for (int u = 0; u < 8; u++)
                    ldmatrix_x2(Bl[u], sBloU + bOff + (u * 8 * AST) * 2 + ko);
#pragma unroll
                for (int t = 0; t < 4; t++)
#pragma unroll
                    for (int u = 0; u < 8; u++)
                        mma_bf16(acc[t][u][0], acc[t][u][1], acc[t][u][2], acc[t][u][3],
                                 Ah[t][0], Ah[t][1], Ah[t][2], Ah[t][3],
                                 Bl[u][0], Bl[u][1]);
#pragma unroll
                for (int t = 0; t < 4; t++)
                    ldmatrix_x4(Al[t], sAloU + aOff + (t * 16 * AST) * 2 + ko);
#pragma unroll
                for (int t = 0; t < 4; t++)
#pragma unroll
                    for (int u = 0; u < 8; u++)
                        mma_bf16(acc[t][u][0], acc[t][u][1], acc[t][u][2], acc[t][u][3],
                                 Al[t][0], Al[t][1], Al[t][2], Al[t][3],
                                 Bh[u][0], Bh[u][1]);
            }
        }

        if (c + 1 < NC) {
            G1_STA(s ^ 1);
            cpasync_wait0();
            __syncthreads();
        }
    }

    // ---- epilogue: bias, store hraw, column stats ----
    float css0[8], css1[8], cqq0[8], cqq1[8];
#pragma unroll
    for (int u = 0; u < 8; u++) {
        const int col = wn * 64 + u * 8 + tg * 2;
        const float bi0 = b1[col], bi1 = b1[col + 1];
        float cs0 = 0.f, cs1 = 0.f, cq0 = 0.f, cq1 = 0.f;
#pragma unroll
        for (int t = 0; t < 4; t++) {
            const int r = row0 + wm * 64 + t * 16 + g;
            float v0 = acc[t][u][0] + bi0;
            float v1 = acc[t][u][1] + bi1;
            float v2 = acc[t][u][2] + bi0;
            float v3 = acc[t][u][3] + bi1;
            *reinterpret_cast<float2*>(
                &g_hraw[((size_t)z * NROWS + r) * HH + col])     = make_float2(v0, v1);
            *reinterpret_cast<float2*>(
                &g_hraw[((size_t)z * NROWS + r + 8) * HH + col]) = make_float2(v2, v3);
            cs0 += v0 + v2; cs1 += v1 + v3;
            cq0 += v0 * v0 + v2 * v2; cq1 += v1 * v1 + v3 * v3;
        }
        css0[u] = cs0; css1[u] = cs1; cqq0[u] = cq0; cqq1[u] = cq1;
    }
#pragma unroll
    for (int off = 4; off < 32; off <<= 1) {
#pragma unroll
        for (int u = 0; u < 8; u++) {
            css0[u] += __shfl_xor_sync(0xffffffffu, css0[u], off);
            css1[u] += __shfl_xor_sync(0xffffffffu, css1[u], off);
            cqq0[u] += __shfl_xor_sync(0xffffffffu, cqq0[u], off);
            cqq1[u] += __shfl_xor_sync(0xffffffffu, cqq1[u], off);
        }
    }
    float* s_ps = reinterpret_cast<float*>(dyn);          // [2][256] (stage0 free)
    float* s_sq = s_ps + 512;
    __syncthreads();   // ensure all warps done with smem stages
    if (g == 0) {
#pragma unroll
        for (int u = 0; u < 8; u++) {
            const int col = wn * 64 + u * 8 + tg * 2;
            s_ps[wm * 256 + col]     = css0[u];
            s_ps[wm * 256 + col + 1] = css1[u];
            s_sq[wm * 256 + col]     = cqq0[u];
            s_sq[wm * 256 + col + 1] = cqq1[u];
        }
    }
    __syncthreads();
    if (tid < 256) {
        g_psum[((size_t)z * NRB + rb) * HH + tid] = s_ps[tid] + s_ps[256 + tid];
        g_psq [((size_t)z * NRB + rb) * HH + tid] = s_sq[tid] + s_sq[256 + tid];
    }
#undef G1_LDA
#undef G1_STA
#undef G1_CPB
}

// ---------------------------------------------------------------------------
// Stats: reduce 512 partials per column -> BN scale/shift.
// ---------------------------------------------------------------------------
__global__ void stats_kernel(const float* __restrict__ gamma,
                             const float* __restrict__ beta_bn)
{
    const int idx = blockIdx.x * blockDim.x + threadIdx.x;
    if (idx >= 2 * HH) return;
    const int z = idx / HH;
    const int c = idx % HH;
    float s = 0.0f, q = 0.0f;
    for (int rbk = 0; rbk < NRB; rbk++) {
        s += g_psum[((size_t)z * NRB + rbk) * HH + c];
        q += g_psq [((size_t)z * NRB + rbk) * HH + c];
    }
    const float mean = s / (float)NROWS;
    const float var  = q / (float)NROWS - mean * mean;
    const float sc   = gamma[c] * rsqrtf(var + 1e-5f);
    g_scale[z * HH + c] = sc;
    g_shift[z * HH + c] = beta_bn[c] - mean * sc;
}

// ---------------------------------------------------------------------------
// GEMM2 (mma.sync): h = relu( relu(BN(hraw)) @ W2 + b2 ).
// CTA 128x128, 8 warps (2m x 4n), warp tile 64x32. B resident in smem.
// smem: Bhi[128][264] Blo[128][264] | A stages (2 x (Ahi+Alo 128x72))
// ---------------------------------------------------------------------------
#define BST2 264
#define G2_BBYTES (128 * BST2 * 2)           // 67584 per matrix
#define G2_ABYTES (128 * AST * 2)            // 18432
#define G2_ASTAGE (2 * G2_ABYTES)            // 36864
#define G2_DYN    (2 * G2_BBYTES + 2 * G2_ASTAGE)   // 208896

__global__ void __launch_bounds__(256) gemm2_mma(const float* __restrict__ b2)
{
    extern __shared__ char dyn[];
    __shared__ float s_sc[HH];
    __shared__ float s_sh[HH];

    const int z    = blockIdx.y;
    const int rb   = blockIdx.x;
    const int row0 = rb * 128;
    const int tid  = threadIdx.x;
    const int lane = tid & 31;
    const int wid  = tid >> 5;
    const int wm   = wid >> 2;       // 0..1
    const int wn   = wid & 3;        // 0..3
    const int g    = lane >> 2;
    const int tg   = lane & 3;
    const int ln16 = lane & 15;
    const int lhalf = (lane >> 4) & 1;

    char* sBhi = dyn;
    char* sBlo = dyn + G2_BBYTES;
    char* sA0  = dyn + 2 * G2_BBYTES;

    s_sc[tid] = g_scale[z * HH + tid];
    s_sh[tid] = g_shift[z * HH + tid];

    // B load (once): 128 rows x 256 bf16 each (hi, lo) via cp.async
    {
        uint32_t bhiU = smem_u32(sBhi), bloU = smem_u32(sBlo);
#pragma unroll
        for (int it = 0; it < 16; it++) {
            int idx = tid + it * 256;
            int n_ = idx >> 5, c8_ = idx & 31;
            int off = (n_ * BST2 + c8_ * 8) * 2;
            cpasync16(bhiU + off, g_w2hi + (size_t)n_ * HH + c8_ * 8);
            cpasync16(bloU + off, g_w2lo + (size_t)n_ * HH + c8_ * 8);
        }
        cpasync_commit();
    }

    float acc[4][4][4];
#pragma unroll
    for (int t = 0; t < 4; t++)
#pragma unroll
        for (int u = 0; u < 4; u++)
#pragma unroll
            for (int j = 0; j < 4; j++) acc[t][u][j] = 0.0f;

    float4 aNext[8];

#define G2_LDA(c) do { \
        const int kk_ = (c) * 64; \
        _Pragma("unroll") \
        for (int it = 0; it < 8; it++) { \
            int idx = tid + it * 256; \
            int r_  = idx >> 4, c4_ = idx & 15; \
            aNext[it] = *reinterpret_cast<const float4*>( \
                g_hraw + ((size_t)z * NROWS + row0 + r_) * HH + kk_ + c4_ * 4); \
        } \
    } while (0)

#define G2_STA(c, stg) do { \
        const int kk_ = (c) * 64; \
        char* sAhi_ = sA0 + (stg) * G2_ASTAGE; \
        char* sAlo_ = sAhi_ + G2_ABYTES; \
        _Pragma("unroll") \
        for (int it = 0; it < 8; it++) { \
            int idx = tid + it * 256; \
            int r_  = idx >> 4, c4_ = idx & 15; \
            const int col = kk_ + c4_ * 4; \
            float a0 = fmaxf(s_sc[col + 0] * aNext[it].x + s_sh[col + 0], 0.0f); \
            float a1 = fmaxf(s_sc[col + 1] * aNext[it].y + s_sh[col + 1], 0.0f); \
            float a2 = fmaxf(s_sc[col + 2] * aNext[it].z + s_sh[col + 2], 0.0f); \
            float a3 = fmaxf(s_sc[col + 3] * aNext[it].w + s_sh[col + 3], 0.0f); \
            uint32_t h0, l0, h1, l1; \
            split2(a0, a1, h0, l0); \
            split2(a2, a3, h1, l1); \
            int off = (r_ * AST + c4_ * 4) * 2; \
            *reinterpret_cast<uint2*>(sAhi_ + off) = make_uint2(h0, h1); \
            *reinterpret_cast<uint2*>(sAlo_ + off) = make_uint2(l0, l1); \
        } \
    } while (0)

    G2_LDA(0);
    cpasync_wait0();           // B resident
    __syncthreads();           // s_sc/s_sh + B visible
    G2_STA(0, 0);
    __syncthreads();

    const uint32_t sBhiU = smem_u32(sBhi);
    const uint32_t sBloU = smem_u32(sBlo);
    const uint32_t bOff  = (((wn * 32) + (ln16 & 7)) * BST2 + ((ln16 >> 3) * 8)) * 2;

    const int NC = HH / 64;    // 4
    for (int c = 0; c < NC; c++) {
        const int s = c & 1;
        if (c + 1 < NC) G2_LDA(c + 1);

        {
            char* sAhi_ = sA0 + s * G2_ASTAGE;
            uint32_t sAhiU = smem_u32(sAhi_);
            uint32_t sAloU = sAhiU + G2_ABYTES;
            const uint32_t aOff = ((wm * 64 + ln16) * AST + lhalf * 8) * 2;
            const uint32_t koB  = (c * 64) * 2;      // B col offset (global k)

#pragma unroll
            for (int ks = 0; ks < 4; ks++) {
                const uint32_t ko = ks * 16 * 2;
                uint32_t Ah[4][4], Al[4][4], Bh[4][2], Bl[4][2];
#pragma unroll
                for (int t = 0; t < 4; t++)
                    ldmatrix_x4(Ah[t], sAhiU + aOff + (t * 16 * AST) * 2 + ko);
#pragma unroll
                for (int u = 0; u < 4; u++)
                    ldmatrix_x2(Bh[u], sBhiU + bOff + (u * 8 * BST2) * 2 + koB + ko);
#pragma unroll
                for (int t = 0; t < 4; t++)
#pragma unroll
                    for (int u = 0; u < 4; u++)
                        mma_bf16(acc[t][u][0], acc[t][u][1], acc[t][u][2], acc[t][u][3],
                                 Ah[t][0], Ah[t][1], Ah[t][2], Ah[t][3],
                                 Bh[u][0], Bh[u][1]);
#pragma unroll
                for (int u = 0; u < 4; u++)
                    ldmatrix_x2(Bl[u], sBloU + bOff + (u * 8 * BST2) * 2 + koB + ko);
#pragma unroll
                for (int t = 0; t < 4; t++)
#pragma unroll
                    for (int u = 0; u < 4; u++)
                        mma_bf16(acc[t][u][0], acc[t][u][1], acc[t][u][2], acc[t][u][3],
                                 Ah[t][0], Ah[t][1], Ah[t][2], Ah[t][3],
                                 Bl[u][0], Bl[u][1]);
#pragma unroll
                for (int t = 0; t < 4; t++)
                    ldmatrix_x4(Al[t], sAloU + aOff + (t * 16 * AST) * 2 + ko);
#pragma unroll
                for (int t = 0; t < 4; t++)
#pragma unroll
                    for (int u = 0; u < 4; u++)
                        mma_bf16(acc[t][u][0], acc[t][u][1], acc[t][u][2], acc[t][u][3],
                                 Al[t][0], Al[t][1], Al[t][2], Al[t][3],
                                 Bh[u][0], Bh[u][1]);
            }
        }

        if (c + 1 < NC) {
            __syncthreads();
            G2_STA(c + 1, s ^ 1);
            __syncthreads();
        }
    }

    // epilogue: relu(acc + b2) -> g_h
#pragma unroll
    for (int u = 0; u < 4; u++) {
        const int col = wn * 32 + u * 8 + tg * 2;
        const float bi0 = b2[col], bi1 = b2[col + 1];
#pragma unroll
        for (int t = 0; t < 4; t++) {
            const int r = row0 + wm * 64 + t * 16 + g;
            float v0 = fmaxf(acc[t][u][0] + bi0, 0.0f);
            float v1 = fmaxf(acc[t][u][1] + bi1, 0.0f);
            float v2 = fmaxf(acc[t][u][2] + bi0, 0.0f);
            float v3 = fmaxf(acc[t][u][3] + bi1, 0.0f);
            *reinterpret_cast<float2*>(
                &g_h[((size_t)z * NROWS + r) * H2 + col])     = make_float2(v0, v1);
            *reinterpret_cast<float2*>(
                &g_h[((size_t)z * NROWS + r + 8) * H2 + col]) = make_float2(v2, v3);
        }
    }
#undef G2_LDA
#undef G2_STA
}

// ---------------------------------------------------------------------------
// Final head: 256-row tiles, 4 rows/thread x 16 cols/thread, chunked k.
// smem: W3[384][64] fp32 (96KB) + h chunks [256][36] x2 (72KB).
// ---------------------------------------------------------------------------
#define FROWS 256
#define CHP   36
#define FINAL_SMEM ((384 * O3 + 2 * FROWS * CHP) * (int)sizeof(float))

__global__ void __launch_bounds__(256) final_kernel(
    const float* __restrict__ W3, const float* __restrict__ b3,
    const float* __restrict__ W4, const float* __restrict__ b4,
    const float* __restrict__ alphap, const float* __restrict__ betap,
    float* __restrict__ out)
{
    extern __shared__ float smem[];
    float* W3s = smem;                     // 384*64
    float* ch1 = W3s + 384 * O3;           // 256*36
    float* ch2 = ch1 + FROWS * CHP;        // 256*36

    const int row0 = blockIdx.x * FROWS;
    const int tid  = threadIdx.x;
    const int r0   = tid >> 2;     // 0..63 ; rows r0 + i*64
    const int q    = tid & 3;
    const int c0   = q * 16;

    // W3 -> smem (6144 float4)
#pragma unroll
    for (int it = 0; it < 24; it++) {
        int i = tid + it * 256;
        reinterpret_cast<float4*>(W3s)[i] = reinterpret_cast<const float4*>(W3)[i];
    }

    float acc3[4][16];
#pragma unroll
    for (int i = 0; i < 4; i++)
#pragma unroll
        for (int j = 0; j < 16; j++) acc3[i][j] = 0.0f;
    float dot[4] = {0, 0, 0, 0}, n1[4] = {0, 0, 0, 0}, n2[4] = {0, 0, 0, 0};

    for (int kc = 0; kc < 4; kc++) {
        const int k0 = kc * 32;
        __syncthreads();
        // load h chunks: 256 rows x 32 cols
#pragma unroll
        for (int it = 0; it < 8; it++) {
            int idx = tid + it * 256;
            int r = idx >> 3, c4 = (idx & 7) * 4;
            *reinterpret_cast<float4*>(&ch1[r * CHP + c4]) =
                *reinterpret_cast<const float4*>(
                    &g_h[((size_t)0 * NROWS + row0 + r) * H2 + k0 + c4]);
            *reinterpret_cast<float4*>(&ch2[r * CHP + c4]) =
                *reinterpret_cast<const float4*>(
                    &g_h[((size_t)1 * NROWS + row0 + r) * H2 + k0 + c4]);
        }
        __syncthreads();

#pragma unroll 4
        for (int k = 0; k < 32; k++) {
            const int kg = k0 + k;
            float4 w0a = *reinterpret_cast<const float4*>(&W3s[kg * O3 + c0]);
            float4 w0b = *reinterpret_cast<const float4*>(&W3s[kg * O3 + c0 + 4]);
            float4 w0c = *reinterpret_cast<const float4*>(&W3s[kg * O3 + c0 + 8]);
            float4 w0d = *reinterpret_cast<const float4*>(&W3s[kg * O3 + c0 + 12]);
            float4 w1a = *reinterpret_cast<const float4*>(&W3s[(kg + 128) * O3 + c0]);
            float4 w1b = *reinterpret_cast<const float4*>(&W3s[(kg + 128) * O3 + c0 + 4]);
            float4 w1c = *reinterpret_cast<const float4*>(&W3s[(kg + 128) * O3 + c0 + 8]);
            float4 w1d = *reinterpret_cast<const float4*>(&W3s[(kg + 128) * O3 + c0 + 12]);
            float4 w2a = *reinterpret_cast<const float4*>(&W3s[(kg + 256) * O3 + c0]);
            float4 w2b = *reinterpret_cast<const float4*>(&W3s[(kg + 256) * O3 + c0 + 4]);
            float4 w2c = *reinterpret_cast<const float4*>(&W3s[(kg + 256) * O3 + c0 + 8]);
            float4 w2d = *reinterpret_cast<const float4*>(&W3s[(kg + 256) * O3 + c0 + 12]);
            const float w0r[16] = {w0a.x, w0a.y, w0a.z, w0a.w, w0b.x, w0b.y, w0b.z, w0b.w,
                                   w0c.x, w0c.y, w0c.z, w0c.w, w0d.x, w0d.y, w0d.z, w0d.w};
            const float w1r[16] = {w1a.x, w1a.y, w1a.z, w1a.w, w1b.x, w1b.y, w1b.z, w1b.w,
                                   w1c.x, w1c.y, w1c.z, w1c.w, w1d.x, w1d.y, w1d.z, w1d.w};
            const float w2r[16] = {w2a.x, w2a.y, w2a.z, w2a.w, w2b.x, w2b.y, w2b.z, w2b.w,
                                   w2c.x, w2c.y, w2c.z, w2c.w, w2d.x, w2d.y, w2d.z, w2d.w};
#pragma unroll
            for (int i = 0; i < 4; i++) {
                const float a = ch1[(r0 + i * 64) * CHP + k];
                const float b = ch2[(r0 + i * 64) * CHP + k];
                const float cm = a * b;
                const float cd = fabsf(a - b);
                const float cs = a + b;
                dot[i] += cm;
                n1[i]  = fmaf(a, a, n1[i]);
                n2[i]  = fmaf(b, b, n2[i]);
#pragma unroll
                for (int j = 0; j < 16; j++) {
                    acc3[i][j] = fmaf(cm, w0r[j], acc3[i][j]);
                    acc3[i][j] = fmaf(cd, w1r[j], acc3[i][j]);
                    acc3[i][j] = fmaf(cs, w2r[j], acc3[i][j]);
                }
            }
        }
    }

    // reduce 16 cols -> s_learn partial, then sum over q lanes
    float b3r[16], w4r[16];
#pragma unroll
    for (int j = 0; j < 16; j++) { b3r[j] = b3[c0 + j]; w4r[j] = W4[c0 + j]; }

    const float alpha = alphap[0], beta = betap[0], b4v = b4[0];
#pragma unroll
    for (int i = 0; i < 4; i++) {
        float sl = 0.0f;
#pragma unroll
        for (int j = 0; j < 16; j++)
            sl += fmaxf(acc3[i][j] + b3r[j], 0.0f) * w4r[j];
        sl += __shfl_xor_sync(0xffffffffu, sl, 1);
        sl += __shfl_xor_sync(0xffffffffu, sl, 2);
        if (q == 0) {
            const float inv1   = 1.0f / fmaxf(sqrtf(n1[i]), 1e-15f);
            const float inv2   = 1.0f / fmaxf(sqrtf(n2[i]), 1e-15f);
            const float s_math = fminf(fmaxf(dot[i] * inv1 * inv2, 0.0f), 1.0f);
            const float sig    = 1.0f / (1.0f + expf(-(sl + b4v)));
            const float fin    = alpha * s_math + beta * sig;
            out[row0 + r0 + i * 64] = fminf(fmaxf(fin, 0.0f), 1.0f);
        }
    }
}

// ---------------------------------------------------------------------------
extern "C" void kernel_launch(void* const* d_in, const int* in_sizes, int n_in,
                              void* d_out, int out_size)
{
    const float* x1      = (const float*)d_in[0];
    const float* x2      = (const float*)d_in[1];
    const float* W1      = (const float*)d_in[2];
    const float* b1      = (const float*)d_in[3];
    const float* gamma   = (const float*)d_in[4];
    const float* beta_bn = (const float*)d_in[5];
    const float* W2      = (const float*)d_in[6];
    const float* b2      = (const float*)d_in[7];
    const float* W3      = (const float*)d_in[8];
    const float* b3      = (const float*)d_in[9];
    const float* W4      = (const float*)d_in[10];
    const float* b4      = (const float*)d_in[11];
    const float* alphap  = (const float*)d_in[12];
    const float* betap   = (const float*)d_in[13];
    float* out = (float*)d_out;

    cudaFuncSetAttribute(gemm1_mma,
                         cudaFuncAttributeMaxDynamicSharedMemorySize, G1_DYN);
    cudaFuncSetAttribute(gemm2_mma,
                         cudaFuncAttributeMaxDynamicSharedMemorySize, G2_DYN);
    cudaFuncSetAttribute(final_kernel,
                         cudaFuncAttributeMaxDynamicSharedMemorySize, FINAL_SMEM);

    prep_weights<<<(DK * HH + HH * H2 + 255) / 256, 256>>>(W1, W2);

    dim3 g1(NRB, 2);
    gemm1_mma<<<g1, 256, G1_DYN>>>(x1, x2, b1);

    stats_kernel<<<1, 512>>>(gamma, beta_bn);

    dim3 g2(NRB, 2);
    gemm2_mma<<<g2, 256, G2_DYN>>>(b2);

    final_kernel<<<NROWS / FROWS, 256, FINAL_SMEM>>>(W3, b3, W4, b4,
                                                     alphap, betap, out);
}

// round 4
// speedup vs baseline: 3.0339x; 1.1704x over previous
#include <cuda_runtime.h>
#include <cuda_bf16.h>
#include <cstdint>
#include <math.h>

// ---------------------------------------------------------------------------
// Problem constants
// ---------------------------------------------------------------------------
#define NROWS 65536
#define DK    512
#define HH    256
#define H2    128
#define O3    64
#define NRB   512           // row blocks of 128

// ---------------------------------------------------------------------------
// Scratch (device globals — allocation-free per harness rules)
// ---------------------------------------------------------------------------
__device__ float g_hraw[2 * NROWS * HH];     // 128 MB : pre-BN activations
__device__ float g_psum[2 * NRB * HH];
__device__ float g_psq [2 * NRB * HH];
__device__ float g_scale[2 * HH];
__device__ float g_shift[2 * HH];
// Transposed + bf16-split weights (B operands, [N][K] K-major)
__device__ __align__(16) __nv_bfloat16 g_w1hi[HH * DK];
__device__ __align__(16) __nv_bfloat16 g_w1lo[HH * DK];
__device__ __align__(16) __nv_bfloat16 g_w2hi[H2 * HH];
__device__ __align__(16) __nv_bfloat16 g_w2lo[H2 * HH];
__device__ __align__(16) __nv_bfloat16 g_w3hi[O3 * 384];
__device__ __align__(16) __nv_bfloat16 g_w3lo[O3 * 384];

// ---------------------------------------------------------------------------
// Warp-MMA helpers (base PTX — no sm_103a-only features)
// ---------------------------------------------------------------------------
__device__ __forceinline__ uint32_t smem_u32(const void* p) {
    uint32_t a;
    asm("{ .reg .u64 t; cvta.to.shared.u64 t, %1; cvt.u32.u64 %0, t; }"
        : "=r"(a) : "l"(p));
    return a;
}

__device__ __forceinline__ void mma_bf16(float& c0, float& c1, float& c2, float& c3,
                                         uint32_t a0, uint32_t a1, uint32_t a2, uint32_t a3,
                                         uint32_t b0, uint32_t b1) {
    asm volatile(
        "mma.sync.aligned.m16n8k16.row.col.f32.bf16.bf16.f32 "
        "{%0,%1,%2,%3}, {%4,%5,%6,%7}, {%8,%9}, {%0,%1,%2,%3};"
        : "+f"(c0), "+f"(c1), "+f"(c2), "+f"(c3)
        : "r"(a0), "r"(a1), "r"(a2), "r"(a3), "r"(b0), "r"(b1));
}

__device__ __forceinline__ void ldmatrix_x4(uint32_t* r, uint32_t addr) {
    asm volatile("ldmatrix.sync.aligned.m8n8.x4.shared.b16 {%0,%1,%2,%3}, [%4];"
        : "=r"(r[0]), "=r"(r[1]), "=r"(r[2]), "=r"(r[3]) : "r"(addr));
}

__device__ __forceinline__ void ldmatrix_x2(uint32_t* r, uint32_t addr) {
    asm volatile("ldmatrix.sync.aligned.m8n8.x2.shared.b16 {%0,%1}, [%2];"
        : "=r"(r[0]), "=r"(r[1]) : "r"(addr));
}

__device__ __forceinline__ void cpasync16(uint32_t dst, const void* src) {
    asm volatile("cp.async.cg.shared.global [%0], [%1], 16;" :: "r"(dst), "l"(src));
}
__device__ __forceinline__ void cpasync_commit() {
    asm volatile("cp.async.commit_group;" ::: "memory");
}
__device__ __forceinline__ void cpasync_wait0() {
    asm volatile("cp.async.wait_group 0;" ::: "memory");
}

__device__ __forceinline__ uint32_t pack_bf(__nv_bfloat16 a, __nv_bfloat16 b) {
    return (uint32_t)__bfloat16_as_ushort(a) |
           ((uint32_t)__bfloat16_as_ushort(b) << 16);
}

// split (x,y) into packed hi/lo bf16 pairs
__device__ __forceinline__ void split2(float x, float y, uint32_t& hi, uint32_t& lo) {
    __nv_bfloat16 hx = __float2bfloat16(x);
    __nv_bfloat16 hy = __float2bfloat16(y);
    float lx = x - __bfloat162float(hx);
    float ly = y - __bfloat162float(hy);
    hi = pack_bf(hx, hy);
    lo = pack_bf(__float2bfloat16(lx), __float2bfloat16(ly));
}

// ---------------------------------------------------------------------------
// Weight prep: transpose + bf16 split W1 -> [256][512], W2 -> [128][256],
// W3 -> [64][384].
// ---------------------------------------------------------------------------
__global__ void prep_weights(const float* __restrict__ W1,
                             const float* __restrict__ W2,
                             const float* __restrict__ W3)
{
    int i = blockIdx.x * 256 + threadIdx.x;
    if (i < DK * HH) {
        int k = i >> 8, n = i & 255;
        float v = W1[i];
        __nv_bfloat16 h = __float2bfloat16(v);
        g_w1hi[n * DK + k] = h;
        g_w1lo[n * DK + k] = __float2bfloat16(v - __bfloat162float(h));
        return;
    }
    int j = i - DK * HH;
    if (j < HH * H2) {
        int k = j >> 7, n = j & 127;
        float v = W2[j];
        __nv_bfloat16 h = __float2bfloat16(v);
        g_w2hi[n * HH + k] = h;
        g_w2lo[n * HH + k] = __float2bfloat16(v - __bfloat162float(h));
        return;
    }
    int j2 = j - HH * H2;
    if (j2 < 384 * O3) {
        int k = j2 >> 6, n = j2 & 63;
        float v = W3[j2];
        __nv_bfloat16 h = __float2bfloat16(v);
        g_w3hi[n * 384 + k] = h;
        g_w3lo[n * 384 + k] = __float2bfloat16(v - __bfloat162float(h));
    }
}

// ---------------------------------------------------------------------------
// GEMM1 (mma.sync bf16 hi/lo split): hraw = X @ W1 + b1, plus column stats.
// CTA 128x256, 8 warps (2m x 4n), warp tile 64x64, K-chunks of 64, 2 stages.
// ---------------------------------------------------------------------------
#define AST 72
#define G1_ABYTES (128 * AST * 2)            // 18432
#define G1_BBYTES (256 * AST * 2)            // 36864
#define G1_STAGE  (2 * G1_ABYTES + 2 * G1_BBYTES)   // 110592
#define G1_DYN    (2 * G1_STAGE)             // 221184

__global__ void __launch_bounds__(256) gemm1_mma(
    const float* __restrict__ x1, const float* __restrict__ x2,
    const float* __restrict__ b1)
{
    extern __shared__ char dyn[];
    const int z    = blockIdx.y;
    const int rb   = blockIdx.x;
    const int row0 = rb * 128;
    const float* __restrict__ X = z ? x2 : x1;

    const int tid  = threadIdx.x;
    const int lane = tid & 31;
    const int wid  = tid >> 5;
    const int wm   = wid >> 2;
    const int wn   = wid & 3;
    const int g    = lane >> 2;
    const int tg   = lane & 3;
    const int ln16 = lane & 15;
    const int lhalf = (lane >> 4) & 1;

    float acc[4][8][4];
#pragma unroll
    for (int t = 0; t < 4; t++)
#pragma unroll
        for (int u = 0; u < 8; u++)
#pragma unroll
            for (int j = 0; j < 4; j++) acc[t][u][j] = 0.0f;

    float4 aNext[8];

#define G1_LDA(c) do { \
        const int kk_ = (c) * 64; \
        _Pragma("unroll") \
        for (int it = 0; it < 8; it++) { \
            int idx = tid + it * 256; \
            int r_  = idx >> 4, c4_ = idx & 15; \
            aNext[it] = *reinterpret_cast<const float4*>( \
                X + (size_t)(row0 + r_) * DK + kk_ + c4_ * 4); \
        } \
    } while (0)

#define G1_STA(stg) do { \
        char* sAhi_ = dyn + (stg) * G1_STAGE; \
        char* sAlo_ = sAhi_ + G1_ABYTES; \
        _Pragma("unroll") \
        for (int it = 0; it < 8; it++) { \
            int idx = tid + it * 256; \
            int r_  = idx >> 4, c4_ = idx & 15; \
            uint32_t h0, l0, h1_, l1; \
            split2(aNext[it].x, aNext[it].y, h0, l0); \
            split2(aNext[it].z, aNext[it].w, h1_, l1); \
            int off = (r_ * AST + c4_ * 4) * 2; \
            *reinterpret_cast<uint2*>(sAhi_ + off) = make_uint2(h0, h1_); \
            *reinterpret_cast<uint2*>(sAlo_ + off) = make_uint2(l0, l1); \
        } \
    } while (0)

#define G1_CPB(c, stg) do { \
        const int kk_ = (c) * 64; \
        char* sBhi_ = dyn + (stg) * G1_STAGE + 2 * G1_ABYTES; \
        char* sBlo_ = sBhi_ + G1_BBYTES; \
        uint32_t bhiU = smem_u32(sBhi_), bloU = smem_u32(sBlo_); \
        _Pragma("unroll") \
        for (int it = 0; it < 8; it++) { \
            int idx = tid + it * 256; \
            int n_ = idx >> 3, c8_ = idx & 7; \
            int off = (n_ * AST + c8_ * 8) * 2; \
            cpasync16(bhiU + off, g_w1hi + (size_t)n_ * DK + kk_ + c8_ * 8); \
            cpasync16(bloU + off, g_w1lo + (size_t)n_ * DK + kk_ + c8_ * 8); \
        } \
        cpasync_commit(); \
    } while (0)

    G1_CPB(0, 0);
    G1_LDA(0);
    G1_STA(0);
    cpasync_wait0();
    __syncthreads();

    const int NC = DK / 64;   // 8
    for (int c = 0; c < NC; c++) {
        const int s = c & 1;
        if (c + 1 < NC) {
            G1_CPB(c + 1, s ^ 1);
            G1_LDA(c + 1);
        }

        {
            char* st = dyn + s * G1_STAGE;
            uint32_t sAhiU = smem_u32(st);
            uint32_t sAloU = sAhiU + G1_ABYTES;
            uint32_t sBhiU = sAhiU + 2 * G1_ABYTES;
            uint32_t sBloU = sBhiU + G1_BBYTES;

            const uint32_t aOff = ((wm * 64 + ln16) * AST + lhalf * 8) * 2;
            const uint32_t bOff = (((wn * 64) + (ln16 & 7)) * AST + ((ln16 >> 3) * 8)) * 2;

#pragma unroll
            for (int ks = 0; ks < 4; ks++) {
                const uint32_t ko = ks * 16 * 2;
                uint32_t Ah[4][4], Al[4][4], Bh[8][2], Bl[8][2];
#pragma unroll
                for (int t = 0; t < 4; t++)
                    ldmatrix_x4(Ah[t], sAhiU + aOff + (t * 16 * AST) * 2 + ko);
#pragma unroll
                for (int u = 0; u < 8; u++)
                    ldmatrix_x2(Bh[u], sBhiU + bOff + (u * 8 * AST) * 2 + ko);
#pragma unroll
                for (int t = 0; t < 4; t++)
#pragma unroll
                    for (int u = 0; u < 8; u++)
                        mma_bf16(acc[t][u][0], acc[t][u][1], acc[t][u][2], acc[t][u][3],
                                 Ah[t][0], Ah[t][1], Ah[t][2], Ah[t][3],
                                 Bh[u][0], Bh[u][1]);
#pragma unroll
                for (int u = 0; u < 8; u++)
                    ldmatrix_x2(Bl[u], sBloU + bOff + (u * 8 * AST) * 2 + ko);
#pragma unroll
                for (int t = 0; t < 4; t++)
#pragma unroll
                    for (int u = 0; u < 8; u++)
                        mma_bf16(acc[t][u][0], acc[t][u][1], acc[t][u][2], acc[t][u][3],
                                 Ah[t][0], Ah[t][1], Ah[t][2], Ah[t][3],
                                 Bl[u][0], Bl[u][1]);
#pragma unroll
                for (int t = 0; t < 4; t++)
                    ldmatrix_x4(Al[t], sAloU + aOff + (t * 16 * AST) * 2 + ko);
#pragma unroll
                for (int t = 0; t < 4; t++)
#pragma unroll
                    for (int u = 0; u < 8; u++)
                        mma_bf16(acc[t][u][0], acc[t][u][1], acc[t][u][2], acc[t][u][3],
                                 Al[t][0], Al[t][1], Al[t][2], Al[t][3],
                                 Bh[u][0], Bh[u][1]);
            }
        }

        if (c + 1 < NC) {
            G1_STA(s ^ 1);
            cpasync_wait0();
            __syncthreads();
        }
    }

    // ---- epilogue: bias, store hraw, column stats ----
    float css0[8], css1[8], cqq0[8], cqq1[8];
#pragma unroll
    for (int u = 0; u < 8; u++) {
        const int col = wn * 64 + u * 8 + tg * 2;
        const float bi0 = b1[col], bi1 = b1[col + 1];
        float cs0 = 0.f, cs1 = 0.f, cq0 = 0.f, cq1 = 0.f;
#pragma unroll
        for (int t = 0; t < 4; t++) {
            const int r = row0 + wm * 64 + t * 16 + g;
            float v0 = acc[t][u][0] + bi0;
            float v1 = acc[t][u][1] + bi1;
            float v2 = acc[t][u][2] + bi0;
            float v3 = acc[t][u][3] + bi1;
            *reinterpret_cast<float2*>(
                &g_hraw[((size_t)z * NROWS + r) * HH + col])     = make_float2(v0, v1);
            *reinterpret_cast<float2*>(
                &g_hraw[((size_t)z * NROWS + r + 8) * HH + col]) = make_float2(v2, v3);
            cs0 += v0 + v2; cs1 += v1 + v3;
            cq0 += v0 * v0 + v2 * v2; cq1 += v1 * v1 + v3 * v3;
        }
        css0[u] = cs0; css1[u] = cs1; cqq0[u] = cq0; cqq1[u] = cq1;
    }
#pragma unroll
    for (int off = 4; off < 32; off <<= 1) {
#pragma unroll
        for (int u = 0; u < 8; u++) {
            css0[u] += __shfl_xor_sync(0xffffffffu, css0[u], off);
            css1[u] += __shfl_xor_sync(0xffffffffu, css1[u], off);
            cqq0[u] += __shfl_xor_sync(0xffffffffu, cqq0[u], off);
            cqq1[u] += __shfl_xor_sync(0xffffffffu, cqq1[u], off);
        }
    }
    float* s_ps = reinterpret_cast<float*>(dyn);
    float* s_sq = s_ps + 512;
    __syncthreads();
    if (g == 0) {
#pragma unroll
        for (int u = 0; u < 8; u++) {
            const int col = wn * 64 + u * 8 + tg * 2;
            s_ps[wm * 256 + col]     = css0[u];
            s_ps[wm * 256 + col + 1] = css1[u];
            s_sq[wm * 256 + col]     = cqq0[u];
            s_sq[wm * 256 + col + 1] = cqq1[u];
        }
    }
    __syncthreads();
    if (tid < 256) {
        g_psum[((size_t)z * NRB + rb) * HH + tid] = s_ps[tid] + s_ps[256 + tid];
        g_psq [((size_t)z * NRB + rb) * HH + tid] = s_sq[tid] + s_sq[256 + tid];
    }
#undef G1_LDA
#undef G1_STA
#undef G1_CPB
}

// ---------------------------------------------------------------------------
// Stats: reduce 512 partials per column -> BN scale/shift.
// ---------------------------------------------------------------------------
__global__ void stats_kernel(const float* __restrict__ gamma,
                             const float* __restrict__ beta_bn)
{
    const int idx = blockIdx.x * blockDim.x + threadIdx.x;
    if (idx >= 2 * HH) return;
    const int z = idx / HH;
    const int c = idx % HH;
    float s = 0.0f, q = 0.0f;
    for (int rbk = 0; rbk < NRB; rbk++) {
        s += g_psum[((size_t)z * NRB + rbk) * HH + c];
        q += g_psq [((size_t)z * NRB + rbk) * HH + c];
    }
    const float mean = s / (float)NROWS;
    const float var  = q / (float)NROWS - mean * mean;
    const float sc   = gamma[c] * rsqrtf(var + 1e-5f);
    g_scale[z * HH + c] = sc;
    g_shift[z * HH + c] = beta_bn[c] - mean * sc;
}

// ---------------------------------------------------------------------------
// FUSED: GEMM2 (both z) + cosine + GEMM3 + head -> out.
// CTA = 128 rows. 8 warps. GEMM2 warp tile 64x32; GEMM3 warp tile 64x16.
// smem: A region 73728 B (2 stages x (Ahi+Alo 128x64@72));
//       B region 73728 B (2 stages x (Bhi+Blo 128x64@72));
// Phase 3 reuses: A region -> combined tile 128x128@136 hi/lo (69632);
//                 B region -> W3 chunk 64x128@136 hi/lo (34816).
// ---------------------------------------------------------------------------
#define F2_AB   (128 * AST * 2)        // 18432
#define F2_ASTG (2 * F2_AB)            // 36864
#define F2_AREG (2 * F2_ASTG)          // 73728
#define F2_BB   (128 * AST * 2)        // 18432
#define F2_BSTG (2 * F2_BB)            // 36864
#define F2_BREG (2 * F2_BSTG)          // 73728
#define F2_DYN  (F2_AREG + F2_BREG)    // 147456
#define ST3 136

__global__ void __launch_bounds__(256) fused2(
    const float* __restrict__ b2, const float* __restrict__ b3,
    const float* __restrict__ W4, const float* __restrict__ b4,
    const float* __restrict__ alphap, const float* __restrict__ betap,
    float* __restrict__ out)
{
    extern __shared__ char dyn[];
    __shared__ float s_sc[HH];
    __shared__ float s_sh[HH];
    __shared__ float s_red[4][128][4];

    const int rb   = blockIdx.x;
    const int row0 = rb * 128;
    const int tid  = threadIdx.x;
    const int lane = tid & 31;
    const int wid  = tid >> 5;
    const int wm   = wid >> 2;       // 0..1
    const int wn   = wid & 3;        // 0..3
    const int g    = lane >> 2;
    const int tg   = lane & 3;
    const int ln16 = lane & 15;
    const int lhalf = (lane >> 4) & 1;

    char* Areg = dyn;
    char* Breg = dyn + F2_AREG;

    float acc[4][4][4];
    float h1[4][4][4];
    float4 aNext[8];

    const uint32_t aOff2 = ((wm * 64 + ln16) * AST + lhalf * 8) * 2;
    const uint32_t bOff2 = ((wn * 32 + (ln16 & 7)) * AST + ((ln16 >> 3) * 8)) * 2;

#define F2_LDA(zz, c) do { \
        const int kk_ = (c) * 64; \
        _Pragma("unroll") \
        for (int it = 0; it < 8; it++) { \
            int idx = tid + it * 256; \
            int r_  = idx >> 4, c4_ = idx & 15; \
            aNext[it] = *reinterpret_cast<const float4*>( \
                g_hraw + ((size_t)(zz) * NROWS + row0 + r_) * HH + kk_ + c4_ * 4); \
        } \
    } while (0)

#define F2_STA(c, stg) do { \
        const int kk_ = (c) * 64; \
        char* sAhi_ = Areg + (stg) * F2_ASTG; \
        char* sAlo_ = sAhi_ + F2_AB; \
        _Pragma("unroll") \
        for (int it = 0; it < 8; it++) { \
            int idx = tid + it * 256; \
            int r_  = idx >> 4, c4_ = idx & 15; \
            const int col_ = kk_ + c4_ * 4; \
            float a0 = fmaxf(s_sc[col_ + 0] * aNext[it].x + s_sh[col_ + 0], 0.0f); \
            float a1 = fmaxf(s_sc[col_ + 1] * aNext[it].y + s_sh[col_ + 1], 0.0f); \
            float a2 = fmaxf(s_sc[col_ + 2] * aNext[it].z + s_sh[col_ + 2], 0.0f); \
            float a3 = fmaxf(s_sc[col_ + 3] * aNext[it].w + s_sh[col_ + 3], 0.0f); \
            uint32_t h0, l0, h1_, l1; \
            split2(a0, a1, h0, l0); \
            split2(a2, a3, h1_, l1); \
            int off = (r_ * AST + c4_ * 4) * 2; \
            *reinterpret_cast<uint2*>(sAhi_ + off) = make_uint2(h0, h1_); \
            *reinterpret_cast<uint2*>(sAlo_ + off) = make_uint2(l0, l1); \
        } \
    } while (0)

#define F2_CPB(c, stg) do { \
        const int kk_ = (c) * 64; \
        char* sBhi_ = Breg + (stg) * F2_BSTG; \
        char* sBlo_ = sBhi_ + F2_BB; \
        uint32_t bhiU = smem_u32(sBhi_), bloU = smem_u32(sBlo_); \
        _Pragma("unroll") \
        for (int it = 0; it < 4; it++) { \
            int idx = tid + it * 256; \
            int n_ = idx >> 3, c8_ = idx & 7; \
            int off = (n_ * AST + c8_ * 8) * 2; \
            cpasync16(bhiU + off, g_w2hi + (size_t)n_ * HH + kk_ + c8_ * 8); \
            cpasync16(bloU + off, g_w2lo + (size_t)n_ * HH + kk_ + c8_ * 8); \
        } \
        cpasync_commit(); \
    } while (0)

    // ========================= Phases 1 & 2: GEMM2 x2 =======================
    for (int z = 0; z < 2; z++) {
        __syncthreads();
        s_sc[tid] = g_scale[z * HH + tid];
        s_sh[tid] = g_shift[z * HH + tid];
        __syncthreads();

#pragma unroll
        for (int t = 0; t < 4; t++)
#pragma unroll
            for (int u = 0; u < 4; u++)
#pragma unroll
                for (int j = 0; j < 4; j++) acc[t][u][j] = 0.0f;

        F2_CPB(0, 0);
        F2_LDA(z, 0);
        F2_STA(0, 0);
        cpasync_wait0();
        __syncthreads();

        const int NC = 4;
        for (int c = 0; c < NC; c++) {
            const int s = c & 1;
            if (c + 1 < NC) {
                F2_CPB(c + 1, s ^ 1);
                F2_LDA(z, c + 1);
            }
            {
                uint32_t sAhiU = smem_u32(Areg + s * F2_ASTG);
                uint32_t sAloU = sAhiU + F2_AB;
                uint32_t sBhiU = smem_u32(Breg + s * F2_BSTG);
                uint32_t sBloU = sBhiU + F2_BB;
#pragma unroll
                for (int ks = 0; ks < 4; ks++) {
                    const uint32_t ko = ks * 32;
                    uint32_t Ah[4][4], Al[4][4], Bh[4][2], Bl[4][2];
#pragma unroll
                    for (int t = 0; t < 4; t++)
                        ldmatrix_x4(Ah[t], sAhiU + aOff2 + (t * 16 * AST) * 2 + ko);
#pragma unroll
                    for (int u = 0; u < 4; u++)
                        ldmatrix_x2(Bh[u], sBhiU + bOff2 + (u * 8 * AST) * 2 + ko);
#pragma unroll
                    for (int t = 0; t < 4; t++)
#pragma unroll
                        for (int u = 0; u < 4; u++)
                            mma_bf16(acc[t][u][0], acc[t][u][1], acc[t][u][2], acc[t][u][3],
                                     Ah[t][0], Ah[t][1], Ah[t][2], Ah[t][3],
                                     Bh[u][0], Bh[u][1]);
#pragma unroll
                    for (int u = 0; u < 4; u++)
                        ldmatrix_x2(Bl[u], sBloU + bOff2 + (u * 8 * AST) * 2 + ko);
#pragma unroll
                    for (int t = 0; t < 4; t++)
#pragma unroll
                        for (int u = 0; u < 4; u++)
                            mma_bf16(acc[t][u][0], acc[t][u][1], acc[t][u][2], acc[t][u][3],
                                     Ah[t][0], Ah[t][1], Ah[t][2], Ah[t][3],
                                     Bl[u][0], Bl[u][1]);
#pragma unroll
                    for (int t = 0; t < 4; t++)
                        ldmatrix_x4(Al[t], sAloU + aOff2 + (t * 16 * AST) * 2 + ko);
#pragma unroll
                    for (int t = 0; t < 4; t++)
#pragma unroll
                        for (int u = 0; u < 4; u++)
                            mma_bf16(acc[t][u][0], acc[t][u][1], acc[t][u][2], acc[t][u][3],
                                     Al[t][0], Al[t][1], Al[t][2], Al[t][3],
                                     Bh[u][0], Bh[u][1]);
                }
            }
            if (c + 1 < NC) {
                __syncthreads();
                F2_STA(c + 1, s ^ 1);
                cpasync_wait0();
                __syncthreads();
            }
        }

        // epilogue: h = relu(acc + b2); stash into h1 (z=0) or keep in acc (z=1)
#pragma unroll
        for (int u = 0; u < 4; u++) {
            const int col = wn * 32 + u * 8 + tg * 2;
            const float bi0 = b2[col], bi1 = b2[col + 1];
#pragma unroll
            for (int t = 0; t < 4; t++) {
                float v0 = fmaxf(acc[t][u][0] + bi0, 0.0f);
                float v1 = fmaxf(acc[t][u][1] + bi1, 0.0f);
                float v2 = fmaxf(acc[t][u][2] + bi0, 0.0f);
                float v3 = fmaxf(acc[t][u][3] + bi1, 0.0f);
                if (z == 0) {
                    h1[t][u][0] = v0; h1[t][u][1] = v1;
                    h1[t][u][2] = v2; h1[t][u][3] = v3;
                } else {
                    acc[t][u][0] = v0; acc[t][u][1] = v1;
                    acc[t][u][2] = v2; acc[t][u][3] = v3;
                }
            }
        }
    }

    // ================== cosine partials (row-wise) from fragments ==========
    {
        float dotR[8], n1R[8], n2R[8];
#pragma unroll
        for (int ri = 0; ri < 8; ri++) { dotR[ri] = 0.f; n1R[ri] = 0.f; n2R[ri] = 0.f; }
#pragma unroll
        for (int t = 0; t < 4; t++)
#pragma unroll
            for (int u = 0; u < 4; u++)
#pragma unroll
                for (int j = 0; j < 4; j++) {
                    const float a = h1[t][u][j];
                    const float b = acc[t][u][j];
                    const int ri = t * 2 + (j >> 1);
                    dotR[ri] = fmaf(a, b, dotR[ri]);
                    n1R[ri]  = fmaf(a, a, n1R[ri]);
                    n2R[ri]  = fmaf(b, b, n2R[ri]);
                }
#pragma unroll
        for (int off = 1; off < 4; off <<= 1) {
#pragma unroll
            for (int ri = 0; ri < 8; ri++) {
                dotR[ri] += __shfl_xor_sync(0xffffffffu, dotR[ri], off);
                n1R[ri]  += __shfl_xor_sync(0xffffffffu, n1R[ri], off);
                n2R[ri]  += __shfl_xor_sync(0xffffffffu, n2R[ri], off);
            }
        }
        if (tg == 0) {
#pragma unroll
            for (int ri = 0; ri < 8; ri++) {
                const int r = wm * 64 + (ri >> 1) * 16 + g + (ri & 1) * 8;
                s_red[0][r][wn] = dotR[ri];
                s_red[1][r][wn] = n1R[ri];
                s_red[2][r][wn] = n2R[ri];
            }
        }
    }

    // ==================== Phase 3: GEMM3 on tensor cores ====================
    float acc3[4][2][4];
#pragma unroll
    for (int t = 0; t < 4; t++)
#pragma unroll
        for (int u = 0; u < 2; u++)
#pragma unroll
            for (int j = 0; j < 4; j++) acc3[t][u][j] = 0.0f;

    const uint32_t aOff3 = ((wm * 64 + ln16) * ST3 + lhalf * 8) * 2;
    const uint32_t bOff3 = ((wn * 16 + (ln16 & 7)) * ST3 + ((ln16 >> 3) * 8)) * 2;
    char* A3hi = Areg;
    char* A3lo = Areg + 128 * ST3 * 2;
    uint32_t A3hiU = smem_u32(A3hi);
    uint32_t A3loU = A3hiU + 128 * ST3 * 2;
    uint32_t B3hiU = smem_u32(Breg);
    uint32_t B3loU = B3hiU + 64 * ST3 * 2;

    __syncthreads();   // all warps done with phase-2 stages + s_red written

    for (int f = 0; f < 3; f++) {
        // prefetch W3 chunk f
#pragma unroll
        for (int it = 0; it < 4; it++) {
            int idx = tid + it * 256;
            int n_ = idx >> 4, cc = idx & 15;
            int off = (n_ * ST3 + cc * 8) * 2;
            cpasync16(B3hiU + off, g_w3hi + n_ * 384 + f * 128 + cc * 8);
            cpasync16(B3loU + off, g_w3lo + n_ * 384 + f * 128 + cc * 8);
        }
        cpasync_commit();

        // write combined feature tile into A region (bf16 hi/lo, stride ST3)
#pragma unroll
        for (int t = 0; t < 4; t++)
#pragma unroll
            for (int u = 0; u < 4; u++) {
                const int col = wn * 32 + u * 8 + tg * 2;
                const int r   = wm * 64 + t * 16 + g;
                float v[4];
#pragma unroll
                for (int j = 0; j < 4; j++) {
                    const float a = h1[t][u][j];
                    const float b = acc[t][u][j];
                    v[j] = (f == 0) ? a * b : (f == 1) ? fabsf(a - b) : a + b;
                }
                uint32_t hi0, lo0, hi1, lo1;
                split2(v[0], v[1], hi0, lo0);
                split2(v[2], v[3], hi1, lo1);
                *reinterpret_cast<uint32_t*>(A3hi + (r * ST3 + col) * 2)       = hi0;
                *reinterpret_cast<uint32_t*>(A3lo + (r * ST3 + col) * 2)       = lo0;
                *reinterpret_cast<uint32_t*>(A3hi + ((r + 8) * ST3 + col) * 2) = hi1;
                *reinterpret_cast<uint32_t*>(A3lo + ((r + 8) * ST3 + col) * 2) = lo1;
            }
        cpasync_wait0();
        __syncthreads();

        // MMA over k=128 (8 steps)
#pragma unroll
        for (int ks = 0; ks < 8; ks++) {
            const uint32_t ko = ks * 32;
            uint32_t Ah[4][4], Al[4][4], Bh[2][2], Bl[2][2];
#pragma unroll
            for (int t = 0; t < 4; t++)
                ldmatrix_x4(Ah[t], A3hiU + aOff3 + (t * 16 * ST3) * 2 + ko);
#pragma unroll
            for (int u = 0; u < 2; u++)
                ldmatrix_x2(Bh[u], B3hiU + bOff3 + (u * 8 * ST3) * 2 + ko);
#pragma unroll
            for (int t = 0; t < 4; t++)
#pragma unroll
                for (int u = 0; u < 2; u++)
                    mma_bf16(acc3[t][u][0], acc3[t][u][1], acc3[t][u][2], acc3[t][u][3],
                             Ah[t][0], Ah[t][1], Ah[t][2], Ah[t][3],
                             Bh[u][0], Bh[u][1]);
#pragma unroll
            for (int u = 0; u < 2; u++)
                ldmatrix_x2(Bl[u], B3loU + bOff3 + (u * 8 * ST3) * 2 + ko);
#pragma unroll
            for (int t = 0; t < 4; t++)
#pragma unroll
                for (int u = 0; u < 2; u++)
                    mma_bf16(acc3[t][u][0], acc3[t][u][1], acc3[t][u][2], acc3[t][u][3],
                             Ah[t][0], Ah[t][1], Ah[t][2], Ah[t][3],
                             Bl[u][0], Bl[u][1]);
#pragma unroll
            for (int t = 0; t < 4; t++)
                ldmatrix_x4(Al[t], A3loU + aOff3 + (t * 16 * ST3) * 2 + ko);
#pragma unroll
            for (int t = 0; t < 4; t++)
#pragma unroll
                for (int u = 0; u < 2; u++)
                    mma_bf16(acc3[t][u][0], acc3[t][u][1], acc3[t][u][2], acc3[t][u][3],
                             Al[t][0], Al[t][1], Al[t][2], Al[t][3],
                             Bh[u][0], Bh[u][1]);
        }
        __syncthreads();
    }

    // ==================== Phase 4: relu -> W4 -> head =======================
    {
        float slR[8];
#pragma unroll
        for (int ri = 0; ri < 8; ri++) slR[ri] = 0.0f;
#pragma unroll
        for (int u = 0; u < 2; u++) {
            const int col = wn * 16 + u * 8 + tg * 2;
            const float b30 = b3[col], b31 = b3[col + 1];
            const float w40 = W4[col], w41 = W4[col + 1];
#pragma unroll
            for (int t = 0; t < 4; t++) {
                slR[t * 2 + 0] += fmaxf(acc3[t][u][0] + b30, 0.0f) * w40
                                + fmaxf(acc3[t][u][1] + b31, 0.0f) * w41;
                slR[t * 2 + 1] += fmaxf(acc3[t][u][2] + b30, 0.0f) * w40
                                + fmaxf(acc3[t][u][3] + b31, 0.0f) * w41;
            }
        }
#pragma unroll
        for (int off = 1; off < 4; off <<= 1)
#pragma unroll
            for (int ri = 0; ri < 8; ri++)
                slR[ri] += __shfl_xor_sync(0xffffffffu, slR[ri], off);
        if (tg == 0) {
#pragma unroll
            for (int ri = 0; ri < 8; ri++) {
                const int r = wm * 64 + (ri >> 1) * 16 + g + (ri & 1) * 8;
                s_red[3][r][wn] = slR[ri];
            }
        }
    }
    __syncthreads();

    if (tid < 128) {
        float dot = 0.f, n1v = 0.f, n2v = 0.f, sl = 0.f;
#pragma unroll
        for (int w = 0; w < 4; w++) {
            dot += s_red[0][tid][w];
            n1v += s_red[1][tid][w];
            n2v += s_red[2][tid][w];
            sl  += s_red[3][tid][w];
        }
        const float inv1   = 1.0f / fmaxf(sqrtf(n1v), 1e-15f);
        const float inv2   = 1.0f / fmaxf(sqrtf(n2v), 1e-15f);
        const float s_math = fminf(fmaxf(dot * inv1 * inv2, 0.0f), 1.0f);
        const float sig    = 1.0f / (1.0f + expf(-(sl + b4[0])));
        const float fin    = alphap[0] * s_math + betap[0] * sig;
        out[row0 + tid] = fminf(fmaxf(fin, 0.0f), 1.0f);
    }
#undef F2_LDA
#undef F2_STA
#undef F2_CPB
}

// ---------------------------------------------------------------------------
extern "C" void kernel_launch(void* const* d_in, const int* in_sizes, int n_in,
                              void* d_out, int out_size)
{
    const float* x1      = (const float*)d_in[0];
    const float* x2      = (const float*)d_in[1];
    const float* W1      = (const float*)d_in[2];
    const float* b1      = (const float*)d_in[3];
    const float* gamma   = (const float*)d_in[4];
    const float* beta_bn = (const float*)d_in[5];
    const float* W2      = (const float*)d_in[6];
    const float* b2      = (const float*)d_in[7];
    const float* W3      = (const float*)d_in[8];
    const float* b3      = (const float*)d_in[9];
    const float* W4      = (const float*)d_in[10];
    const float* b4      = (const float*)d_in[11];
    const float* alphap  = (const float*)d_in[12];
    const float* betap   = (const float*)d_in[13];
    float* out = (float*)d_out;

    cudaFuncSetAttribute(gemm1_mma,
                         cudaFuncAttributeMaxDynamicSharedMemorySize, G1_DYN);
    cudaFuncSetAttribute(fused2,
                         cudaFuncAttributeMaxDynamicSharedMemorySize, F2_DYN);

    const int prep_elems = DK * HH + HH * H2 + 384 * O3;
    prep_weights<<<(prep_elems + 255) / 256, 256>>>(W1, W2, W3);

    dim3 g1(NRB, 2);
    gemm1_mma<<<g1, 256, G1_DYN>>>(x1, x2, b1);

    stats_kernel<<<1, 512>>>(gamma, beta_bn);

    fused2<<<NRB, 256, F2_DYN>>>(b2, b3, W4, b4, alphap, betap, out);
}

// round 5
// speedup vs baseline: 3.0819x; 1.0158x over previous
#include <cuda_runtime.h>
#include <cuda_bf16.h>
#include <cstdint>
#include <math.h>

// ---------------------------------------------------------------------------
// Problem constants
// ---------------------------------------------------------------------------
#define NROWS 65536
#define DK    512
#define HH    256
#define H2    128
#define O3    64
#define NRB1  1024          // gemm1 row blocks of 64
#define NRB2  512           // fused2 row blocks of 128

// ---------------------------------------------------------------------------
// Scratch (device globals — allocation-free per harness rules)
// ---------------------------------------------------------------------------
__device__ float g_hraw[2 * NROWS * HH];     // 128 MB : pre-BN activations
__device__ float g_psum[2 * NRB1 * HH];
__device__ float g_psq [2 * NRB1 * HH];
__device__ float g_scale[2 * HH];
__device__ float g_shift[2 * HH];
// Transposed + bf16-split weights (B operands, [N][K] K-major)
__device__ __align__(16) __nv_bfloat16 g_w1hi[HH * DK];
__device__ __align__(16) __nv_bfloat16 g_w1lo[HH * DK];
__device__ __align__(16) __nv_bfloat16 g_w2hi[H2 * HH];
__device__ __align__(16) __nv_bfloat16 g_w2lo[H2 * HH];
__device__ __align__(16) __nv_bfloat16 g_w3hi[O3 * 384];
__device__ __align__(16) __nv_bfloat16 g_w3lo[O3 * 384];

// ---------------------------------------------------------------------------
// Warp-MMA helpers (base PTX — no sm_103a-only features)
// ---------------------------------------------------------------------------
__device__ __forceinline__ uint32_t smem_u32(const void* p) {
    uint32_t a;
    asm("{ .reg .u64 t; cvta.to.shared.u64 t, %1; cvt.u32.u64 %0, t; }"
        : "=r"(a) : "l"(p));
    return a;
}

__device__ __forceinline__ void mma_bf16(float& c0, float& c1, float& c2, float& c3,
                                         uint32_t a0, uint32_t a1, uint32_t a2, uint32_t a3,
                                         uint32_t b0, uint32_t b1) {
    asm volatile(
        "mma.sync.aligned.m16n8k16.row.col.f32.bf16.bf16.f32 "
        "{%0,%1,%2,%3}, {%4,%5,%6,%7}, {%8,%9}, {%0,%1,%2,%3};"
        : "+f"(c0), "+f"(c1), "+f"(c2), "+f"(c3)
        : "r"(a0), "r"(a1), "r"(a2), "r"(a3), "r"(b0), "r"(b1));
}

__device__ __forceinline__ void ldmatrix_x4(uint32_t* r, uint32_t addr) {
    asm volatile("ldmatrix.sync.aligned.m8n8.x4.shared.b16 {%0,%1,%2,%3}, [%4];"
        : "=r"(r[0]), "=r"(r[1]), "=r"(r[2]), "=r"(r[3]) : "r"(addr));
}

__device__ __forceinline__ void ldmatrix_x2(uint32_t* r, uint32_t addr) {
    asm volatile("ldmatrix.sync.aligned.m8n8.x2.shared.b16 {%0,%1}, [%2];"
        : "=r"(r[0]), "=r"(r[1]) : "r"(addr));
}

__device__ __forceinline__ void cpasync16(uint32_t dst, const void* src) {
    asm volatile("cp.async.cg.shared.global [%0], [%1], 16;" :: "r"(dst), "l"(src));
}
__device__ __forceinline__ void cpasync_commit() {
    asm volatile("cp.async.commit_group;" ::: "memory");
}
__device__ __forceinline__ void cpasync_wait0() {
    asm volatile("cp.async.wait_group 0;" ::: "memory");
}

__device__ __forceinline__ uint32_t pack_bf(__nv_bfloat16 a, __nv_bfloat16 b) {
    return (uint32_t)__bfloat16_as_ushort(a) |
           ((uint32_t)__bfloat16_as_ushort(b) << 16);
}

// split (x,y) into packed hi/lo bf16 pairs
__device__ __forceinline__ void split2(float x, float y, uint32_t& hi, uint32_t& lo) {
    __nv_bfloat16 hx = __float2bfloat16(x);
    __nv_bfloat16 hy = __float2bfloat16(y);
    float lx = x - __bfloat162float(hx);
    float ly = y - __bfloat162float(hy);
    hi = pack_bf(hx, hy);
    lo = pack_bf(__float2bfloat16(lx), __float2bfloat16(ly));
}

// ---------------------------------------------------------------------------
// Weight prep: transpose + bf16 split W1 -> [256][512], W2 -> [128][256],
// W3 -> [64][384].
// ---------------------------------------------------------------------------
__global__ void prep_weights(const float* __restrict__ W1,
                             const float* __restrict__ W2,
                             const float* __restrict__ W3)
{
    int i = blockIdx.x * 256 + threadIdx.x;
    if (i < DK * HH) {
        int k = i >> 8, n = i & 255;
        float v = W1[i];
        __nv_bfloat16 h = __float2bfloat16(v);
        g_w1hi[n * DK + k] = h;
        g_w1lo[n * DK + k] = __float2bfloat16(v - __bfloat162float(h));
        return;
    }
    int j = i - DK * HH;
    if (j < HH * H2) {
        int k = j >> 7, n = j & 127;
        float v = W2[j];
        __nv_bfloat16 h = __float2bfloat16(v);
        g_w2hi[n * HH + k] = h;
        g_w2lo[n * HH + k] = __float2bfloat16(v - __bfloat162float(h));
        return;
    }
    int j2 = j - HH * H2;
    if (j2 < 384 * O3) {
        int k = j2 >> 6, n = j2 & 63;
        float v = W3[j2];
        __nv_bfloat16 h = __float2bfloat16(v);
        g_w3hi[n * 384 + k] = h;
        g_w3lo[n * 384 + k] = __float2bfloat16(v - __bfloat162float(h));
    }
}

// ---------------------------------------------------------------------------
// GEMM1 (mma.sync bf16 hi/lo split): hraw = X @ W1 + b1, plus column stats.
// v3: CTA 64x256, 512 threads (16 warps, 2m x 8n), warp tile 32x32.
// K-chunks of 64, double-buffered. ~105 regs/thread -> 16 warps/SM.
// ---------------------------------------------------------------------------
#define AST 72
#define G1_AB  (64 * AST * 2)                 // 9216  (per hi or lo)
#define G1_BB  (256 * AST * 2)                // 36864
#define G1_STAGE (2 * G1_AB + 2 * G1_BB)      // 92160
#define G1_DYN   (2 * G1_STAGE)               // 184320

__global__ void __launch_bounds__(512) gemm1_mma(
    const float* __restrict__ x1, const float* __restrict__ x2,
    const float* __restrict__ b1)
{
    extern __shared__ char dyn[];
    const int z    = blockIdx.y;
    const int rb   = blockIdx.x;
    const int row0 = rb * 64;
    const float* __restrict__ X = z ? x2 : x1;

    const int tid  = threadIdx.x;
    const int lane = tid & 31;
    const int wid  = tid >> 5;
    const int wm   = wid >> 3;       // 0..1
    const int wn   = wid & 7;        // 0..7
    const int g    = lane >> 2;      // 0..7
    const int tg   = lane & 3;       // 0..3
    const int ln16 = lane & 15;
    const int lhalf = (lane >> 4) & 1;

    float acc[2][4][4];
#pragma unroll
    for (int t = 0; t < 2; t++)
#pragma unroll
        for (int u = 0; u < 4; u++)
#pragma unroll
            for (int j = 0; j < 4; j++) acc[t][u][j] = 0.0f;

    float4 aNext[2];

#define G1_LDA(c) do { \
        const int kk_ = (c) * 64; \
        _Pragma("unroll") \
        for (int it = 0; it < 2; it++) { \
            int idx = tid + it * 512; \
            int r_  = idx >> 4, c4_ = idx & 15; \
            aNext[it] = *reinterpret_cast<const float4*>( \
                X + (size_t)(row0 + r_) * DK + kk_ + c4_ * 4); \
        } \
    } while (0)

#define G1_STA(stg) do { \
        char* sAhi_ = dyn + (stg) * G1_STAGE; \
        char* sAlo_ = sAhi_ + G1_AB; \
        _Pragma("unroll") \
        for (int it = 0; it < 2; it++) { \
            int idx = tid + it * 512; \
            int r_  = idx >> 4, c4_ = idx & 15; \
            uint32_t h0, l0, h1_, l1; \
            split2(aNext[it].x, aNext[it].y, h0, l0); \
            split2(aNext[it].z, aNext[it].w, h1_, l1); \
            int off = (r_ * AST + c4_ * 4) * 2; \
            *reinterpret_cast<uint2*>(sAhi_ + off) = make_uint2(h0, h1_); \
            *reinterpret_cast<uint2*>(sAlo_ + off) = make_uint2(l0, l1); \
        } \
    } while (0)

#define G1_CPB(c, stg) do { \
        const int kk_ = (c) * 64; \
        char* sBhi_ = dyn + (stg) * G1_STAGE + 2 * G1_AB; \
        char* sBlo_ = sBhi_ + G1_BB; \
        uint32_t bhiU = smem_u32(sBhi_), bloU = smem_u32(sBlo_); \
        _Pragma("unroll") \
        for (int it = 0; it < 4; it++) { \
            int idx = tid + it * 512; \
            int n_ = idx >> 3, c8_ = idx & 7; \
            int off = (n_ * AST + c8_ * 8) * 2; \
            cpasync16(bhiU + off, g_w1hi + (size_t)n_ * DK + kk_ + c8_ * 8); \
            cpasync16(bloU + off, g_w1lo + (size_t)n_ * DK + kk_ + c8_ * 8); \
        } \
        cpasync_commit(); \
    } while (0)

    G1_CPB(0, 0);
    G1_LDA(0);
    G1_STA(0);
    cpasync_wait0();
    __syncthreads();

    const int NC = DK / 64;   // 8
    for (int c = 0; c < NC; c++) {
        const int s = c & 1;
        if (c + 1 < NC) {
            G1_CPB(c + 1, s ^ 1);
            G1_LDA(c + 1);
        }

        {
            char* st = dyn + s * G1_STAGE;
            uint32_t sAhiU = smem_u32(st);
            uint32_t sAloU = sAhiU + G1_AB;
            uint32_t sBhiU = sAhiU + 2 * G1_AB;
            uint32_t sBloU = sBhiU + G1_BB;

            const uint32_t aOff = ((wm * 32 + ln16) * AST + lhalf * 8) * 2;
            const uint32_t bOff = (((wn * 32) + (ln16 & 7)) * AST + ((ln16 >> 3) * 8)) * 2;

#pragma unroll
            for (int ks = 0; ks < 4; ks++) {
                const uint32_t ko = ks * 32;
                uint32_t Ah[2][4], Al[2][4], Bh[4][2], Bl[4][2];
#pragma unroll
                for (int t = 0; t < 2; t++)
                    ldmatrix_x4(Ah[t], sAhiU + aOff + (t * 16 * AST) * 2 + ko);
#pragma unroll
                for (int u = 0; u < 4; u++)
                    ldmatrix_x2(Bh[u], sBhiU + bOff + (u * 8 * AST) * 2 + ko);
#pragma unroll
                for (int t = 0; t < 2; t++)
#pragma unroll
                    for (int u = 0; u < 4; u++)
                        mma_bf16(acc[t][u][0], acc[t][u][1], acc[t][u][2], acc[t][u][3],
                                 Ah[t][0], Ah[t][1], Ah[t][2], Ah[t][3],
                                 Bh[u][0], Bh[u][1]);
#pragma unroll
                for (int u = 0; u < 4; u++)
                    ldmatrix_x2(Bl[u], sBloU + bOff + (u * 8 * AST) * 2 + ko);
#pragma unroll
                for (int t = 0; t < 2; t++)
#pragma unroll
                    for (int u = 0; u < 4; u++)
                        mma_bf16(acc[t][u][0], acc[t][u][1], acc[t][u][2], acc[t][u][3],
                                 Ah[t][0], Ah[t][1], Ah[t][2], Ah[t][3],
                                 Bl[u][0], Bl[u][1]);
#pragma unroll
                for (int t = 0; t < 2; t++)
                    ldmatrix_x4(Al[t], sAloU + aOff + (t * 16 * AST) * 2 + ko);
#pragma unroll
                for (int t = 0; t < 2; t++)
#pragma unroll
                    for (int u = 0; u < 4; u++)
                        mma_bf16(acc[t][u][0], acc[t][u][1], acc[t][u][2], acc[t][u][3],
                                 Al[t][0], Al[t][1], Al[t][2], Al[t][3],
                                 Bh[u][0], Bh[u][1]);
            }
        }

        if (c + 1 < NC) {
            G1_STA(s ^ 1);
            cpasync_wait0();
            __syncthreads();
        }
    }

    // ---- epilogue: bias, store hraw, column partial stats ----
    float css0[4], css1[4], cqq0[4], cqq1[4];
#pragma unroll
    for (int u = 0; u < 4; u++) {
        const int col = wn * 32 + u * 8 + tg * 2;
        const float bi0 = b1[col], bi1 = b1[col + 1];
        float cs0 = 0.f, cs1 = 0.f, cq0 = 0.f, cq1 = 0.f;
#pragma unroll
        for (int t = 0; t < 2; t++) {
            const int r = row0 + wm * 32 + t * 16 + g;
            float v0 = acc[t][u][0] + bi0;
            float v1 = acc[t][u][1] + bi1;
            float v2 = acc[t][u][2] + bi0;
            float v3 = acc[t][u][3] + bi1;
            *reinterpret_cast<float2*>(
                &g_hraw[((size_t)z * NROWS + r) * HH + col])     = make_float2(v0, v1);
            *reinterpret_cast<float2*>(
                &g_hraw[((size_t)z * NROWS + r + 8) * HH + col]) = make_float2(v2, v3);
            cs0 += v0 + v2; cs1 += v1 + v3;
            cq0 += v0 * v0 + v2 * v2; cq1 += v1 * v1 + v3 * v3;
        }
        css0[u] = cs0; css1[u] = cs1; cqq0[u] = cq0; cqq1[u] = cq1;
    }
#pragma unroll
    for (int off = 4; off < 32; off <<= 1) {
#pragma unroll
        for (int u = 0; u < 4; u++) {
            css0[u] += __shfl_xor_sync(0xffffffffu, css0[u], off);
            css1[u] += __shfl_xor_sync(0xffffffffu, css1[u], off);
            cqq0[u] += __shfl_xor_sync(0xffffffffu, cqq0[u], off);
            cqq1[u] += __shfl_xor_sync(0xffffffffu, cqq1[u], off);
        }
    }
    float* s_ps = reinterpret_cast<float*>(dyn);   // [2][256]
    float* s_sq = s_ps + 512;
    __syncthreads();
    if (g == 0) {
#pragma unroll
        for (int u = 0; u < 4; u++) {
            const int col = wn * 32 + u * 8 + tg * 2;
            s_ps[wm * 256 + col]     = css0[u];
            s_ps[wm * 256 + col + 1] = css1[u];
            s_sq[wm * 256 + col]     = cqq0[u];
            s_sq[wm * 256 + col + 1] = cqq1[u];
        }
    }
    __syncthreads();
    if (tid < 256) {
        g_psum[((size_t)z * NRB1 + rb) * HH + tid] = s_ps[tid] + s_ps[256 + tid];
        g_psq [((size_t)z * NRB1 + rb) * HH + tid] = s_sq[tid] + s_sq[256 + tid];
    }
#undef G1_LDA
#undef G1_STA
#undef G1_CPB
}

// ---------------------------------------------------------------------------
// Stats v2: one block per (z, column); 256 threads reduce 1024 partials.
// ---------------------------------------------------------------------------
__global__ void __launch_bounds__(256) stats_kernel(
    const float* __restrict__ gamma, const float* __restrict__ beta_bn)
{
    const int z = blockIdx.x >> 8;
    const int c = blockIdx.x & 255;
    const int tid = threadIdx.x;

    float s = 0.0f, q = 0.0f;
    for (int i = tid; i < NRB1; i += 256) {
        s += g_psum[((size_t)z * NRB1 + i) * HH + c];
        q += g_psq [((size_t)z * NRB1 + i) * HH + c];
    }
#pragma unroll
    for (int off = 16; off > 0; off >>= 1) {
        s += __shfl_xor_sync(0xffffffffu, s, off);
        q += __shfl_xor_sync(0xffffffffu, q, off);
    }
    __shared__ float rs[8], rq[8];
    if ((tid & 31) == 0) { rs[tid >> 5] = s; rq[tid >> 5] = q; }
    __syncthreads();
    if (tid == 0) {
        float S = 0.f, Q = 0.f;
#pragma unroll
        for (int w = 0; w < 8; w++) { S += rs[w]; Q += rq[w]; }
        const float mean = S / (float)NROWS;
        const float var  = Q / (float)NROWS - mean * mean;
        const float sc   = gamma[c] * rsqrtf(var + 1e-5f);
        g_scale[z * HH + c] = sc;
        g_shift[z * HH + c] = beta_bn[c] - mean * sc;
    }
}

// ---------------------------------------------------------------------------
// FUSED: GEMM2 (both z) + cosine + GEMM3 + head -> out. (unchanged, proven)
// ---------------------------------------------------------------------------
#define F2_AB   (128 * AST * 2)        // 18432
#define F2_ASTG (2 * F2_AB)            // 36864
#define F2_AREG (2 * F2_ASTG)          // 73728
#define F2_BB   (128 * AST * 2)        // 18432
#define F2_BSTG (2 * F2_BB)            // 36864
#define F2_BREG (2 * F2_BSTG)          // 73728
#define F2_DYN  (F2_AREG + F2_BREG)    // 147456
#define ST3 136

__global__ void __launch_bounds__(256) fused2(
    const float* __restrict__ b2, const float* __restrict__ b3,
    const float* __restrict__ W4, const float* __restrict__ b4,
    const float* __restrict__ alphap, const float* __restrict__ betap,
    float* __restrict__ out)
{
    extern __shared__ char dyn[];
    __shared__ float s_sc[HH];
    __shared__ float s_sh[HH];
    __shared__ float s_red[4][128][4];

    const int rb   = blockIdx.x;
    const int row0 = rb * 128;
    const int tid  = threadIdx.x;
    const int lane = tid & 31;
    const int wid  = tid >> 5;
    const int wm   = wid >> 2;       // 0..1
    const int wn   = wid & 3;        // 0..3
    const int g    = lane >> 2;
    const int tg   = lane & 3;
    const int ln16 = lane & 15;
    const int lhalf = (lane >> 4) & 1;

    char* Areg = dyn;
    char* Breg = dyn + F2_AREG;

    float acc[4][4][4];
    float h1[4][4][4];
    float4 aNext[8];

    const uint32_t aOff2 = ((wm * 64 + ln16) * AST + lhalf * 8) * 2;
    const uint32_t bOff2 = ((wn * 32 + (ln16 & 7)) * AST + ((ln16 >> 3) * 8)) * 2;

#define F2_LDA(zz, c) do { \
        const int kk_ = (c) * 64; \
        _Pragma("unroll") \
        for (int it = 0; it < 8; it++) { \
            int idx = tid + it * 256; \
            int r_  = idx >> 4, c4_ = idx & 15; \
            aNext[it] = *reinterpret_cast<const float4*>( \
                g_hraw + ((size_t)(zz) * NROWS + row0 + r_) * HH + kk_ + c4_ * 4); \
        } \
    } while (0)

#define F2_STA(c, stg) do { \
        const int kk_ = (c) * 64; \
        char* sAhi_ = Areg + (stg) * F2_ASTG; \
        char* sAlo_ = sAhi_ + F2_AB; \
        _Pragma("unroll") \
        for (int it = 0; it < 8; it++) { \
            int idx = tid + it * 256; \
            int r_  = idx >> 4, c4_ = idx & 15; \
            const int col_ = kk_ + c4_ * 4; \
            float a0 = fmaxf(s_sc[col_ + 0] * aNext[it].x + s_sh[col_ + 0], 0.0f); \
            float a1 = fmaxf(s_sc[col_ + 1] * aNext[it].y + s_sh[col_ + 1], 0.0f); \
            float a2 = fmaxf(s_sc[col_ + 2] * aNext[it].z + s_sh[col_ + 2], 0.0f); \
            float a3 = fmaxf(s_sc[col_ + 3] * aNext[it].w + s_sh[col_ + 3], 0.0f); \
            uint32_t h0, l0, h1_, l1; \
            split2(a0, a1, h0, l0); \
            split2(a2, a3, h1_, l1); \
            int off = (r_ * AST + c4_ * 4) * 2; \
            *reinterpret_cast<uint2*>(sAhi_ + off) = make_uint2(h0, h1_); \
            *reinterpret_cast<uint2*>(sAlo_ + off) = make_uint2(l0, l1); \
        } \
    } while (0)

#define F2_CPB(c, stg) do { \
        const int kk_ = (c) * 64; \
        char* sBhi_ = Breg + (stg) * F2_BSTG; \
        char* sBlo_ = sBhi_ + F2_BB; \
        uint32_t bhiU = smem_u32(sBhi_), bloU = smem_u32(sBlo_); \
        _Pragma("unroll") \
        for (int it = 0; it < 4; it++) { \
            int idx = tid + it * 256; \
            int n_ = idx >> 3, c8_ = idx & 7; \
            int off = (n_ * AST + c8_ * 8) * 2; \
            cpasync16(bhiU + off, g_w2hi + (size_t)n_ * HH + kk_ + c8_ * 8); \
            cpasync16(bloU + off, g_w2lo + (size_t)n_ * HH + kk_ + c8_ * 8); \
        } \
        cpasync_commit(); \
    } while (0)

    // ========================= Phases 1 & 2: GEMM2 x2 =======================
    for (int z = 0; z < 2; z++) {
        __syncthreads();
        s_sc[tid] = g_scale[z * HH + tid];
        s_sh[tid] = g_shift[z * HH + tid];
        __syncthreads();

#pragma unroll
        for (int t = 0; t < 4; t++)
#pragma unroll
            for (int u = 0; u < 4; u++)
#pragma unroll
                for (int j = 0; j < 4; j++) acc[t][u][j] = 0.0f;

        F2_CPB(0, 0);
        F2_LDA(z, 0);
        F2_STA(0, 0);
        cpasync_wait0();
        __syncthreads();

        const int NC = 4;
        for (int c = 0; c < NC; c++) {
            const int s = c & 1;
            if (c + 1 < NC) {
                F2_CPB(c + 1, s ^ 1);
                F2_LDA(z, c + 1);
            }
            {
                uint32_t sAhiU = smem_u32(Areg + s * F2_ASTG);
                uint32_t sAloU = sAhiU + F2_AB;
                uint32_t sBhiU = smem_u32(Breg + s * F2_BSTG);
                uint32_t sBloU = sBhiU + F2_BB;
#pragma unroll
                for (int ks = 0; ks < 4; ks++) {
                    const uint32_t ko = ks * 32;
                    uint32_t Ah[4][4], Al[4][4], Bh[4][2], Bl[4][2];
#pragma unroll
                    for (int t = 0; t < 4; t++)
                        ldmatrix_x4(Ah[t], sAhiU + aOff2 + (t * 16 * AST) * 2 + ko);
#pragma unroll
                    for (int u = 0; u < 4; u++)
                        ldmatrix_x2(Bh[u], sBhiU + bOff2 + (u * 8 * AST) * 2 + ko);
#pragma unroll
                    for (int t = 0; t < 4; t++)
#pragma unroll
                        for (int u = 0; u < 4; u++)
                            mma_bf16(acc[t][u][0], acc[t][u][1], acc[t][u][2], acc[t][u][3],
                                     Ah[t][0], Ah[t][1], Ah[t][2], Ah[t][3],
                                     Bh[u][0], Bh[u][1]);
#pragma unroll
                    for (int u = 0; u < 4; u++)
                        ldmatrix_x2(Bl[u], sBloU + bOff2 + (u * 8 * AST) * 2 + ko);
#pragma unroll
                    for (int t = 0; t < 4; t++)
#pragma unroll
                        for (int u = 0; u < 4; u++)
                            mma_bf16(acc[t][u][0], acc[t][u][1], acc[t][u][2], acc[t][u][3],
                                     Ah[t][0], Ah[t][1], Ah[t][2], Ah[t][3],
                                     Bl[u][0], Bl[u][1]);
#pragma unroll
                    for (int t = 0; t < 4; t++)
                        ldmatrix_x4(Al[t], sAloU + aOff2 + (t * 16 * AST) * 2 + ko);
#pragma unroll
                    for (int t = 0; t < 4; t++)
#pragma unroll
                        for (int u = 0; u < 4; u++)
                            mma_bf16(acc[t][u][0], acc[t][u][1], acc[t][u][2], acc[t][u][3],
                                     Al[t][0], Al[t][1], Al[t][2], Al[t][3],
                                     Bh[u][0], Bh[u][1]);
                }
            }
            if (c + 1 < NC) {
                __syncthreads();
                F2_STA(c + 1, s ^ 1);
                cpasync_wait0();
                __syncthreads();
            }
        }

        // epilogue: h = relu(acc + b2); stash into h1 (z=0) or keep in acc (z=1)
#pragma unroll
        for (int u = 0; u < 4; u++) {
            const int col = wn * 32 + u * 8 + tg * 2;
            const float bi0 = b2[col], bi1 = b2[col + 1];
#pragma unroll
            for (int t = 0; t < 4; t++) {
                float v0 = fmaxf(acc[t][u][0] + bi0, 0.0f);
                float v1 = fmaxf(acc[t][u][1] + bi1, 0.0f);
                float v2 = fmaxf(acc[t][u][2] + bi0, 0.0f);
                float v3 = fmaxf(acc[t][u][3] + bi1, 0.0f);
                if (z == 0) {
                    h1[t][u][0] = v0; h1[t][u][1] = v1;
                    h1[t][u][2] = v2; h1[t][u][3] = v3;
                } else {
                    acc[t][u][0] = v0; acc[t][u][1] = v1;
                    acc[t][u][2] = v2; acc[t][u][3] = v3;
                }
            }
        }
    }

    // ================== cosine partials (row-wise) from fragments ==========
    {
        float dotR[8], n1R[8], n2R[8];
#pragma unroll
        for (int ri = 0; ri < 8; ri++) { dotR[ri] = 0.f; n1R[ri] = 0.f; n2R[ri] = 0.f; }
#pragma unroll
        for (int t = 0; t < 4; t++)
#pragma unroll
            for (int u = 0; u < 4; u++)
#pragma unroll
                for (int j = 0; j < 4; j++) {
                    const float a = h1[t][u][j];
                    const float b = acc[t][u][j];
                    const int ri = t * 2 + (j >> 1);
                    dotR[ri] = fmaf(a, b, dotR[ri]);
                    n1R[ri]  = fmaf(a, a, n1R[ri]);
                    n2R[ri]  = fmaf(b, b, n2R[ri]);
                }
#pragma unroll
        for (int off = 1; off < 4; off <<= 1) {
#pragma unroll
            for (int ri = 0; ri < 8; ri++) {
                dotR[ri] += __shfl_xor_sync(0xffffffffu, dotR[ri], off);
                n1R[ri]  += __shfl_xor_sync(0xffffffffu, n1R[ri], off);
                n2R[ri]  += __shfl_xor_sync(0xffffffffu, n2R[ri], off);
            }
        }
        if (tg == 0) {
#pragma unroll
            for (int ri = 0; ri < 8; ri++) {
                const int r = wm * 64 + (ri >> 1) * 16 + g + (ri & 1) * 8;
                s_red[0][r][wn] = dotR[ri];
                s_red[1][r][wn] = n1R[ri];
                s_red[2][r][wn] = n2R[ri];
            }
        }
    }

    // ==================== Phase 3: GEMM3 on tensor cores ====================
    float acc3[4][2][4];
#pragma unroll
    for (int t = 0; t < 4; t++)
#pragma unroll
        for (int u = 0; u < 2; u++)
#pragma unroll
            for (int j = 0; j < 4; j++) acc3[t][u][j] = 0.0f;

    const uint32_t aOff3 = ((wm * 64 + ln16) * ST3 + lhalf * 8) * 2;
    const uint32_t bOff3 = ((wn * 16 + (ln16 & 7)) * ST3 + ((ln16 >> 3) * 8)) * 2;
    char* A3hi = Areg;
    char* A3lo = Areg + 128 * ST3 * 2;
    uint32_t A3hiU = smem_u32(A3hi);
    uint32_t A3loU = A3hiU + 128 * ST3 * 2;
    uint32_t B3hiU = smem_u32(Breg);
    uint32_t B3loU = B3hiU + 64 * ST3 * 2;

    __syncthreads();

    for (int f = 0; f < 3; f++) {
#pragma unroll
        for (int it = 0; it < 4; it++) {
            int idx = tid + it * 256;
            int n_ = idx >> 4, cc = idx & 15;
            int off = (n_ * ST3 + cc * 8) * 2;
            cpasync16(B3hiU + off, g_w3hi + n_ * 384 + f * 128 + cc * 8);
            cpasync16(B3loU + off, g_w3lo + n_ * 384 + f * 128 + cc * 8);
        }
        cpasync_commit();

#pragma unroll
        for (int t = 0; t < 4; t++)
#pragma unroll
            for (int u = 0; u < 4; u++) {
                const int col = wn * 32 + u * 8 + tg * 2;
                const int r   = wm * 64 + t * 16 + g;
                float v[4];
#pragma unroll
                for (int j = 0; j < 4; j++) {
                    const float a = h1[t][u][j];
                    const float b = acc[t][u][j];
                    v[j] = (f == 0) ? a * b : (f == 1) ? fabsf(a - b) : a + b;
                }
                uint32_t hi0, lo0, hi1, lo1;
                split2(v[0], v[1], hi0, lo0);
                split2(v[2], v[3], hi1, lo1);
                *reinterpret_cast<uint32_t*>(A3hi + (r * ST3 + col) * 2)       = hi0;
                *reinterpret_cast<uint32_t*>(A3lo + (r * ST3 + col) * 2)       = lo0;
                *reinterpret_cast<uint32_t*>(A3hi + ((r + 8) * ST3 + col) * 2) = hi1;
                *reinterpret_cast<uint32_t*>(A3lo + ((r + 8) * ST3 + col) * 2) = lo1;
            }
        cpasync_wait0();
        __syncthreads();

#pragma unroll
        for (int ks = 0; ks < 8; ks++) {
            const uint32_t ko = ks * 32;
            uint32_t Ah[4][4], Al[4][4], Bh[2][2], Bl[2][2];
#pragma unroll
            for (int t = 0; t < 4; t++)
                ldmatrix_x4(Ah[t], A3hiU + aOff3 + (t * 16 * ST3) * 2 + ko);
#pragma unroll
            for (int u = 0; u < 2; u++)
                ldmatrix_x2(Bh[u], B3hiU + bOff3 + (u * 8 * ST3) * 2 + ko);
#pragma unroll
            for (int t = 0; t < 4; t++)
#pragma unroll
                for (int u = 0; u < 2; u++)
                    mma_bf16(acc3[t][u][0], acc3[t][u][1], acc3[t][u][2], acc3[t][u][3],
                             Ah[t][0], Ah[t][1], Ah[t][2], Ah[t][3],
                             Bh[u][0], Bh[u][1]);
#pragma unroll
            for (int u = 0; u < 2; u++)
                ldmatrix_x2(Bl[u], B3loU + bOff3 + (u * 8 * ST3) * 2 + ko);
#pragma unroll
            for (int t = 0; t < 4; t++)
#pragma unroll
                for (int u = 0; u < 2; u++)
                    mma_bf16(acc3[t][u][0], acc3[t][u][1], acc3[t][u][2], acc3[t][u][3],
                             Ah[t][0], Ah[t][1], Ah[t][2], Ah[t][3],
                             Bl[u][0], Bl[u][1]);
#pragma unroll
            for (int t = 0; t < 4; t++)
                ldmatrix_x4(Al[t], A3loU + aOff3 + (t * 16 * ST3) * 2 + ko);
#pragma unroll
            for (int t = 0; t < 4; t++)
#pragma unroll
                for (int u = 0; u < 2; u++)
                    mma_bf16(acc3[t][u][0], acc3[t][u][1], acc3[t][u][2], acc3[t][u][3],
                             Al[t][0], Al[t][1], Al[t][2], Al[t][3],
                             Bh[u][0], Bh[u][1]);
        }
        __syncthreads();
    }

    // ==================== Phase 4: relu -> W4 -> head =======================
    {
        float slR[8];
#pragma unroll
        for (int ri = 0; ri < 8; ri++) slR[ri] = 0.0f;
#pragma unroll
        for (int u = 0; u < 2; u++) {
            const int col = wn * 16 + u * 8 + tg * 2;
            const float b30 = b3[col], b31 = b3[col + 1];
            const float w40 = W4[col], w41 = W4[col + 1];
#pragma unroll
            for (int t = 0; t < 4; t++) {
                slR[t * 2 + 0] += fmaxf(acc3[t][u][0] + b30, 0.0f) * w40
                                + fmaxf(acc3[t][u][1] + b31, 0.0f) * w41;
                slR[t * 2 + 1] += fmaxf(acc3[t][u][2] + b30, 0.0f) * w40
                                + fmaxf(acc3[t][u][3] + b31, 0.0f) * w41;
            }
        }
#pragma unroll
        for (int off = 1; off < 4; off <<= 1)
#pragma unroll
            for (int ri = 0; ri < 8; ri++)
                slR[ri] += __shfl_xor_sync(0xffffffffu, slR[ri], off);
        if (tg == 0) {
#pragma unroll
            for (int ri = 0; ri < 8; ri++) {
                const int r = wm * 64 + (ri >> 1) * 16 + g + (ri & 1) * 8;
                s_red[3][r][wn] = slR[ri];
            }
        }
    }
    __syncthreads();

    if (tid < 128) {
        float dot = 0.f, n1v = 0.f, n2v = 0.f, sl = 0.f;
#pragma unroll
        for (int w = 0; w < 4; w++) {
            dot += s_red[0][tid][w];
            n1v += s_red[1][tid][w];
            n2v += s_red[2][tid][w];
            sl  += s_red[3][tid][w];
        }
        const float inv1   = 1.0f / fmaxf(sqrtf(n1v), 1e-15f);
        const float inv2   = 1.0f / fmaxf(sqrtf(n2v), 1e-15f);
        const float s_math = fminf(fmaxf(dot * inv1 * inv2, 0.0f), 1.0f);
        const float sig    = 1.0f / (1.0f + expf(-(sl + b4[0])));
        const float fin    = alphap[0] * s_math + betap[0] * sig;
        out[row0 + tid] = fminf(fmaxf(fin, 0.0f), 1.0f);
    }
#undef F2_LDA
#undef F2_STA
#undef F2_CPB
}

// ---------------------------------------------------------------------------
extern "C" void kernel_launch(void* const* d_in, const int* in_sizes, int n_in,
                              void* d_out, int out_size)
{
    const float* x1      = (const float*)d_in[0];
    const float* x2      = (const float*)d_in[1];
    const float* W1      = (const float*)d_in[2];
    const float* b1      = (const float*)d_in[3];
    const float* gamma   = (const float*)d_in[4];
    const float* beta_bn = (const float*)d_in[5];
    const float* W2      = (const float*)d_in[6];
    const float* b2      = (const float*)d_in[7];
    const float* W3      = (const float*)d_in[8];
    const float* b3      = (const float*)d_in[9];
    const float* W4      = (const float*)d_in[10];
    const float* b4      = (const float*)d_in[11];
    const float* alphap  = (const float*)d_in[12];
    const float* betap   = (const float*)d_in[13];
    float* out = (float*)d_out;

    cudaFuncSetAttribute(gemm1_mma,
                         cudaFuncAttributeMaxDynamicSharedMemorySize, G1_DYN);
    cudaFuncSetAttribute(fused2,
                         cudaFuncAttributeMaxDynamicSharedMemorySize, F2_DYN);

    const int prep_elems = DK * HH + HH * H2 + 384 * O3;
    prep_weights<<<(prep_elems + 255) / 256, 256>>>(W1, W2, W3);

    dim3 g1(NRB1, 2);
    gemm1_mma<<<g1, 512, G1_DYN>>>(x1, x2, b1);

    stats_kernel<<<512, 256>>>(gamma, beta_bn);

    fused2<<<NRB2, 256, F2_DYN>>>(b2, b3, W4, b4, alphap, betap, out);
}

// round 6
// speedup vs baseline: 3.6100x; 1.1714x over previous
#include <cuda_runtime.h>
#include <cuda_bf16.h>
#include <cuda_fp16.h>
#include <cstdint>
#include <math.h>

// ---------------------------------------------------------------------------
// Problem constants
// ---------------------------------------------------------------------------
#define NROWS 65536
#define DK    512
#define HH    256
#define H2    128
#define O3    64
#define NRB1  1024          // gemm1 row blocks of 64
#define NRB2  512           // fused2 row blocks of 128

// ---------------------------------------------------------------------------
// Scratch (device globals — allocation-free per harness rules)
// ---------------------------------------------------------------------------
__device__ float g_hraw[2 * NROWS * HH];     // 128 MB : pre-BN activations
__device__ float g_psum[2 * NRB1 * HH];
__device__ float g_psq [2 * NRB1 * HH];
__device__ float g_scale[2 * HH];
__device__ float g_shift[2 * HH];
// W1: fp16 hi/lo pair (K-major [256][512]) — gemm1 is 2-pass fp16
__device__ __align__(16) __half g_w1hi[HH * DK];
__device__ __align__(16) __half g_w1lo[HH * DK];
// W2/W3: bf16 hi/lo (3-pass path, unchanged)
__device__ __align__(16) __nv_bfloat16 g_w2hi[H2 * HH];
__device__ __align__(16) __nv_bfloat16 g_w2lo[H2 * HH];
__device__ __align__(16) __nv_bfloat16 g_w3hi[O3 * 384];
__device__ __align__(16) __nv_bfloat16 g_w3lo[O3 * 384];

// ---------------------------------------------------------------------------
// Warp-MMA helpers (base PTX — no sm_103a-only features)
// ---------------------------------------------------------------------------
__device__ __forceinline__ uint32_t smem_u32(const void* p) {
    uint32_t a;
    asm("{ .reg .u64 t; cvta.to.shared.u64 t, %1; cvt.u32.u64 %0, t; }"
        : "=r"(a) : "l"(p));
    return a;
}

__device__ __forceinline__ void mma_bf16(float& c0, float& c1, float& c2, float& c3,
                                         uint32_t a0, uint32_t a1, uint32_t a2, uint32_t a3,
                                         uint32_t b0, uint32_t b1) {
    asm volatile(
        "mma.sync.aligned.m16n8k16.row.col.f32.bf16.bf16.f32 "
        "{%0,%1,%2,%3}, {%4,%5,%6,%7}, {%8,%9}, {%0,%1,%2,%3};"
        : "+f"(c0), "+f"(c1), "+f"(c2), "+f"(c3)
        : "r"(a0), "r"(a1), "r"(a2), "r"(a3), "r"(b0), "r"(b1));
}

__device__ __forceinline__ void mma_f16(float& c0, float& c1, float& c2, float& c3,
                                        uint32_t a0, uint32_t a1, uint32_t a2, uint32_t a3,
                                        uint32_t b0, uint32_t b1) {
    asm volatile(
        "mma.sync.aligned.m16n8k16.row.col.f32.f16.f16.f32 "
        "{%0,%1,%2,%3}, {%4,%5,%6,%7}, {%8,%9}, {%0,%1,%2,%3};"
        : "+f"(c0), "+f"(c1), "+f"(c2), "+f"(c3)
        : "r"(a0), "r"(a1), "r"(a2), "r"(a3), "r"(b0), "r"(b1));
}

__device__ __forceinline__ void ldmatrix_x4(uint32_t* r, uint32_t addr) {
    asm volatile("ldmatrix.sync.aligned.m8n8.x4.shared.b16 {%0,%1,%2,%3}, [%4];"
        : "=r"(r[0]), "=r"(r[1]), "=r"(r[2]), "=r"(r[3]) : "r"(addr));
}

__device__ __forceinline__ void ldmatrix_x2(uint32_t* r, uint32_t addr) {
    asm volatile("ldmatrix.sync.aligned.m8n8.x2.shared.b16 {%0,%1}, [%2];"
        : "=r"(r[0]), "=r"(r[1]) : "r"(addr));
}

__device__ __forceinline__ void cpasync16(uint32_t dst, const void* src) {
    asm volatile("cp.async.cg.shared.global [%0], [%1], 16;" :: "r"(dst), "l"(src));
}
__device__ __forceinline__ void cpasync_commit() {
    asm volatile("cp.async.commit_group;" ::: "memory");
}
__device__ __forceinline__ void cpasync_wait0() {
    asm volatile("cp.async.wait_group 0;" ::: "memory");
}

__device__ __forceinline__ uint32_t pack_bf(__nv_bfloat16 a, __nv_bfloat16 b) {
    return (uint32_t)__bfloat16_as_ushort(a) |
           ((uint32_t)__bfloat16_as_ushort(b) << 16);
}

// split (x,y) into packed hi/lo bf16 pairs (fused2 path)
__device__ __forceinline__ void split2(float x, float y, uint32_t& hi, uint32_t& lo) {
    __nv_bfloat16 hx = __float2bfloat16(x);
    __nv_bfloat16 hy = __float2bfloat16(y);
    float lx = x - __bfloat162float(hx);
    float ly = y - __bfloat162float(hy);
    hi = pack_bf(hx, hy);
    lo = pack_bf(__float2bfloat16(lx), __float2bfloat16(ly));
}

// pack (x,y) into one fp16x2 word (gemm1 A operand — single fp16, no split)
__device__ __forceinline__ uint32_t pack_h2(float x, float y) {
    __half2 h = __floats2half2_rn(x, y);
    return *reinterpret_cast<uint32_t*>(&h);
}

// ---------------------------------------------------------------------------
// Weight prep: W1 -> fp16 hi/lo [256][512]; W2 -> bf16 [128][256];
// W3 -> bf16 [64][384].
// ---------------------------------------------------------------------------
__global__ void prep_weights(const float* __restrict__ W1,
                             const float* __restrict__ W2,
                             const float* __restrict__ W3)
{
    int i = blockIdx.x * 256 + threadIdx.x;
    if (i < DK * HH) {
        int k = i >> 8, n = i & 255;
        float v = W1[i];
        __half h = __float2half_rn(v);
        g_w1hi[n * DK + k] = h;
        g_w1lo[n * DK + k] = __float2half_rn(v - __half2float(h));
        return;
    }
    int j = i - DK * HH;
    if (j < HH * H2) {
        int k = j >> 7, n = j & 127;
        float v = W2[j];
        __nv_bfloat16 h = __float2bfloat16(v);
        g_w2hi[n * HH + k] = h;
        g_w2lo[n * HH + k] = __float2bfloat16(v - __bfloat162float(h));
        return;
    }
    int j2 = j - HH * H2;
    if (j2 < 384 * O3) {
        int k = j2 >> 6, n = j2 & 63;
        float v = W3[j2];
        __nv_bfloat16 h = __float2bfloat16(v);
        g_w3hi[n * 384 + k] = h;
        g_w3lo[n * 384 + k] = __float2bfloat16(v - __bfloat162float(h));
    }
}

// ---------------------------------------------------------------------------
// GEMM1 v4 (mma.sync fp16, 2 passes): hraw = X @ W1 + b1, plus column stats.
// A = fp16(x) single; B = W1 fp16 hi/lo. Passes: A*Bhi + A*Blo.
// CTA 64x256, 512 threads (16 warps, 2m x 8n), warp tile 32x32, 2 stages.
// ---------------------------------------------------------------------------
#define AST 72
#define G1_AB  (64 * AST * 2)                 // 9216  (single A buffer)
#define G1_BB  (256 * AST * 2)                // 36864 per B buffer
#define G1_STAGE (G1_AB + 2 * G1_BB)          // 82944
#define G1_DYN   (2 * G1_STAGE)               // 165888

__global__ void __launch_bounds__(512) gemm1_mma(
    const float* __restrict__ x1, const float* __restrict__ x2,
    const float* __restrict__ b1)
{
    extern __shared__ char dyn[];
    const int z    = blockIdx.y;
    const int rb   = blockIdx.x;
    const int row0 = rb * 64;
    const float* __restrict__ X = z ? x2 : x1;

    const int tid  = threadIdx.x;
    const int lane = tid & 31;
    const int wid  = tid >> 5;
    const int wm   = wid >> 3;       // 0..1
    const int wn   = wid & 7;        // 0..7
    const int g    = lane >> 2;      // 0..7
    const int tg   = lane & 3;       // 0..3
    const int ln16 = lane & 15;
    const int lhalf = (lane >> 4) & 1;

    float acc[2][4][4];
#pragma unroll
    for (int t = 0; t < 2; t++)
#pragma unroll
        for (int u = 0; u < 4; u++)
#pragma unroll
            for (int j = 0; j < 4; j++) acc[t][u][j] = 0.0f;

    float4 aNext[2];

#define G1_LDA(c) do { \
        const int kk_ = (c) * 64; \
        _Pragma("unroll") \
        for (int it = 0; it < 2; it++) { \
            int idx = tid + it * 512; \
            int r_  = idx >> 4, c4_ = idx & 15; \
            aNext[it] = *reinterpret_cast<const float4*>( \
                X + (size_t)(row0 + r_) * DK + kk_ + c4_ * 4); \
        } \
    } while (0)

#define G1_STA(stg) do { \
        char* sAh_ = dyn + (stg) * G1_STAGE; \
        _Pragma("unroll") \
        for (int it = 0; it < 2; it++) { \
            int idx = tid + it * 512; \
            int r_  = idx >> 4, c4_ = idx & 15; \
            uint32_t p0 = pack_h2(aNext[it].x, aNext[it].y); \
            uint32_t p1 = pack_h2(aNext[it].z, aNext[it].w); \
            int off = (r_ * AST + c4_ * 4) * 2; \
            *reinterpret_cast<uint2*>(sAh_ + off) = make_uint2(p0, p1); \
        } \
    } while (0)

#define G1_CPB(c, stg) do { \
        const int kk_ = (c) * 64; \
        char* sBhi_ = dyn + (stg) * G1_STAGE + G1_AB; \
        char* sBlo_ = sBhi_ + G1_BB; \
        uint32_t bhiU = smem_u32(sBhi_), bloU = smem_u32(sBlo_); \
        _Pragma("unroll") \
        for (int it = 0; it < 4; it++) { \
            int idx = tid + it * 512; \
            int n_ = idx >> 3, c8_ = idx & 7; \
            int off = (n_ * AST + c8_ * 8) * 2; \
            cpasync16(bhiU + off, g_w1hi + (size_t)n_ * DK + kk_ + c8_ * 8); \
            cpasync16(bloU + off, g_w1lo + (size_t)n_ * DK + kk_ + c8_ * 8); \
        } \
        cpasync_commit(); \
    } while (0)

    G1_CPB(0, 0);
    G1_LDA(0);
    G1_STA(0);
    cpasync_wait0();
    __syncthreads();

    const int NC = DK / 64;   // 8
    for (int c = 0; c < NC; c++) {
        const int s = c & 1;
        if (c + 1 < NC) {
            G1_CPB(c + 1, s ^ 1);
            G1_LDA(c + 1);
        }

        {
            char* st = dyn + s * G1_STAGE;
            uint32_t sAhU  = smem_u32(st);
            uint32_t sBhiU = sAhU + G1_AB;
            uint32_t sBloU = sBhiU + G1_BB;

            const uint32_t aOff = ((wm * 32 + ln16) * AST + lhalf * 8) * 2;
            const uint32_t bOff = (((wn * 32) + (ln16 & 7)) * AST + ((ln16 >> 3) * 8)) * 2;

#pragma unroll
            for (int ks = 0; ks < 4; ks++) {
                const uint32_t ko = ks * 32;
                uint32_t Ah[2][4], Bh[4][2], Bl[4][2];
#pragma unroll
                for (int t = 0; t < 2; t++)
                    ldmatrix_x4(Ah[t], sAhU + aOff + (t * 16 * AST) * 2 + ko);
#pragma unroll
                for (int u = 0; u < 4; u++)
                    ldmatrix_x2(Bh[u], sBhiU + bOff + (u * 8 * AST) * 2 + ko);
#pragma unroll
                for (int t = 0; t < 2; t++)
#pragma unroll
                    for (int u = 0; u < 4; u++)
                        mma_f16(acc[t][u][0], acc[t][u][1], acc[t][u][2], acc[t][u][3],
                                Ah[t][0], Ah[t][1], Ah[t][2], Ah[t][3],
                                Bh[u][0], Bh[u][1]);
#pragma unroll
                for (int u = 0; u < 4; u++)
                    ldmatrix_x2(Bl[u], sBloU + bOff + (u * 8 * AST) * 2 + ko);
#pragma unroll
                for (int t = 0; t < 2; t++)
#pragma unroll
                    for (int u = 0; u < 4; u++)
                        mma_f16(acc[t][u][0], acc[t][u][1], acc[t][u][2], acc[t][u][3],
                                Ah[t][0], Ah[t][1], Ah[t][2], Ah[t][3],
                                Bl[u][0], Bl[u][1]);
            }
        }

        if (c + 1 < NC) {
            G1_STA(s ^ 1);
            cpasync_wait0();
            __syncthreads();
        }
    }

    // ---- epilogue: bias, store hraw, column partial stats ----
    float css0[4], css1[4], cqq0[4], cqq1[4];
#pragma unroll
    for (int u = 0; u < 4; u++) {
        const int col = wn * 32 + u * 8 + tg * 2;
        const float bi0 = b1[col], bi1 = b1[col + 1];
        float cs0 = 0.f, cs1 = 0.f, cq0 = 0.f, cq1 = 0.f;
#pragma unroll
        for (int t = 0; t < 2; t++) {
            const int r = row0 + wm * 32 + t * 16 + g;
            float v0 = acc[t][u][0] + bi0;
            float v1 = acc[t][u][1] + bi1;
            float v2 = acc[t][u][2] + bi0;
            float v3 = acc[t][u][3] + bi1;
            *reinterpret_cast<float2*>(
                &g_hraw[((size_t)z * NROWS + r) * HH + col])     = make_float2(v0, v1);
            *reinterpret_cast<float2*>(
                &g_hraw[((size_t)z * NROWS + r + 8) * HH + col]) = make_float2(v2, v3);
            cs0 += v0 + v2; cs1 += v1 + v3;
            cq0 += v0 * v0 + v2 * v2; cq1 += v1 * v1 + v3 * v3;
        }
        css0[u] = cs0; css1[u] = cs1; cqq0[u] = cq0; cqq1[u] = cq1;
    }
#pragma unroll
    for (int off = 4; off < 32; off <<= 1) {
#pragma unroll
        for (int u = 0; u < 4; u++) {
            css0[u] += __shfl_xor_sync(0xffffffffu, css0[u], off);
            css1[u] += __shfl_xor_sync(0xffffffffu, css1[u], off);
            cqq0[u] += __shfl_xor_sync(0xffffffffu, cqq0[u], off);
            cqq1[u] += __shfl_xor_sync(0xffffffffu, cqq1[u], off);
        }
    }
    float* s_ps = reinterpret_cast<float*>(dyn);   // [2][256]
    float* s_sq = s_ps + 512;
    __syncthreads();
    if (g == 0) {
#pragma unroll
        for (int u = 0; u < 4; u++) {
            const int col = wn * 32 + u * 8 + tg * 2;
            s_ps[wm * 256 + col]     = css0[u];
            s_ps[wm * 256 + col + 1] = css1[u];
            s_sq[wm * 256 + col]     = cqq0[u];
            s_sq[wm * 256 + col + 1] = cqq1[u];
        }
    }
    __syncthreads();
    if (tid < 256) {
        g_psum[((size_t)z * NRB1 + rb) * HH + tid] = s_ps[tid] + s_ps[256 + tid];
        g_psq [((size_t)z * NRB1 + rb) * HH + tid] = s_sq[tid] + s_sq[256 + tid];
    }
#undef G1_LDA
#undef G1_STA
#undef G1_CPB
}

// ---------------------------------------------------------------------------
// Stats: one block per (z, column); 256 threads reduce 1024 partials.
// ---------------------------------------------------------------------------
__global__ void __launch_bounds__(256) stats_kernel(
    const float* __restrict__ gamma, const float* __restrict__ beta_bn)
{
    const int z = blockIdx.x >> 8;
    const int c = blockIdx.x & 255;
    const int tid = threadIdx.x;

    float s = 0.0f, q = 0.0f;
    for (int i = tid; i < NRB1; i += 256) {
        s += g_psum[((size_t)z * NRB1 + i) * HH + c];
        q += g_psq [((size_t)z * NRB1 + i) * HH + c];
    }
#pragma unroll
    for (int off = 16; off > 0; off >>= 1) {
        s += __shfl_xor_sync(0xffffffffu, s, off);
        q += __shfl_xor_sync(0xffffffffu, q, off);
    }
    __shared__ float rs[8], rq[8];
    if ((tid & 31) == 0) { rs[tid >> 5] = s; rq[tid >> 5] = q; }
    __syncthreads();
    if (tid == 0) {
        float S = 0.f, Q = 0.f;
#pragma unroll
        for (int w = 0; w < 8; w++) { S += rs[w]; Q += rq[w]; }
        const float mean = S / (float)NROWS;
        const float var  = Q / (float)NROWS - mean * mean;
        const float sc   = gamma[c] * rsqrtf(var + 1e-5f);
        g_scale[z * HH + c] = sc;
        g_shift[z * HH + c] = beta_bn[c] - mean * sc;
    }
}

// ---------------------------------------------------------------------------
// FUSED: GEMM2 (both z) + cosine + GEMM3 + head -> out. (bf16 3-pass, proven)
// ---------------------------------------------------------------------------
#define F2_AB   (128 * AST * 2)        // 18432
#define F2_ASTG (2 * F2_AB)            // 36864
#define F2_AREG (2 * F2_ASTG)          // 73728
#define F2_BB   (128 * AST * 2)        // 18432
#define F2_BSTG (2 * F2_BB)            // 36864
#define F2_BREG (2 * F2_BSTG)          // 73728
#define F2_DYN  (F2_AREG + F2_BREG)    // 147456
#define ST3 136

__global__ void __launch_bounds__(256) fused2(
    const float* __restrict__ b2, const float* __restrict__ b3,
    const float* __restrict__ W4, const float* __restrict__ b4,
    const float* __restrict__ alphap, const float* __restrict__ betap,
    float* __restrict__ out)
{
    extern __shared__ char dyn[];
    __shared__ float s_sc[HH];
    __shared__ float s_sh[HH];
    __shared__ float s_red[4][128][4];

    const int rb   = blockIdx.x;
    const int row0 = rb * 128;
    const int tid  = threadIdx.x;
    const int lane = tid & 31;
    const int wid  = tid >> 5;
    const int wm   = wid >> 2;       // 0..1
    const int wn   = wid & 3;        // 0..3
    const int g    = lane >> 2;
    const int tg   = lane & 3;
    const int ln16 = lane & 15;
    const int lhalf = (lane >> 4) & 1;

    char* Areg = dyn;
    char* Breg = dyn + F2_AREG;

    float acc[4][4][4];
    float h1[4][4][4];
    float4 aNext[8];

    const uint32_t aOff2 = ((wm * 64 + ln16) * AST + lhalf * 8) * 2;
    const uint32_t bOff2 = ((wn * 32 + (ln16 & 7)) * AST + ((ln16 >> 3) * 8)) * 2;

#define F2_LDA(zz, c) do { \
        const int kk_ = (c) * 64; \
        _Pragma("unroll") \
        for (int it = 0; it < 8; it++) { \
            int idx = tid + it * 256; \
            int r_  = idx >> 4, c4_ = idx & 15; \
            aNext[it] = *reinterpret_cast<const float4*>( \
                g_hraw + ((size_t)(zz) * NROWS + row0 + r_) * HH + kk_ + c4_ * 4); \
        } \
    } while (0)

#define F2_STA(c, stg) do { \
        const int kk_ = (c) * 64; \
        char* sAhi_ = Areg + (stg) * F2_ASTG; \
        char* sAlo_ = sAhi_ + F2_AB; \
        _Pragma("unroll") \
        for (int it = 0; it < 8; it++) { \
            int idx = tid + it * 256; \
            int r_  = idx >> 4, c4_ = idx & 15; \
            const int col_ = kk_ + c4_ * 4; \
            float a0 = fmaxf(s_sc[col_ + 0] * aNext[it].x + s_sh[col_ + 0], 0.0f); \
            float a1 = fmaxf(s_sc[col_ + 1] * aNext[it].y + s_sh[col_ + 1], 0.0f); \
            float a2 = fmaxf(s_sc[col_ + 2] * aNext[it].z + s_sh[col_ + 2], 0.0f); \
            float a3 = fmaxf(s_sc[col_ + 3] * aNext[it].w + s_sh[col_ + 3], 0.0f); \
            uint32_t h0, l0, h1_, l1; \
            split2(a0, a1, h0, l0); \
            split2(a2, a3, h1_, l1); \
            int off = (r_ * AST + c4_ * 4) * 2; \
            *reinterpret_cast<uint2*>(sAhi_ + off) = make_uint2(h0, h1_); \
            *reinterpret_cast<uint2*>(sAlo_ + off) = make_uint2(l0, l1); \
        } \
    } while (0)

#define F2_CPB(c, stg) do { \
        const int kk_ = (c) * 64; \
        char* sBhi_ = Breg + (stg) * F2_BSTG; \
        char* sBlo_ = sBhi_ + F2_BB; \
        uint32_t bhiU = smem_u32(sBhi_), bloU = smem_u32(sBlo_); \
        _Pragma("unroll") \
        for (int it = 0; it < 4; it++) { \
            int idx = tid + it * 256; \
            int n_ = idx >> 3, c8_ = idx & 7; \
            int off = (n_ * AST + c8_ * 8) * 2; \
            cpasync16(bhiU + off, g_w2hi + (size_t)n_ * HH + kk_ + c8_ * 8); \
            cpasync16(bloU + off, g_w2lo + (size_t)n_ * HH + kk_ + c8_ * 8); \
        } \
        cpasync_commit(); \
    } while (0)

    // ========================= Phases 1 & 2: GEMM2 x2 =======================
    for (int z = 0; z < 2; z++) {
        __syncthreads();
        s_sc[tid] = g_scale[z * HH + tid];
        s_sh[tid] = g_shift[z * HH + tid];
        __syncthreads();

#pragma unroll
        for (int t = 0; t < 4; t++)
#pragma unroll
            for (int u = 0; u < 4; u++)
#pragma unroll
                for (int j = 0; j < 4; j++) acc[t][u][j] = 0.0f;

        F2_CPB(0, 0);
        F2_LDA(z, 0);
        F2_STA(0, 0);
        cpasync_wait0();
        __syncthreads();

        const int NC = 4;
        for (int c = 0; c < NC; c++) {
            const int s = c & 1;
            if (c + 1 < NC) {
                F2_CPB(c + 1, s ^ 1);
                F2_LDA(z, c + 1);
            }
            {
                uint32_t sAhiU = smem_u32(Areg + s * F2_ASTG);
                uint32_t sAloU = sAhiU + F2_AB;
                uint32_t sBhiU = smem_u32(Breg + s * F2_BSTG);
                uint32_t sBloU = sBhiU + F2_BB;
#pragma unroll
                for (int ks = 0; ks < 4; ks++) {
                    const uint32_t ko = ks * 32;
                    uint32_t Ah[4][4], Al[4][4], Bh[4][2], Bl[4][2];
#pragma unroll
                    for (int t = 0; t < 4; t++)
                        ldmatrix_x4(Ah[t], sAhiU + aOff2 + (t * 16 * AST) * 2 + ko);
#pragma unroll
                    for (int u = 0; u < 4; u++)
                        ldmatrix_x2(Bh[u], sBhiU + bOff2 + (u * 8 * AST) * 2 + ko);
#pragma unroll
                    for (int t = 0; t < 4; t++)
#pragma unroll
                        for (int u = 0; u < 4; u++)
                            mma_bf16(acc[t][u][0], acc[t][u][1], acc[t][u][2], acc[t][u][3],
                                     Ah[t][0], Ah[t][1], Ah[t][2], Ah[t][3],
                                     Bh[u][0], Bh[u][1]);
#pragma unroll
                    for (int u = 0; u < 4; u++)
                        ldmatrix_x2(Bl[u], sBloU + bOff2 + (u * 8 * AST) * 2 + ko);
#pragma unroll
                    for (int t = 0; t < 4; t++)
#pragma unroll
                        for (int u = 0; u < 4; u++)
                            mma_bf16(acc[t][u][0], acc[t][u][1], acc[t][u][2], acc[t][u][3],
                                     Ah[t][0], Ah[t][1], Ah[t][2], Ah[t][3],
                                     Bl[u][0], Bl[u][1]);
#pragma unroll
                    for (int t = 0; t < 4; t++)
                        ldmatrix_x4(Al[t], sAloU + aOff2 + (t * 16 * AST) * 2 + ko);
#pragma unroll
                    for (int t = 0; t < 4; t++)
#pragma unroll
                        for (int u = 0; u < 4; u++)
                            mma_bf16(acc[t][u][0], acc[t][u][1], acc[t][u][2], acc[t][u][3],
                                     Al[t][0], Al[t][1], Al[t][2], Al[t][3],
                                     Bh[u][0], Bh[u][1]);
                }
            }
            if (c + 1 < NC) {
                __syncthreads();
                F2_STA(c + 1, s ^ 1);
                cpasync_wait0();
                __syncthreads();
            }
        }

        // epilogue: h = relu(acc + b2); stash into h1 (z=0) or keep in acc (z=1)
#pragma unroll
        for (int u = 0; u < 4; u++) {
            const int col = wn * 32 + u * 8 + tg * 2;
            const float bi0 = b2[col], bi1 = b2[col + 1];
#pragma unroll
            for (int t = 0; t < 4; t++) {
                float v0 = fmaxf(acc[t][u][0] + bi0, 0.0f);
                float v1 = fmaxf(acc[t][u][1] + bi1, 0.0f);
                float v2 = fmaxf(acc[t][u][2] + bi0, 0.0f);
                float v3 = fmaxf(acc[t][u][3] + bi1, 0.0f);
                if (z == 0) {
                    h1[t][u][0] = v0; h1[t][u][1] = v1;
                    h1[t][u][2] = v2; h1[t][u][3] = v3;
                } else {
                    acc[t][u][0] = v0; acc[t][u][1] = v1;
                    acc[t][u][2] = v2; acc[t][u][3] = v3;
                }
            }
        }
    }

    // ================== cosine partials (row-wise) from fragments ==========
    {
        float dotR[8], n1R[8], n2R[8];
#pragma unroll
        for (int ri = 0; ri < 8; ri++) { dotR[ri] = 0.f; n1R[ri] = 0.f; n2R[ri] = 0.f; }
#pragma unroll
        for (int t = 0; t < 4; t++)
#pragma unroll
            for (int u = 0; u < 4; u++)
#pragma unroll
                for (int j = 0; j < 4; j++) {
                    const float a = h1[t][u][j];
                    const float b = acc[t][u][j];
                    const int ri = t * 2 + (j >> 1);
                    dotR[ri] = fmaf(a, b, dotR[ri]);
                    n1R[ri]  = fmaf(a, a, n1R[ri]);
                    n2R[ri]  = fmaf(b, b, n2R[ri]);
                }
#pragma unroll
        for (int off = 1; off < 4; off <<= 1) {
#pragma unroll
            for (int ri = 0; ri < 8; ri++) {
                dotR[ri] += __shfl_xor_sync(0xffffffffu, dotR[ri], off);
                n1R[ri]  += __shfl_xor_sync(0xffffffffu, n1R[ri], off);
                n2R[ri]  += __shfl_xor_sync(0xffffffffu, n2R[ri], off);
            }
        }
        if (tg == 0) {
#pragma unroll
            for (int ri = 0; ri < 8; ri++) {
                const int r = wm * 64 + (ri >> 1) * 16 + g + (ri & 1) * 8;
                s_red[0][r][wn] = dotR[ri];
                s_red[1][r][wn] = n1R[ri];
                s_red[2][r][wn] = n2R[ri];
            }
        }
    }

    // ==================== Phase 3: GEMM3 on tensor cores ====================
    float acc3[4][2][4];
#pragma unroll
    for (int t = 0; t < 4; t++)
#pragma unroll
        for (int u = 0; u < 2; u++)
#pragma unroll
            for (int j = 0; j < 4; j++) acc3[t][u][j] = 0.0f;

    const uint32_t aOff3 = ((wm * 64 + ln16) * ST3 + lhalf * 8) * 2;
    const uint32_t bOff3 = ((wn * 16 + (ln16 & 7)) * ST3 + ((ln16 >> 3) * 8)) * 2;
    char* A3hi = Areg;
    char* A3lo = Areg + 128 * ST3 * 2;
    uint32_t A3hiU = smem_u32(A3hi);
    uint32_t A3loU = A3hiU + 128 * ST3 * 2;
    uint32_t B3hiU = smem_u32(Breg);
    uint32_t B3loU = B3hiU + 64 * ST3 * 2;

    __syncthreads();

    for (int f = 0; f < 3; f++) {
#pragma unroll
        for (int it = 0; it < 4; it++) {
            int idx = tid + it * 256;
            int n_ = idx >> 4, cc = idx & 15;
            int off = (n_ * ST3 + cc * 8) * 2;
            cpasync16(B3hiU + off, g_w3hi + n_ * 384 + f * 128 + cc * 8);
            cpasync16(B3loU + off, g_w3lo + n_ * 384 + f * 128 + cc * 8);
        }
        cpasync_commit();

#pragma unroll
        for (int t = 0; t < 4; t++)
#pragma unroll
            for (int u = 0; u < 4; u++) {
                const int col = wn * 32 + u * 8 + tg * 2;
                const int r   = wm * 64 + t * 16 + g;
                float v[4];
#pragma unroll
                for (int j = 0; j < 4; j++) {
                    const float a = h1[t][u][j];
                    const float b = acc[t][u][j];
                    v[j] = (f == 0) ? a * b : (f == 1) ? fabsf(a - b) : a + b;
                }
                uint32_t hi0, lo0, hi1, lo1;
                split2(v[0], v[1], hi0, lo0);
                split2(v[2], v[3], hi1, lo1);
                *reinterpret_cast<uint32_t*>(A3hi + (r * ST3 + col) * 2)       = hi0;
                *reinterpret_cast<uint32_t*>(A3lo + (r * ST3 + col) * 2)       = lo0;
                *reinterpret_cast<uint32_t*>(A3hi + ((r + 8) * ST3 + col) * 2) = hi1;
                *reinterpret_cast<uint32_t*>(A3lo + ((r + 8) * ST3 + col) * 2) = lo1;
            }
        cpasync_wait0();
        __syncthreads();

#pragma unroll
        for (int ks = 0; ks < 8; ks++) {
            const uint32_t ko = ks * 32;
            uint32_t Ah[4][4], Al[4][4], Bh[2][2], Bl[2][2];
#pragma unroll
            for (int t = 0; t < 4; t++)
                ldmatrix_x4(Ah[t], A3hiU + aOff3 + (t * 16 * ST3) * 2 + ko);
#pragma unroll
            for (int u = 0; u < 2; u++)
                ldmatrix_x2(Bh[u], B3hiU + bOff3 + (u * 8 * ST3) * 2 + ko);
#pragma unroll
            for (int t = 0; t < 4; t++)
#pragma unroll
                for (int u = 0; u < 2; u++)
                    mma_bf16(acc3[t][u][0], acc3[t][u][1], acc3[t][u][2], acc3[t][u][3],
                             Ah[t][0], Ah[t][1], Ah[t][2], Ah[t][3],
                             Bh[u][0], Bh[u][1]);
#pragma unroll
            for (int u = 0; u < 2; u++)
                ldmatrix_x2(Bl[u], B3loU + bOff3 + (u * 8 * ST3) * 2 + ko);
#pragma unroll
            for (int t = 0; t < 4; t++)
#pragma unroll
                for (int u = 0; u < 2; u++)
                    mma_bf16(acc3[t][u][0], acc3[t][u][1], acc3[t][u][2], acc3[t][u][3],
                             Ah[t][0], Ah[t][1], Ah[t][2], Ah[t][3],
                             Bl[u][0], Bl[u][1]);
#pragma unroll
            for (int t = 0; t < 4; t++)
                ldmatrix_x4(Al[t], A3loU + aOff3 + (t * 16 * ST3) * 2 + ko);
#pragma unroll
            for (int t = 0; t < 4; t++)
#pragma unroll
                for (int u = 0; u < 2; u++)
                    mma_bf16(acc3[t][u][0], acc3[t][u][1], acc3[t][u][2], acc3[t][u][3],
                             Al[t][0], Al[t][1], Al[t][2], Al[t][3],
                             Bh[u][0], Bh[u][1]);
        }
        __syncthreads();
    }

    // ==================== Phase 4: relu -> W4 -> head =======================
    {
        float slR[8];
#pragma unroll
        for (int ri = 0; ri < 8; ri++) slR[ri] = 0.0f;
#pragma unroll
        for (int u = 0; u < 2; u++) {
            const int col = wn * 16 + u * 8 + tg * 2;
            const float b30 = b3[col], b31 = b3[col + 1];
            const float w40 = W4[col], w41 = W4[col + 1];
#pragma unroll
            for (int t = 0; t < 4; t++) {
                slR[t * 2 + 0] += fmaxf(acc3[t][u][0] + b30, 0.0f) * w40
                                + fmaxf(acc3[t][u][1] + b31, 0.0f) * w41;
                slR[t * 2 + 1] += fmaxf(acc3[t][u][2] + b30, 0.0f) * w40
                                + fmaxf(acc3[t][u][3] + b31, 0.0f) * w41;
            }
        }
#pragma unroll
        for (int off = 1; off < 4; off <<= 1)
#pragma unroll
            for (int ri = 0; ri < 8; ri++)
                slR[ri] += __shfl_xor_sync(0xffffffffu, slR[ri], off);
        if (tg == 0) {
#pragma unroll
            for (int ri = 0; ri < 8; ri++) {
                const int r = wm * 64 + (ri >> 1) * 16 + g + (ri & 1) * 8;
                s_red[3][r][wn] = slR[ri];
            }
        }
    }
    __syncthreads();

    if (tid < 128) {
        float dot = 0.f, n1v = 0.f, n2v = 0.f, sl = 0.f;
#pragma unroll
        for (int w = 0; w < 4; w++) {
            dot += s_red[0][tid][w];
            n1v += s_red[1][tid][w];
            n2v += s_red[2][tid][w];
            sl  += s_red[3][tid][w];
        }
        const float inv1   = 1.0f / fmaxf(sqrtf(n1v), 1e-15f);
        const float inv2   = 1.0f / fmaxf(sqrtf(n2v), 1e-15f);
        const float s_math = fminf(fmaxf(dot * inv1 * inv2, 0.0f), 1.0f);
        const float sig    = 1.0f / (1.0f + expf(-(sl + b4[0])));
        const float fin    = alphap[0] * s_math + betap[0] * sig;
        out[row0 + tid] = fminf(fmaxf(fin, 0.0f), 1.0f);
    }
#undef F2_LDA
#undef F2_STA
#undef F2_CPB
}

// ---------------------------------------------------------------------------
extern "C" void kernel_launch(void* const* d_in, const int* in_sizes, int n_in,
                              void* d_out, int out_size)
{
    const float* x1      = (const float*)d_in[0];
    const float* x2      = (const float*)d_in[1];
    const float* W1      = (const float*)d_in[2];
    const float* b1      = (const float*)d_in[3];
    const float* gamma   = (const float*)d_in[4];
    const float* beta_bn = (const float*)d_in[5];
    const float* W2      = (const float*)d_in[6];
    const float* b2      = (const float*)d_in[7];
    const float* W3      = (const float*)d_in[8];
    const float* b3      = (const float*)d_in[9];
    const float* W4      = (const float*)d_in[10];
    const float* b4      = (const float*)d_in[11];
    const float* alphap  = (const float*)d_in[12];
    const float* betap   = (const float*)d_in[13];
    float* out = (float*)d_out;

    cudaFuncSetAttribute(gemm1_mma,
                         cudaFuncAttributeMaxDynamicSharedMemorySize, G1_DYN);
    cudaFuncSetAttribute(fused2,
                         cudaFuncAttributeMaxDynamicSharedMemorySize, F2_DYN);

    const int prep_elems = DK * HH + HH * H2 + 384 * O3;
    prep_weights<<<(prep_elems + 255) / 256, 256>>>(W1, W2, W3);

    dim3 g1(NRB1, 2);
    gemm1_mma<<<g1, 512, G1_DYN>>>(x1, x2, b1);

    stats_kernel<<<512, 256>>>(gamma, beta_bn);

    fused2<<<NRB2, 256, F2_DYN>>>(b2, b3, W4, b4, alphap, betap, out);
}

// round 7
// speedup vs baseline: 5.9715x; 1.6542x over previous
#include <cuda_runtime.h>
#include <cuda_bf16.h>
#include <cuda_fp16.h>
#include <cstdint>
#include <math.h>

// ---------------------------------------------------------------------------
// Problem constants
// ---------------------------------------------------------------------------
#define NROWS 65536
#define DK    512
#define HH    256
#define H2    128
#define O3    64
#define NRB1  1024          // gemm1 row blocks of 64
#define NRB2  512           // fused2 row blocks of 128

// ---------------------------------------------------------------------------
// Scratch (device globals — allocation-free per harness rules)
// ---------------------------------------------------------------------------
__device__ float g_hraw[2 * NROWS * HH];     // 128 MB : pre-BN activations
__device__ float g_psum[2 * NRB1 * HH];
__device__ float g_psq [2 * NRB1 * HH];
__device__ float g_scale[2 * HH];
__device__ float g_shift[2 * HH];
// W1: single fp16 (K-major [256][512]) — gemm1 is 1-pass fp16
__device__ __align__(16) __half g_w1[HH * DK];
// W2/W3: fp16 hi/lo (2-pass path in fused2)
__device__ __align__(16) __half g_w2hi[H2 * HH];
__device__ __align__(16) __half g_w2lo[H2 * HH];
__device__ __align__(16) __half g_w3hi[O3 * 384];
__device__ __align__(16) __half g_w3lo[O3 * 384];

// ---------------------------------------------------------------------------
// Warp-MMA helpers (base PTX — no sm_103a-only features)
// ---------------------------------------------------------------------------
__device__ __forceinline__ uint32_t smem_u32(const void* p) {
    uint32_t a;
    asm("{ .reg .u64 t; cvta.to.shared.u64 t, %1; cvt.u32.u64 %0, t; }"
        : "=r"(a) : "l"(p));
    return a;
}

__device__ __forceinline__ void mma_f16(float& c0, float& c1, float& c2, float& c3,
                                        uint32_t a0, uint32_t a1, uint32_t a2, uint32_t a3,
                                        uint32_t b0, uint32_t b1) {
    asm volatile(
        "mma.sync.aligned.m16n8k16.row.col.f32.f16.f16.f32 "
        "{%0,%1,%2,%3}, {%4,%5,%6,%7}, {%8,%9}, {%0,%1,%2,%3};"
        : "+f"(c0), "+f"(c1), "+f"(c2), "+f"(c3)
        : "r"(a0), "r"(a1), "r"(a2), "r"(a3), "r"(b0), "r"(b1));
}

__device__ __forceinline__ void ldmatrix_x4(uint32_t* r, uint32_t addr) {
    asm volatile("ldmatrix.sync.aligned.m8n8.x4.shared.b16 {%0,%1,%2,%3}, [%4];"
        : "=r"(r[0]), "=r"(r[1]), "=r"(r[2]), "=r"(r[3]) : "r"(addr));
}

__device__ __forceinline__ void ldmatrix_x2(uint32_t* r, uint32_t addr) {
    asm volatile("ldmatrix.sync.aligned.m8n8.x2.shared.b16 {%0,%1}, [%2];"
        : "=r"(r[0]), "=r"(r[1]) : "r"(addr));
}

__device__ __forceinline__ void cpasync16(uint32_t dst, const void* src) {
    asm volatile("cp.async.cg.shared.global [%0], [%1], 16;" :: "r"(dst), "l"(src));
}
__device__ __forceinline__ void cpasync_commit() {
    asm volatile("cp.async.commit_group;" ::: "memory");
}
__device__ __forceinline__ void cpasync_wait0() {
    asm volatile("cp.async.wait_group 0;" ::: "memory");
}

// pack (x,y) into one fp16x2 word
__device__ __forceinline__ uint32_t pack_h2(float x, float y) {
    __half2 h = __floats2half2_rn(x, y);
    return *reinterpret_cast<uint32_t*>(&h);
}

// ---------------------------------------------------------------------------
// Weight prep: W1 -> fp16 single [256][512]; W2 -> fp16 hi/lo [128][256];
// W3 -> fp16 hi/lo [64][384].
// ---------------------------------------------------------------------------
__global__ void prep_weights(const float* __restrict__ W1,
                             const float* __restrict__ W2,
                             const float* __restrict__ W3)
{
    int i = blockIdx.x * 256 + threadIdx.x;
    if (i < DK * HH) {
        int k = i >> 8, n = i & 255;
        g_w1[n * DK + k] = __float2half_rn(W1[i]);
        return;
    }
    int j = i - DK * HH;
    if (j < HH * H2) {
        int k = j >> 7, n = j & 127;
        float v = W2[j];
        __half h = __float2half_rn(v);
        g_w2hi[n * HH + k] = h;
        g_w2lo[n * HH + k] = __float2half_rn(v - __half2float(h));
        return;
    }
    int j2 = j - HH * H2;
    if (j2 < 384 * O3) {
        int k = j2 >> 6, n = j2 & 63;
        float v = W3[j2];
        __half h = __float2half_rn(v);
        g_w3hi[n * 384 + k] = h;
        g_w3lo[n * 384 + k] = __float2half_rn(v - __half2float(h));
    }
}

// ---------------------------------------------------------------------------
// GEMM1 v5 (mma.sync fp16, SINGLE pass): hraw = X @ W1 + b1, plus stats.
// CTA 64x256, 512 threads (16 warps, 2m x 8n), warp tile 32x32, 2 stages.
// ---------------------------------------------------------------------------
#define AST 72
#define G1_AB  (64 * AST * 2)                 // 9216
#define G1_BB  (256 * AST * 2)                // 36864
#define G1_STAGE (G1_AB + G1_BB)              // 46080
#define G1_DYN   (2 * G1_STAGE)               // 92160

__global__ void __launch_bounds__(512) gemm1_mma(
    const float* __restrict__ x1, const float* __restrict__ x2,
    const float* __restrict__ b1)
{
    extern __shared__ char dyn[];
    const int z    = blockIdx.y;
    const int rb   = blockIdx.x;
    const int row0 = rb * 64;
    const float* __restrict__ X = z ? x2 : x1;

    const int tid  = threadIdx.x;
    const int lane = tid & 31;
    const int wid  = tid >> 5;
    const int wm   = wid >> 3;       // 0..1
    const int wn   = wid & 7;        // 0..7
    const int g    = lane >> 2;      // 0..7
    const int tg   = lane & 3;       // 0..3
    const int ln16 = lane & 15;
    const int lhalf = (lane >> 4) & 1;

    float acc[2][4][4];
#pragma unroll
    for (int t = 0; t < 2; t++)
#pragma unroll
        for (int u = 0; u < 4; u++)
#pragma unroll
            for (int j = 0; j < 4; j++) acc[t][u][j] = 0.0f;

    float4 aNext[2];

#define G1_LDA(c) do { \
        const int kk_ = (c) * 64; \
        _Pragma("unroll") \
        for (int it = 0; it < 2; it++) { \
            int idx = tid + it * 512; \
            int r_  = idx >> 4, c4_ = idx & 15; \
            aNext[it] = *reinterpret_cast<const float4*>( \
                X + (size_t)(row0 + r_) * DK + kk_ + c4_ * 4); \
        } \
    } while (0)

#define G1_STA(stg) do { \
        char* sAh_ = dyn + (stg) * G1_STAGE; \
        _Pragma("unroll") \
        for (int it = 0; it < 2; it++) { \
            int idx = tid + it * 512; \
            int r_  = idx >> 4, c4_ = idx & 15; \
            uint32_t p0 = pack_h2(aNext[it].x, aNext[it].y); \
            uint32_t p1 = pack_h2(aNext[it].z, aNext[it].w); \
            int off = (r_ * AST + c4_ * 4) * 2; \
            *reinterpret_cast<uint2*>(sAh_ + off) = make_uint2(p0, p1); \
        } \
    } while (0)

#define G1_CPB(c, stg) do { \
        const int kk_ = (c) * 64; \
        char* sB_ = dyn + (stg) * G1_STAGE + G1_AB; \
        uint32_t bU = smem_u32(sB_); \
        _Pragma("unroll") \
        for (int it = 0; it < 4; it++) { \
            int idx = tid + it * 512; \
            int n_ = idx >> 3, c8_ = idx & 7; \
            int off = (n_ * AST + c8_ * 8) * 2; \
            cpasync16(bU + off, g_w1 + (size_t)n_ * DK + kk_ + c8_ * 8); \
        } \
        cpasync_commit(); \
    } while (0)

    G1_CPB(0, 0);
    G1_LDA(0);
    G1_STA(0);
    cpasync_wait0();
    __syncthreads();

    const int NC = DK / 64;   // 8
    for (int c = 0; c < NC; c++) {
        const int s = c & 1;
        if (c + 1 < NC) {
            G1_CPB(c + 1, s ^ 1);
            G1_LDA(c + 1);
        }

        {
            char* st = dyn + s * G1_STAGE;
            uint32_t sAhU = smem_u32(st);
            uint32_t sBU  = sAhU + G1_AB;

            const uint32_t aOff = ((wm * 32 + ln16) * AST + lhalf * 8) * 2;
            const uint32_t bOff = (((wn * 32) + (ln16 & 7)) * AST + ((ln16 >> 3) * 8)) * 2;

#pragma unroll
            for (int ks = 0; ks < 4; ks++) {
                const uint32_t ko = ks * 32;
                uint32_t Ah[2][4], Bh[4][2];
#pragma unroll
                for (int t = 0; t < 2; t++)
                    ldmatrix_x4(Ah[t], sAhU + aOff + (t * 16 * AST) * 2 + ko);
#pragma unroll
                for (int u = 0; u < 4; u++)
                    ldmatrix_x2(Bh[u], sBU + bOff + (u * 8 * AST) * 2 + ko);
#pragma unroll
                for (int t = 0; t < 2; t++)
#pragma unroll
                    for (int u = 0; u < 4; u++)
                        mma_f16(acc[t][u][0], acc[t][u][1], acc[t][u][2], acc[t][u][3],
                                Ah[t][0], Ah[t][1], Ah[t][2], Ah[t][3],
                                Bh[u][0], Bh[u][1]);
            }
        }

        if (c + 1 < NC) {
            G1_STA(s ^ 1);
            cpasync_wait0();
            __syncthreads();
        }
    }

    // ---- epilogue: bias, store hraw, column partial stats ----
    float css0[4], css1[4], cqq0[4], cqq1[4];
#pragma unroll
    for (int u = 0; u < 4; u++) {
        const int col = wn * 32 + u * 8 + tg * 2;
        const float bi0 = b1[col], bi1 = b1[col + 1];
        float cs0 = 0.f, cs1 = 0.f, cq0 = 0.f, cq1 = 0.f;
#pragma unroll
        for (int t = 0; t < 2; t++) {
            const int r = row0 + wm * 32 + t * 16 + g;
            float v0 = acc[t][u][0] + bi0;
            float v1 = acc[t][u][1] + bi1;
            float v2 = acc[t][u][2] + bi0;
            float v3 = acc[t][u][3] + bi1;
            *reinterpret_cast<float2*>(
                &g_hraw[((size_t)z * NROWS + r) * HH + col])     = make_float2(v0, v1);
            *reinterpret_cast<float2*>(
                &g_hraw[((size_t)z * NROWS + r + 8) * HH + col]) = make_float2(v2, v3);
            cs0 += v0 + v2; cs1 += v1 + v3;
            cq0 += v0 * v0 + v2 * v2; cq1 += v1 * v1 + v3 * v3;
        }
        css0[u] = cs0; css1[u] = cs1; cqq0[u] = cq0; cqq1[u] = cq1;
    }
#pragma unroll
    for (int off = 4; off < 32; off <<= 1) {
#pragma unroll
        for (int u = 0; u < 4; u++) {
            css0[u] += __shfl_xor_sync(0xffffffffu, css0[u], off);
            css1[u] += __shfl_xor_sync(0xffffffffu, css1[u], off);
            cqq0[u] += __shfl_xor_sync(0xffffffffu, cqq0[u], off);
            cqq1[u] += __shfl_xor_sync(0xffffffffu, cqq1[u], off);
        }
    }
    float* s_ps = reinterpret_cast<float*>(dyn);   // [2][256]
    float* s_sq = s_ps + 512;
    __syncthreads();
    if (g == 0) {
#pragma unroll
        for (int u = 0; u < 4; u++) {
            const int col = wn * 32 + u * 8 + tg * 2;
            s_ps[wm * 256 + col]     = css0[u];
            s_ps[wm * 256 + col + 1] = css1[u];
            s_sq[wm * 256 + col]     = cqq0[u];
            s_sq[wm * 256 + col + 1] = cqq1[u];
        }
    }
    __syncthreads();
    if (tid < 256) {
        g_psum[((size_t)z * NRB1 + rb) * HH + tid] = s_ps[tid] + s_ps[256 + tid];
        g_psq [((size_t)z * NRB1 + rb) * HH + tid] = s_sq[tid] + s_sq[256 + tid];
    }
#undef G1_LDA
#undef G1_STA
#undef G1_CPB
}

// ---------------------------------------------------------------------------
// Stats: one block per (z, column); 256 threads reduce 1024 partials.
// ---------------------------------------------------------------------------
__global__ void __launch_bounds__(256) stats_kernel(
    const float* __restrict__ gamma, const float* __restrict__ beta_bn)
{
    const int z = blockIdx.x >> 8;
    const int c = blockIdx.x & 255;
    const int tid = threadIdx.x;

    float s = 0.0f, q = 0.0f;
    for (int i = tid; i < NRB1; i += 256) {
        s += g_psum[((size_t)z * NRB1 + i) * HH + c];
        q += g_psq [((size_t)z * NRB1 + i) * HH + c];
    }
#pragma unroll
    for (int off = 16; off > 0; off >>= 1) {
        s += __shfl_xor_sync(0xffffffffu, s, off);
        q += __shfl_xor_sync(0xffffffffu, q, off);
    }
    __shared__ float rs[8], rq[8];
    if ((tid & 31) == 0) { rs[tid >> 5] = s; rq[tid >> 5] = q; }
    __syncthreads();
    if (tid == 0) {
        float S = 0.f, Q = 0.f;
#pragma unroll
        for (int w = 0; w < 8; w++) { S += rs[w]; Q += rq[w]; }
        const float mean = S / (float)NROWS;
        const float var  = Q / (float)NROWS - mean * mean;
        const float sc   = gamma[c] * rsqrtf(var + 1e-5f);
        g_scale[z * HH + c] = sc;
        g_shift[z * HH + c] = beta_bn[c] - mean * sc;
    }
}

// ---------------------------------------------------------------------------
// FUSED v2 (fp16 2-pass): GEMM2 (both z) + cosine + GEMM3 + head -> out.
// A = single fp16; W2/W3 = fp16 hi/lo. CTA 128 rows, 8 warps.
// smem: A region 36864 (2 stages x 128x64 fp16 @72);
//       B region 73728 (2 stages x (Bhi+Blo 128x64@72)).
// Phase 3 reuse: A region -> combined tile 128x128@136 fp16 (34816);
//                B region -> W3 chunk hi/lo 64x128@136 (34816).
// ---------------------------------------------------------------------------
#define F2_AB   (128 * AST * 2)        // 18432 (single A stage)
#define F2_AREG (2 * F2_AB)            // 36864
#define F2_BB   (128 * AST * 2)        // 18432
#define F2_BSTG (2 * F2_BB)            // 36864
#define F2_BREG (2 * F2_BSTG)          // 73728
#define F2_DYN  (F2_AREG + F2_BREG)    // 110592
#define ST3 136

__global__ void __launch_bounds__(256) fused2(
    const float* __restrict__ b2, const float* __restrict__ b3,
    const float* __restrict__ W4, const float* __restrict__ b4,
    const float* __restrict__ alphap, const float* __restrict__ betap,
    float* __restrict__ out)
{
    extern __shared__ char dyn[];
    __shared__ float s_sc[HH];
    __shared__ float s_sh[HH];
    __shared__ float s_red[4][128][4];

    const int rb   = blockIdx.x;
    const int row0 = rb * 128;
    const int tid  = threadIdx.x;
    const int lane = tid & 31;
    const int wid  = tid >> 5;
    const int wm   = wid >> 2;       // 0..1
    const int wn   = wid & 3;        // 0..3
    const int g    = lane >> 2;
    const int tg   = lane & 3;
    const int ln16 = lane & 15;
    const int lhalf = (lane >> 4) & 1;

    char* Areg = dyn;
    char* Breg = dyn + F2_AREG;

    float acc[4][4][4];
    float h1[4][4][4];
    float4 aNext[8];

    const uint32_t aOff2 = ((wm * 64 + ln16) * AST + lhalf * 8) * 2;
    const uint32_t bOff2 = ((wn * 32 + (ln16 & 7)) * AST + ((ln16 >> 3) * 8)) * 2;

#define F2_LDA(zz, c) do { \
        const int kk_ = (c) * 64; \
        _Pragma("unroll") \
        for (int it = 0; it < 8; it++) { \
            int idx = tid + it * 256; \
            int r_  = idx >> 4, c4_ = idx & 15; \
            aNext[it] = *reinterpret_cast<const float4*>( \
                g_hraw + ((size_t)(zz) * NROWS + row0 + r_) * HH + kk_ + c4_ * 4); \
        } \
    } while (0)

#define F2_STA(c, stg) do { \
        const int kk_ = (c) * 64; \
        char* sA_ = Areg + (stg) * F2_AB; \
        _Pragma("unroll") \
        for (int it = 0; it < 8; it++) { \
            int idx = tid + it * 256; \
            int r_  = idx >> 4, c4_ = idx & 15; \
            const int col_ = kk_ + c4_ * 4; \
            float a0 = fmaxf(s_sc[col_ + 0] * aNext[it].x + s_sh[col_ + 0], 0.0f); \
            float a1 = fmaxf(s_sc[col_ + 1] * aNext[it].y + s_sh[col_ + 1], 0.0f); \
            float a2 = fmaxf(s_sc[col_ + 2] * aNext[it].z + s_sh[col_ + 2], 0.0f); \
            float a3 = fmaxf(s_sc[col_ + 3] * aNext[it].w + s_sh[col_ + 3], 0.0f); \
            uint32_t p0 = pack_h2(a0, a1); \
            uint32_t p1 = pack_h2(a2, a3); \
            int off = (r_ * AST + c4_ * 4) * 2; \
            *reinterpret_cast<uint2*>(sA_ + off) = make_uint2(p0, p1); \
        } \
    } while (0)

#define F2_CPB(c, stg) do { \
        const int kk_ = (c) * 64; \
        char* sBhi_ = Breg + (stg) * F2_BSTG; \
        char* sBlo_ = sBhi_ + F2_BB; \
        uint32_t bhiU = smem_u32(sBhi_), bloU = smem_u32(sBlo_); \
        _Pragma("unroll") \
        for (int it = 0; it < 4; it++) { \
            int idx = tid + it * 256; \
            int n_ = idx >> 3, c8_ = idx & 7; \
            int off = (n_ * AST + c8_ * 8) * 2; \
            cpasync16(bhiU + off, g_w2hi + (size_t)n_ * HH + kk_ + c8_ * 8); \
            cpasync16(bloU + off, g_w2lo + (size_t)n_ * HH + kk_ + c8_ * 8); \
        } \
        cpasync_commit(); \
    } while (0)

    // ========================= Phases 1 & 2: GEMM2 x2 =======================
    for (int z = 0; z < 2; z++) {
        __syncthreads();
        s_sc[tid] = g_scale[z * HH + tid];
        s_sh[tid] = g_shift[z * HH + tid];
        __syncthreads();

#pragma unroll
        for (int t = 0; t < 4; t++)
#pragma unroll
            for (int u = 0; u < 4; u++)
#pragma unroll
                for (int j = 0; j < 4; j++) acc[t][u][j] = 0.0f;

        F2_CPB(0, 0);
        F2_LDA(z, 0);
        F2_STA(0, 0);
        cpasync_wait0();
        __syncthreads();

        const int NC = 4;
        for (int c = 0; c < NC; c++) {
            const int s = c & 1;
            if (c + 1 < NC) {
                F2_CPB(c + 1, s ^ 1);
                F2_LDA(z, c + 1);
            }
            {
                uint32_t sAU   = smem_u32(Areg + s * F2_AB);
                uint32_t sBhiU = smem_u32(Breg + s * F2_BSTG);
                uint32_t sBloU = sBhiU + F2_BB;
#pragma unroll
                for (int ks = 0; ks < 4; ks++) {
                    const uint32_t ko = ks * 32;
                    uint32_t Ah[4][4], Bh[4][2], Bl[4][2];
#pragma unroll
                    for (int t = 0; t < 4; t++)
                        ldmatrix_x4(Ah[t], sAU + aOff2 + (t * 16 * AST) * 2 + ko);
#pragma unroll
                    for (int u = 0; u < 4; u++)
                        ldmatrix_x2(Bh[u], sBhiU + bOff2 + (u * 8 * AST) * 2 + ko);
#pragma unroll
                    for (int t = 0; t < 4; t++)
#pragma unroll
                        for (int u = 0; u < 4; u++)
                            mma_f16(acc[t][u][0], acc[t][u][1], acc[t][u][2], acc[t][u][3],
                                    Ah[t][0], Ah[t][1], Ah[t][2], Ah[t][3],
                                    Bh[u][0], Bh[u][1]);
#pragma unroll
                    for (int u = 0; u < 4; u++)
                        ldmatrix_x2(Bl[u], sBloU + bOff2 + (u * 8 * AST) * 2 + ko);
#pragma unroll
                    for (int t = 0; t < 4; t++)
#pragma unroll
                        for (int u = 0; u < 4; u++)
                            mma_f16(acc[t][u][0], acc[t][u][1], acc[t][u][2], acc[t][u][3],
                                    Ah[t][0], Ah[t][1], Ah[t][2], Ah[t][3],
                                    Bl[u][0], Bl[u][1]);
                }
            }
            if (c + 1 < NC) {
                __syncthreads();
                F2_STA(c + 1, s ^ 1);
                cpasync_wait0();
                __syncthreads();
            }
        }

        // epilogue: h = relu(acc + b2); stash into h1 (z=0) or keep in acc (z=1)
#pragma unroll
        for (int u = 0; u < 4; u++) {
            const int col = wn * 32 + u * 8 + tg * 2;
            const float bi0 = b2[col], bi1 = b2[col + 1];
#pragma unroll
            for (int t = 0; t < 4; t++) {
                float v0 = fmaxf(acc[t][u][0] + bi0, 0.0f);
                float v1 = fmaxf(acc[t][u][1] + bi1, 0.0f);
                float v2 = fmaxf(acc[t][u][2] + bi0, 0.0f);
                float v3 = fmaxf(acc[t][u][3] + bi1, 0.0f);
                if (z == 0) {
                    h1[t][u][0] = v0; h1[t][u][1] = v1;
                    h1[t][u][2] = v2; h1[t][u][3] = v3;
                } else {
                    acc[t][u][0] = v0; acc[t][u][1] = v1;
                    acc[t][u][2] = v2; acc[t][u][3] = v3;
                }
            }
        }
    }

    // ================== cosine partials (row-wise) from fragments ==========
    {
        float dotR[8], n1R[8], n2R[8];
#pragma unroll
        for (int ri = 0; ri < 8; ri++) { dotR[ri] = 0.f; n1R[ri] = 0.f; n2R[ri] = 0.f; }
#pragma unroll
        for (int t = 0; t < 4; t++)
#pragma unroll
            for (int u = 0; u < 4; u++)
#pragma unroll
                for (int j = 0; j < 4; j++) {
                    const float a = h1[t][u][j];
                    const float b = acc[t][u][j];
                    const int ri = t * 2 + (j >> 1);
                    dotR[ri] = fmaf(a, b, dotR[ri]);
                    n1R[ri]  = fmaf(a, a, n1R[ri]);
                    n2R[ri]  = fmaf(b, b, n2R[ri]);
                }
#pragma unroll
        for (int off = 1; off < 4; off <<= 1) {
#pragma unroll
            for (int ri = 0; ri < 8; ri++) {
                dotR[ri] += __shfl_xor_sync(0xffffffffu, dotR[ri], off);
                n1R[ri]  += __shfl_xor_sync(0xffffffffu, n1R[ri], off);
                n2R[ri]  += __shfl_xor_sync(0xffffffffu, n2R[ri], off);
            }
        }
        if (tg == 0) {
#pragma unroll
            for (int ri = 0; ri < 8; ri++) {
                const int r = wm * 64 + (ri >> 1) * 16 + g + (ri & 1) * 8;
                s_red[0][r][wn] = dotR[ri];
                s_red[1][r][wn] = n1R[ri];
                s_red[2][r][wn] = n2R[ri];
            }
        }
    }

    // ==================== Phase 3: GEMM3 on tensor cores (2-pass) ===========
    float acc3[4][2][4];
#pragma unroll
    for (int t = 0; t < 4; t++)
#pragma unroll
        for (int u = 0; u < 2; u++)
#pragma unroll
            for (int j = 0; j < 4; j++) acc3[t][u][j] = 0.0f;

    const uint32_t aOff3 = ((wm * 64 + ln16) * ST3 + lhalf * 8) * 2;
    const uint32_t bOff3 = ((wn * 16 + (ln16 & 7)) * ST3 + ((ln16 >> 3) * 8)) * 2;
    char* A3 = Areg;                         // 128*136*2 = 34816 <= 36864
    uint32_t A3U   = smem_u32(A3);
    uint32_t B3hiU = smem_u32(Breg);         // 64*136*2 = 17408
    uint32_t B3loU = B3hiU + 64 * ST3 * 2;

    __syncthreads();   // all warps done with phase-2 stages + s_red written

    for (int f = 0; f < 3; f++) {
        // prefetch W3 chunk f (hi + lo)
#pragma unroll
        for (int it = 0; it < 4; it++) {
            int idx = tid + it * 256;
            int n_ = idx >> 4, cc = idx & 15;
            int off = (n_ * ST3 + cc * 8) * 2;
            cpasync16(B3hiU + off, g_w3hi + n_ * 384 + f * 128 + cc * 8);
            cpasync16(B3loU + off, g_w3lo + n_ * 384 + f * 128 + cc * 8);
        }
        cpasync_commit();

        // write combined feature tile into A region (single fp16, stride ST3)
#pragma unroll
        for (int t = 0; t < 4; t++)
#pragma unroll
            for (int u = 0; u < 4; u++) {
                const int col = wn * 32 + u * 8 + tg * 2;
                const int r   = wm * 64 + t * 16 + g;
                float v[4];
#pragma unroll
                for (int j = 0; j < 4; j++) {
                    const float a = h1[t][u][j];
                    const float b = acc[t][u][j];
                    v[j] = (f == 0) ? a * b : (f == 1) ? fabsf(a - b) : a + b;
                }
                *reinterpret_cast<uint32_t*>(A3 + (r * ST3 + col) * 2)       = pack_h2(v[0], v[1]);
                *reinterpret_cast<uint32_t*>(A3 + ((r + 8) * ST3 + col) * 2) = pack_h2(v[2], v[3]);
            }
        cpasync_wait0();
        __syncthreads();

        // MMA over k=128 (8 steps), 2 passes (Bhi, Blo)
#pragma unroll
        for (int ks = 0; ks < 8; ks++) {
            const uint32_t ko = ks * 32;
            uint32_t Ah[4][4], Bh[2][2], Bl[2][2];
#pragma unroll
            for (int t = 0; t < 4; t++)
                ldmatrix_x4(Ah[t], A3U + aOff3 + (t * 16 * ST3) * 2 + ko);
#pragma unroll
            for (int u = 0; u < 2; u++)
                ldmatrix_x2(Bh[u], B3hiU + bOff3 + (u * 8 * ST3) * 2 + ko);
#pragma unroll
            for (int t = 0; t < 4; t++)
#pragma unroll
                for (int u = 0; u < 2; u++)
                    mma_f16(acc3[t][u][0], acc3[t][u][1], acc3[t][u][2], acc3[t][u][3],
                            Ah[t][0], Ah[t][1], Ah[t][2], Ah[t][3],
                            Bh[u][0], Bh[u][1]);
#pragma unroll
            for (int u = 0; u < 2; u++)
                ldmatrix_x2(Bl[u], B3loU + bOff3 + (u * 8 * ST3) * 2 + ko);
#pragma unroll
            for (int t = 0; t < 4; t++)
#pragma unroll
                for (int u = 0; u < 2; u++)
                    mma_f16(acc3[t][u][0], acc3[t][u][1], acc3[t][u][2], acc3[t][u][3],
                            Ah[t][0], Ah[t][1], Ah[t][2], Ah[t][3],
                            Bl[u][0], Bl[u][1]);
        }
        __syncthreads();
    }

    // ==================== Phase 4: relu -> W4 -> head =======================
    {
        float slR[8];
#pragma unroll
        for (int ri = 0; ri < 8; ri++) slR[ri] = 0.0f;
#pragma unroll
        for (int u = 0; u < 2; u++) {
            const int col = wn * 16 + u * 8 + tg * 2;
            const float b30 = b3[col], b31 = b3[col + 1];
            const float w40 = W4[col], w41 = W4[col + 1];
#pragma unroll
            for (int t = 0; t < 4; t++) {
                slR[t * 2 + 0] += fmaxf(acc3[t][u][0] + b30, 0.0f) * w40
                                + fmaxf(acc3[t][u][1] + b31, 0.0f) * w41;
                slR[t * 2 + 1] += fmaxf(acc3[t][u][2] + b30, 0.0f) * w40
                                + fmaxf(acc3[t][u][3] + b31, 0.0f) * w41;
            }
        }
#pragma unroll
        for (int off = 1; off < 4; off <<= 1)
#pragma unroll
            for (int ri = 0; ri < 8; ri++)
                slR[ri] += __shfl_xor_sync(0xffffffffu, slR[ri], off);
        if (tg == 0) {
#pragma unroll
            for (int ri = 0; ri < 8; ri++) {
                const int r = wm * 64 + (ri >> 1) * 16 + g + (ri & 1) * 8;
                s_red[3][r][wn] = slR[ri];
            }
        }
    }
    __syncthreads();

    if (tid < 128) {
        float dot = 0.f, n1v = 0.f, n2v = 0.f, sl = 0.f;
#pragma unroll
        for (int w = 0; w < 4; w++) {
            dot += s_red[0][tid][w];
            n1v += s_red[1][tid][w];
            n2v += s_red[2][tid][w];
            sl  += s_red[3][tid][w];
        }
        const float inv1   = 1.0f / fmaxf(sqrtf(n1v), 1e-15f);
        const float inv2   = 1.0f / fmaxf(sqrtf(n2v), 1e-15f);
        const float s_math = fminf(fmaxf(dot * inv1 * inv2, 0.0f), 1.0f);
        const float sig    = 1.0f / (1.0f + expf(-(sl + b4[0])));
        const float fin    = alphap[0] * s_math + betap[0] * sig;
        out[row0 + tid] = fminf(fmaxf(fin, 0.0f), 1.0f);
    }
#undef F2_LDA
#undef F2_STA
#undef F2_CPB
}

// ---------------------------------------------------------------------------
extern "C" void kernel_launch(void* const* d_in, const int* in_sizes, int n_in,
                              void* d_out, int out_size)
{
    const float* x1      = (const float*)d_in[0];
    const float* x2      = (const float*)d_in[1];
    const float* W1      = (const float*)d_in[2];
    const float* b1      = (const float*)d_in[3];
    const float* gamma   = (const float*)d_in[4];
    const float* beta_bn = (const float*)d_in[5];
    const float* W2      = (const float*)d_in[6];
    const float* b2      = (const float*)d_in[7];
    const float* W3      = (const float*)d_in[8];
    const float* b3      = (const float*)d_in[9];
    const float* W4      = (const float*)d_in[10];
    const float* b4      = (const float*)d_in[11];
    const float* alphap  = (const float*)d_in[12];
    const float* betap   = (const float*)d_in[13];
    float* out = (float*)d_out;

    cudaFuncSetAttribute(gemm1_mma,
                         cudaFuncAttributeMaxDynamicSharedMemorySize, G1_DYN);
    cudaFuncSetAttribute(fused2,
                         cudaFuncAttributeMaxDynamicSharedMemorySize, F2_DYN);

    const int prep_elems = DK * HH + HH * H2 + 384 * O3;
    prep_weights<<<(prep_elems + 255) / 256, 256>>>(W1, W2, W3);

    dim3 g1(NRB1, 2);
    gemm1_mma<<<g1, 512, G1_DYN>>>(x1, x2, b1);

    stats_kernel<<<512, 256>>>(gamma, beta_bn);

    fused2<<<NRB2, 256, F2_DYN>>>(b2, b3, W4, b4, alphap, betap, out);
}

// round 9
// speedup vs baseline: 6.9617x; 1.1658x over previous
#include <cuda_runtime.h>
#include <cuda_bf16.h>
#include <cuda_fp16.h>
#include <cstdint>
#include <math.h>

// ---------------------------------------------------------------------------
// Problem constants
// ---------------------------------------------------------------------------
#define NROWS 65536
#define DK    512
#define HH    256
#define H2    128
#define O3    64
#define NRB1  1024          // gemm1 row blocks of 64
#define NRB2  512           // fused2 row blocks of 128

// ---------------------------------------------------------------------------
// Scratch (device globals — allocation-free per harness rules)
// ---------------------------------------------------------------------------
__device__ __align__(16) __half g_hraw[2 * NROWS * HH];   // 64 MB fp16 pre-BN
__device__ float g_psum[2 * NRB1 * HH];
__device__ float g_psq [2 * NRB1 * HH];
__device__ float g_scale[2 * HH];
__device__ float g_shift[2 * HH];
// All weights single fp16, transposed K-major [N][K]
__device__ __align__(16) __half g_w1[HH * DK];
__device__ __align__(16) __half g_w2[H2 * HH];
__device__ __align__(16) __half g_w3[O3 * 384];

// ---------------------------------------------------------------------------
// Warp-MMA helpers (base PTX — no sm_103a-only features)
// ---------------------------------------------------------------------------
__device__ __forceinline__ uint32_t smem_u32(const void* p) {
    uint32_t a;
    asm("{ .reg .u64 t; cvta.to.shared.u64 t, %1; cvt.u32.u64 %0, t; }"
        : "=r"(a) : "l"(p));
    return a;
}

__device__ __forceinline__ void mma_f16(float& c0, float& c1, float& c2, float& c3,
                                        uint32_t a0, uint32_t a1, uint32_t a2, uint32_t a3,
                                        uint32_t b0, uint32_t b1) {
    asm volatile(
        "mma.sync.aligned.m16n8k16.row.col.f32.f16.f16.f32 "
        "{%0,%1,%2,%3}, {%4,%5,%6,%7}, {%8,%9}, {%0,%1,%2,%3};"
        : "+f"(c0), "+f"(c1), "+f"(c2), "+f"(c3)
        : "r"(a0), "r"(a1), "r"(a2), "r"(a3), "r"(b0), "r"(b1));
}

__device__ __forceinline__ void ldmatrix_x4(uint32_t* r, uint32_t addr) {
    asm volatile("ldmatrix.sync.aligned.m8n8.x4.shared.b16 {%0,%1,%2,%3}, [%4];"
        : "=r"(r[0]), "=r"(r[1]), "=r"(r[2]), "=r"(r[3]) : "r"(addr));
}

__device__ __forceinline__ void ldmatrix_x2(uint32_t* r, uint32_t addr) {
    asm volatile("ldmatrix.sync.aligned.m8n8.x2.shared.b16 {%0,%1}, [%2];"
        : "=r"(r[0]), "=r"(r[1]) : "r"(addr));
}

__device__ __forceinline__ void cpasync16(uint32_t dst, const void* src) {
    asm volatile("cp.async.cg.shared.global [%0], [%1], 16;" :: "r"(dst), "l"(src));
}
__device__ __forceinline__ void cpasync_commit() {
    asm volatile("cp.async.commit_group;" ::: "memory");
}
__device__ __forceinline__ void cpasync_wait0() {
    asm volatile("cp.async.wait_group 0;" ::: "memory");
}

// pack (x,y) into one fp16x2 word
__device__ __forceinline__ uint32_t pack_h2(float x, float y) {
    __half2 h = __floats2half2_rn(x, y);
    return *reinterpret_cast<uint32_t*>(&h);
}

__device__ __forceinline__ float2 unpack_h2(uint32_t u) {
    __half2 h = *reinterpret_cast<__half2*>(&u);
    return __half22float2(h);
}

// ---------------------------------------------------------------------------
// Weight prep: transpose to K-major fp16. W1[256][512], W2[128][256], W3[64][384].
// ---------------------------------------------------------------------------
__global__ void prep_weights(const float* __restrict__ W1,
                             const float* __restrict__ W2,
                             const float* __restrict__ W3)
{
    int i = blockIdx.x * 256 + threadIdx.x;
    if (i < DK * HH) {
        int k = i >> 8, n = i & 255;
        g_w1[n * DK + k] = __float2half_rn(W1[i]);
        return;
    }
    int j = i - DK * HH;
    if (j < HH * H2) {
        int k = j >> 7, n = j & 127;
        g_w2[n * HH + k] = __float2half_rn(W2[j]);
        return;
    }
    int j2 = j - HH * H2;
    if (j2 < 384 * O3) {
        int k = j2 >> 6, n = j2 & 63;
        g_w3[n * 384 + k] = __float2half_rn(W3[j2]);
    }
}

// ---------------------------------------------------------------------------
// GEMM1 (mma.sync fp16, single pass): hraw(fp16) = X @ W1 + b1, plus stats.
// CTA 64x256, 512 threads (16 warps, 2m x 8n), warp tile 32x32, 2 stages.
// ---------------------------------------------------------------------------
#define AST 72
#define G1_AB  (64 * AST * 2)                 // 9216
#define G1_BB  (256 * AST * 2)                // 36864
#define G1_STAGE (G1_AB + G1_BB)              // 46080
#define G1_DYN   (2 * G1_STAGE)               // 92160

__global__ void __launch_bounds__(512) gemm1_mma(
    const float* __restrict__ x1, const float* __restrict__ x2,
    const float* __restrict__ b1)
{
    extern __shared__ char dyn[];
    const int z    = blockIdx.y;
    const int rb   = blockIdx.x;
    const int row0 = rb * 64;
    const float* __restrict__ X = z ? x2 : x1;

    const int tid  = threadIdx.x;
    const int lane = tid & 31;
    const int wid  = tid >> 5;
    const int wm   = wid >> 3;       // 0..1
    const int wn   = wid & 7;        // 0..7
    const int g    = lane >> 2;      // 0..7
    const int tg   = lane & 3;       // 0..3
    const int ln16 = lane & 15;
    const int lhalf = (lane >> 4) & 1;

    float acc[2][4][4];
#pragma unroll
    for (int t = 0; t < 2; t++)
#pragma unroll
        for (int u = 0; u < 4; u++)
#pragma unroll
            for (int j = 0; j < 4; j++) acc[t][u][j] = 0.0f;

    float4 aNext[2];

#define G1_LDA(c) do { \
        const int kk_ = (c) * 64; \
        _Pragma("unroll") \
        for (int it = 0; it < 2; it++) { \
            int idx = tid + it * 512; \
            int r_  = idx >> 4, c4_ = idx & 15; \
            aNext[it] = *reinterpret_cast<const float4*>( \
                X + (size_t)(row0 + r_) * DK + kk_ + c4_ * 4); \
        } \
    } while (0)

#define G1_STA(stg) do { \
        char* sAh_ = dyn + (stg) * G1_STAGE; \
        _Pragma("unroll") \
        for (int it = 0; it < 2; it++) { \
            int idx = tid + it * 512; \
            int r_  = idx >> 4, c4_ = idx & 15; \
            uint32_t p0 = pack_h2(aNext[it].x, aNext[it].y); \
            uint32_t p1 = pack_h2(aNext[it].z, aNext[it].w); \
            int off = (r_ * AST + c4_ * 4) * 2; \
            *reinterpret_cast<uint2*>(sAh_ + off) = make_uint2(p0, p1); \
        } \
    } while (0)

#define G1_CPB(c, stg) do { \
        const int kk_ = (c) * 64; \
        char* sB_ = dyn + (stg) * G1_STAGE + G1_AB; \
        uint32_t bU = smem_u32(sB_); \
        _Pragma("unroll") \
        for (int it = 0; it < 4; it++) { \
            int idx = tid + it * 512; \
            int n_ = idx >> 3, c8_ = idx & 7; \
            int off = (n_ * AST + c8_ * 8) * 2; \
            cpasync16(bU + off, g_w1 + (size_t)n_ * DK + kk_ + c8_ * 8); \
        } \
        cpasync_commit(); \
    } while (0)

    G1_CPB(0, 0);
    G1_LDA(0);
    G1_STA(0);
    cpasync_wait0();
    __syncthreads();

    const int NC = DK / 64;   // 8
    for (int c = 0; c < NC; c++) {
        const int s = c & 1;
        if (c + 1 < NC) {
            G1_CPB(c + 1, s ^ 1);
            G1_LDA(c + 1);
        }

        {
            char* st = dyn + s * G1_STAGE;
            uint32_t sAhU = smem_u32(st);
            uint32_t sBU  = sAhU + G1_AB;

            const uint32_t aOff = ((wm * 32 + ln16) * AST + lhalf * 8) * 2;
            const uint32_t bOff = (((wn * 32) + (ln16 & 7)) * AST + ((ln16 >> 3) * 8)) * 2;

#pragma unroll
            for (int ks = 0; ks < 4; ks++) {
                const uint32_t ko = ks * 32;
                uint32_t Ah[2][4], Bh[4][2];
#pragma unroll
                for (int t = 0; t < 2; t++)
                    ldmatrix_x4(Ah[t], sAhU + aOff + (t * 16 * AST) * 2 + ko);
#pragma unroll
                for (int u = 0; u < 4; u++)
                    ldmatrix_x2(Bh[u], sBU + bOff + (u * 8 * AST) * 2 + ko);
#pragma unroll
                for (int t = 0; t < 2; t++)
#pragma unroll
                    for (int u = 0; u < 4; u++)
                        mma_f16(acc[t][u][0], acc[t][u][1], acc[t][u][2], acc[t][u][3],
                                Ah[t][0], Ah[t][1], Ah[t][2], Ah[t][3],
                                Bh[u][0], Bh[u][1]);
            }
        }

        if (c + 1 < NC) {
            G1_STA(s ^ 1);
            cpasync_wait0();
            __syncthreads();
        }
    }

    // ---- epilogue: bias, store hraw (fp16), column partial stats (fp32) ----
    float css0[4], css1[4], cqq0[4], cqq1[4];
#pragma unroll
    for (int u = 0; u < 4; u++) {
        const int col = wn * 32 + u * 8 + tg * 2;
        const float bi0 = b1[col], bi1 = b1[col + 1];
        float cs0 = 0.f, cs1 = 0.f, cq0 = 0.f, cq1 = 0.f;
#pragma unroll
        for (int t = 0; t < 2; t++) {
            const int r = row0 + wm * 32 + t * 16 + g;
            float v0 = acc[t][u][0] + bi0;
            float v1 = acc[t][u][1] + bi1;
            float v2 = acc[t][u][2] + bi0;
            float v3 = acc[t][u][3] + bi1;
            *reinterpret_cast<uint32_t*>(
                &g_hraw[((size_t)z * NROWS + r) * HH + col])     = pack_h2(v0, v1);
            *reinterpret_cast<uint32_t*>(
                &g_hraw[((size_t)z * NROWS + r + 8) * HH + col]) = pack_h2(v2, v3);
            cs0 += v0 + v2; cs1 += v1 + v3;
            cq0 += v0 * v0 + v2 * v2; cq1 += v1 * v1 + v3 * v3;
        }
        css0[u] = cs0; css1[u] = cs1; cqq0[u] = cq0; cqq1[u] = cq1;
    }
#pragma unroll
    for (int off = 4; off < 32; off <<= 1) {
#pragma unroll
        for (int u = 0; u < 4; u++) {
            css0[u] += __shfl_xor_sync(0xffffffffu, css0[u], off);
            css1[u] += __shfl_xor_sync(0xffffffffu, css1[u], off);
            cqq0[u] += __shfl_xor_sync(0xffffffffu, cqq0[u], off);
            cqq1[u] += __shfl_xor_sync(0xffffffffu, cqq1[u], off);
        }
    }
    float* s_ps = reinterpret_cast<float*>(dyn);   // [2][256]
    float* s_sq = s_ps + 512;
    __syncthreads();
    if (g == 0) {
#pragma unroll
        for (int u = 0; u < 4; u++) {
            const int col = wn * 32 + u * 8 + tg * 2;
            s_ps[wm * 256 + col]     = css0[u];
            s_ps[wm * 256 + col + 1] = css1[u];
            s_sq[wm * 256 + col]     = cqq0[u];
            s_sq[wm * 256 + col + 1] = cqq1[u];
        }
    }
    __syncthreads();
    if (tid < 256) {
        g_psum[((size_t)z * NRB1 + rb) * HH + tid] = s_ps[tid] + s_ps[256 + tid];
        g_psq [((size_t)z * NRB1 + rb) * HH + tid] = s_sq[tid] + s_sq[256 + tid];
    }
#undef G1_LDA
#undef G1_STA
#undef G1_CPB
}

// ---------------------------------------------------------------------------
// Stats: one block per (z, column); 256 threads reduce 1024 partials.
// ---------------------------------------------------------------------------
__global__ void __launch_bounds__(256) stats_kernel(
    const float* __restrict__ gamma, const float* __restrict__ beta_bn)
{
    const int z = blockIdx.x >> 8;
    const int c = blockIdx.x & 255;
    const int tid = threadIdx.x;

    float s = 0.0f, q = 0.0f;
    for (int i = tid; i < NRB1; i += 256) {
        s += g_psum[((size_t)z * NRB1 + i) * HH + c];
        q += g_psq [((size_t)z * NRB1 + i) * HH + c];
    }
#pragma unroll
    for (int off = 16; off > 0; off >>= 1) {
        s += __shfl_xor_sync(0xffffffffu, s, off);
        q += __shfl_xor_sync(0xffffffffu, q, off);
    }
    __shared__ float rs[8], rq[8];
    if ((tid & 31) == 0) { rs[tid >> 5] = s; rq[tid >> 5] = q; }
    __syncthreads();
    if (tid == 0) {
        float S = 0.f, Q = 0.f;
#pragma unroll
        for (int w = 0; w < 8; w++) { S += rs[w]; Q += rq[w]; }
        const float mean = S / (float)NROWS;
        const float var  = Q / (float)NROWS - mean * mean;
        const float sc   = gamma[c] * rsqrtf(var + 1e-5f);
        g_scale[z * HH + c] = sc;
        g_shift[z * HH + c] = beta_bn[c] - mean * sc;
    }
}

// ---------------------------------------------------------------------------
// FUSED v3 (fp16 single pass): GEMM2 (both z) + cosine + GEMM3 + head -> out.
// A single fp16 (from fp16 hraw, BN in fp32); W2/W3 single fp16.
// smem: A region 36864 (2 stages x 128x64@72); B region 36864 (2 stages).
// Phase 3 reuse: A region -> combined tile 128x128@136 fp16 (34816);
//                B region -> W3 chunk 64x128@136 (17408).
// ---------------------------------------------------------------------------
#define F2_AB   (128 * AST * 2)        // 18432 (single A stage)
#define F2_AREG (2 * F2_AB)            // 36864
#define F2_BB   (128 * AST * 2)        // 18432
#define F2_BREG (2 * F2_BB)            // 36864
#define F2_DYN  (F2_AREG + F2_BREG)    // 73728
#define ST3 136

__global__ void __launch_bounds__(256) fused2(
    const float* __restrict__ b2, const float* __restrict__ b3,
    const float* __restrict__ W4, const float* __restrict__ b4,
    const float* __restrict__ alphap, const float* __restrict__ betap,
    float* __restrict__ out)
{
    extern __shared__ char dyn[];
    __shared__ float s_sc[HH];
    __shared__ float s_sh[HH];
    __shared__ float s_red[4][128][4];

    const int rb   = blockIdx.x;
    const int row0 = rb * 128;
    const int tid  = threadIdx.x;
    const int lane = tid & 31;
    const int wid  = tid >> 5;
    const int wm   = wid >> 2;       // 0..1
    const int wn   = wid & 3;        // 0..3
    const int g    = lane >> 2;
    const int tg   = lane & 3;
    const int ln16 = lane & 15;
    const int lhalf = (lane >> 4) & 1;

    char* Areg = dyn;
    char* Breg = dyn + F2_AREG;

    float acc[4][4][4];
    float h1[4][4][4];
    uint4 aNext[4];

    const uint32_t aOff2 = ((wm * 64 + ln16) * AST + lhalf * 8) * 2;
    const uint32_t bOff2 = (((wn * 32 + (ln16 & 7)) * AST) + ((ln16 >> 3) * 8)) * 2;

#define F2_LDA(zz, c) do { \
        const int kk_ = (c) * 64; \
        _Pragma("unroll") \
        for (int it = 0; it < 4; it++) { \
            int idx = tid + it * 256; \
            int r_  = idx >> 3, c8_ = idx & 7; \
            aNext[it] = *reinterpret_cast<const uint4*>( \
                g_hraw + ((size_t)(zz) * NROWS + row0 + r_) * HH + kk_ + c8_ * 8); \
        } \
    } while (0)

#define F2_STA(c, stg) do { \
        const int kk_ = (c) * 64; \
        char* sA_ = Areg + (stg) * F2_AB; \
        _Pragma("unroll") \
        for (int it = 0; it < 4; it++) { \
            int idx = tid + it * 256; \
            int r_  = idx >> 3, c8_ = idx & 7; \
            const int col_ = kk_ + c8_ * 8; \
            float2 f0 = unpack_h2(aNext[it].x); \
            float2 f1 = unpack_h2(aNext[it].y); \
            float2 f2 = unpack_h2(aNext[it].z); \
            float2 f3 = unpack_h2(aNext[it].w); \
            float a0 = fmaxf(s_sc[col_ + 0] * f0.x + s_sh[col_ + 0], 0.0f); \
            float a1 = fmaxf(s_sc[col_ + 1] * f0.y + s_sh[col_ + 1], 0.0f); \
            float a2 = fmaxf(s_sc[col_ + 2] * f1.x + s_sh[col_ + 2], 0.0f); \
            float a3 = fmaxf(s_sc[col_ + 3] * f1.y + s_sh[col_ + 3], 0.0f); \
            float a4 = fmaxf(s_sc[col_ + 4] * f2.x + s_sh[col_ + 4], 0.0f); \
            float a5 = fmaxf(s_sc[col_ + 5] * f2.y + s_sh[col_ + 5], 0.0f); \
            float a6 = fmaxf(s_sc[col_ + 6] * f3.x + s_sh[col_ + 6], 0.0f); \
            float a7 = fmaxf(s_sc[col_ + 7] * f3.y + s_sh[col_ + 7], 0.0f); \
            int off = (r_ * AST + c8_ * 8) * 2; \
            *reinterpret_cast<uint4*>(sA_ + off) = \
                make_uint4(pack_h2(a0, a1), pack_h2(a2, a3), \
                           pack_h2(a4, a5), pack_h2(a6, a7)); \
        } \
    } while (0)

#define F2_CPB(c, stg) do { \
        const int kk_ = (c) * 64; \
        char* sB_ = Breg + (stg) * F2_BB; \
        uint32_t bU = smem_u32(sB_); \
        _Pragma("unroll") \
        for (int it = 0; it < 4; it++) { \
            int idx = tid + it * 256; \
            int n_ = idx >> 3, c8_ = idx & 7; \
            int off = (n_ * AST + c8_ * 8) * 2; \
            cpasync16(bU + off, g_w2 + (size_t)n_ * HH + kk_ + c8_ * 8); \
        } \
        cpasync_commit(); \
    } while (0)

    // ========================= Phases 1 & 2: GEMM2 x2 =======================
    for (int z = 0; z < 2; z++) {
        __syncthreads();
        s_sc[tid] = g_scale[z * HH + tid];
        s_sh[tid] = g_shift[z * HH + tid];
        __syncthreads();

#pragma unroll
        for (int t = 0; t < 4; t++)
#pragma unroll
            for (int u = 0; u < 4; u++)
#pragma unroll
                for (int j = 0; j < 4; j++) acc[t][u][j] = 0.0f;

        F2_CPB(0, 0);
        F2_LDA(z, 0);
        F2_STA(0, 0);
        cpasync_wait0();
        __syncthreads();

        const int NC = 4;
        for (int c = 0; c < NC; c++) {
            const int s = c & 1;
            if (c + 1 < NC) {
                F2_CPB(c + 1, s ^ 1);
                F2_LDA(z, c + 1);
            }
            {
                uint32_t sAU = smem_u32(Areg + s * F2_AB);
                uint32_t sBU = smem_u32(Breg + s * F2_BB);
#pragma unroll
                for (int ks = 0; ks < 4; ks++) {
                    const uint32_t ko = ks * 32;
                    uint32_t Ah[4][4], Bh[4][2];
#pragma unroll
                    for (int t = 0; t < 4; t++)
                        ldmatrix_x4(Ah[t], sAU + aOff2 + (t * 16 * AST) * 2 + ko);
#pragma unroll
                    for (int u = 0; u < 4; u++)
                        ldmatrix_x2(Bh[u], sBU + bOff2 + (u * 8 * AST) * 2 + ko);
#pragma unroll
                    for (int t = 0; t < 4; t++)
#pragma unroll
                        for (int u = 0; u < 4; u++)
                            mma_f16(acc[t][u][0], acc[t][u][1], acc[t][u][2], acc[t][u][3],
                                    Ah[t][0], Ah[t][1], Ah[t][2], Ah[t][3],
                                    Bh[u][0], Bh[u][1]);
                }
            }
            if (c + 1 < NC) {
                __syncthreads();
                F2_STA(c + 1, s ^ 1);
                cpasync_wait0();
                __syncthreads();
            }
        }

        // epilogue: h = relu(acc + b2); stash into h1 (z=0) or keep in acc (z=1)
#pragma unroll
        for (int u = 0; u < 4; u++) {
            const int col = wn * 32 + u * 8 + tg * 2;
            const float bi0 = b2[col], bi1 = b2[col + 1];
#pragma unroll
            for (int t = 0; t < 4; t++) {
                float v0 = fmaxf(acc[t][u][0] + bi0, 0.0f);
                float v1 = fmaxf(acc[t][u][1] + bi1, 0.0f);
                float v2 = fmaxf(acc[t][u][2] + bi0, 0.0f);
                float v3 = fmaxf(acc[t][u][3] + bi1, 0.0f);
                if (z == 0) {
                    h1[t][u][0] = v0; h1[t][u][1] = v1;
                    h1[t][u][2] = v2; h1[t][u][3] = v3;
                } else {
                    acc[t][u][0] = v0; acc[t][u][1] = v1;
                    acc[t][u][2] = v2; acc[t][u][3] = v3;
                }
            }
        }
    }

    // ================== cosine partials (row-wise) from fragments ==========
    {
        float dotR[8], n1R[8], n2R[8];
#pragma unroll
        for (int ri = 0; ri < 8; ri++) { dotR[ri] = 0.f; n1R[ri] = 0.f; n2R[ri] = 0.f; }
#pragma unroll
        for (int t = 0; t < 4; t++)
#pragma unroll
            for (int u = 0; u < 4; u++)
#pragma unroll
                for (int j = 0; j < 4; j++) {
                    const float a = h1[t][u][j];
                    const float b = acc[t][u][j];
                    const int ri = t * 2 + (j >> 1);
                    dotR[ri] = fmaf(a, b, dotR[ri]);
                    n1R[ri]  = fmaf(a, a, n1R[ri]);
                    n2R[ri]  = fmaf(b, b, n2R[ri]);
                }
#pragma unroll
        for (int off = 1; off < 4; off <<= 1) {
#pragma unroll
            for (int ri = 0; ri < 8; ri++) {
                dotR[ri] += __shfl_xor_sync(0xffffffffu, dotR[ri], off);
                n1R[ri]  += __shfl_xor_sync(0xffffffffu, n1R[ri], off);
                n2R[ri]  += __shfl_xor_sync(0xffffffffu, n2R[ri], off);
            }
        }
        if (tg == 0) {
#pragma unroll
            for (int ri = 0; ri < 8; ri++) {
                const int r = wm * 64 + (ri >> 1) * 16 + g + (ri & 1) * 8;
                s_red[0][r][wn] = dotR[ri];
                s_red[1][r][wn] = n1R[ri];
                s_red[2][r][wn] = n2R[ri];
            }
        }
    }

    // ==================== Phase 3: GEMM3 on tensor cores (1-pass) ===========
    float acc3[4][2][4];
#pragma unroll
    for (int t = 0; t < 4; t++)
#pragma unroll
        for (int u = 0; u < 2; u++)
#pragma unroll
            for (int j = 0; j < 4; j++) acc3[t][u][j] = 0.0f;

    const uint32_t aOff3 = ((wm * 64 + ln16) * ST3 + lhalf * 8) * 2;
    const uint32_t bOff3 = (((wn * 16 + (ln16 & 7)) * ST3) + ((ln16 >> 3) * 8)) * 2;
    char* A3 = Areg;                         // 128*136*2 = 34816 <= 36864
    uint32_t A3U = smem_u32(A3);
    uint32_t B3U = smem_u32(Breg);           // 64*136*2 = 17408 <= 36864

    __syncthreads();   // all warps done with phase-2 stages + s_red written

    for (int f = 0; f < 3; f++) {
        // prefetch W3 chunk f
#pragma unroll
        for (int it = 0; it < 4; it++) {
            int idx = tid + it * 256;
            int n_ = idx >> 4, cc = idx & 15;
            int off = (n_ * ST3 + cc * 8) * 2;
            cpasync16(B3U + off, g_w3 + n_ * 384 + f * 128 + cc * 8);
        }
        cpasync_commit();

        // write combined feature tile into A region (single fp16, stride ST3)
#pragma unroll
        for (int t = 0; t < 4; t++)
#pragma unroll
            for (int u = 0; u < 4; u++) {
                const int col = wn * 32 + u * 8 + tg * 2;
                const int r   = wm * 64 + t * 16 + g;
                float v[4];
#pragma unroll
                for (int j = 0; j < 4; j++) {
                    const float a = h1[t][u][j];
                    const float b = acc[t][u][j];
                    v[j] = (f == 0) ? a * b : (f == 1) ? fabsf(a - b) : a + b;
                }
                *reinterpret_cast<uint32_t*>(A3 + (r * ST3 + col) * 2)       = pack_h2(v[0], v[1]);
                *reinterpret_cast<uint32_t*>(A3 + ((r + 8) * ST3 + col) * 2) = pack_h2(v[2], v[3]);
            }
        cpasync_wait0();
        __syncthreads();

        // MMA over k=128 (8 steps), single pass
#pragma unroll
        for (int ks = 0; ks < 8; ks++) {
            const uint32_t ko = ks * 32;
            uint32_t Ah[4][4], Bh[2][2];
#pragma unroll
            for (int t = 0; t < 4; t++)
                ldmatrix_x4(Ah[t], A3U + aOff3 + (t * 16 * ST3) * 2 + ko);
#pragma unroll
            for (int u = 0; u < 2; u++)
                ldmatrix_x2(Bh[u], B3U + bOff3 + (u * 8 * ST3) * 2 + ko);
#pragma unroll
            for (int t = 0; t < 4; t++)
#pragma unroll
                for (int u = 0; u < 2; u++)
                    mma_f16(acc3[t][u][0], acc3[t][u][1], acc3[t][u][2], acc3[t][u][3],
                            Ah[t][0], Ah[t][1], Ah[t][2], Ah[t][3],
                            Bh[u][0], Bh[u][1]);
        }
        __syncthreads();
    }

    // ==================== Phase 4: relu -> W4 -> head =======================
    {
        float slR[8];
#pragma unroll
        for (int ri = 0; ri < 8; ri++) slR[ri] = 0.0f;
#pragma unroll
        for (int u = 0; u < 2; u++) {
            const int col = wn * 16 + u * 8 + tg * 2;
            const float b30 = b3[col], b31 = b3[col + 1];
            const float w40 = W4[col], w41 = W4[col + 1];
#pragma unroll
            for (int t = 0; t < 4; t++) {
                slR[t * 2 + 0] += fmaxf(acc3[t][u][0] + b30, 0.0f) * w40
                                + fmaxf(acc3[t][u][1] + b31, 0.0f) * w41;
                slR[t * 2 + 1] += fmaxf(acc3[t][u][2] + b30, 0.0f) * w40
                                + fmaxf(acc3[t][u][3] + b31, 0.0f) * w41;
            }
        }
#pragma unroll
        for (int off = 1; off < 4; off <<= 1)
#pragma unroll
            for (int ri = 0; ri < 8; ri++)
                slR[ri] += __shfl_xor_sync(0xffffffffu, slR[ri], off);
        if (tg == 0) {
#pragma unroll
            for (int ri = 0; ri < 8; ri++) {
                const int r = wm * 64 + (ri >> 1) * 16 + g + (ri & 1) * 8;
                s_red[3][r][wn] = slR[ri];
            }
        }
    }
    __syncthreads();

    if (tid < 128) {
        float dot = 0.f, n1v = 0.f, n2v = 0.f, sl = 0.f;
#pragma unroll
        for (int w = 0; w < 4; w++) {
            dot += s_red[0][tid][w];
            n1v += s_red[1][tid][w];
            n2v += s_red[2][tid][w];
            sl  += s_red[3][tid][w];
        }
        const float inv1   = 1.0f / fmaxf(sqrtf(n1v), 1e-15f);
        const float inv2   = 1.0f / fmaxf(sqrtf(n2v), 1e-15f);
        const float s_math = fminf(fmaxf(dot * inv1 * inv2, 0.0f), 1.0f);
        const float sig    = 1.0f / (1.0f + expf(-(sl + b4[0])));
        const float fin    = alphap[0] * s_math + betap[0] * sig;
        out[row0 + tid] = fminf(fmaxf(fin, 0.0f), 1.0f);
    }
#undef F2_LDA
#undef F2_STA
#undef F2_CPB
}

// ---------------------------------------------------------------------------
extern "C" void kernel_launch(void* const* d_in, const int* in_sizes, int n_in,
                              void* d_out, int out_size)
{
    const float* x1      = (const float*)d_in[0];
    const float* x2      = (const float*)d_in[1];
    const float* W1      = (const float*)d_in[2];
    const float* b1      = (const float*)d_in[3];
    const float* gamma   = (const float*)d_in[4];
    const float* beta_bn = (const float*)d_in[5];
    const float* W2      = (const float*)d_in[6];
    const float* b2      = (const float*)d_in[7];
    const float* W3      = (const float*)d_in[8];
    const float* b3      = (const float*)d_in[9];
    const float* W4      = (const float*)d_in[10];
    const float* b4      = (const float*)d_in[11];
    const float* alphap  = (const float*)d_in[12];
    const float* betap   = (const float*)d_in[13];
    float* out = (float*)d_out;

    cudaFuncSetAttribute(gemm1_mma,
                         cudaFuncAttributeMaxDynamicSharedMemorySize, G1_DYN);
    cudaFuncSetAttribute(fused2,
                         cudaFuncAttributeMaxDynamicSharedMemorySize, F2_DYN);

    const int prep_elems = DK * HH + HH * H2 + 384 * O3;
    prep_weights<<<(prep_elems + 255) / 256, 256>>>(W1, W2, W3);

    dim3 g1(NRB1, 2);
    gemm1_mma<<<g1, 512, G1_DYN>>>(x1, x2, b1);

    stats_kernel<<<512, 256>>>(gamma, beta_bn);

    fused2<<<NRB2, 256, F2_DYN>>>(b2, b3, W4, b4, alphap, betap, out);
}

// round 10
// speedup vs baseline: 7.3245x; 1.0521x over previous
#include <cuda_runtime.h>
#include <cuda_bf16.h>
#include <cuda_fp16.h>
#include <cstdint>
#include <math.h>

// ---------------------------------------------------------------------------
// Problem constants
// ---------------------------------------------------------------------------
#define NROWS 65536
#define DK    512
#define HH    256
#define H2    128
#define O3    64
#define NRB1  1024          // gemm1 row blocks of 64
#define NRB2  512           // fused2 row blocks of 128

// ---------------------------------------------------------------------------
// Scratch (device globals — allocation-free per harness rules)
// ---------------------------------------------------------------------------
__device__ __align__(16) __half g_hraw[2 * NROWS * HH];   // 64 MB fp16 pre-BN
__device__ float g_psum[2 * NRB1 * HH];
__device__ float g_psq [2 * NRB1 * HH];
__device__ float g_scale[2 * HH];
__device__ float g_shift[2 * HH];
// All weights single fp16, transposed K-major [N][K]
__device__ __align__(16) __half g_w1[HH * DK];
__device__ __align__(16) __half g_w2[H2 * HH];
__device__ __align__(16) __half g_w3[O3 * 384];

// ---------------------------------------------------------------------------
// Warp-MMA helpers (base PTX — no sm_103a-only features)
// ---------------------------------------------------------------------------
__device__ __forceinline__ uint32_t smem_u32(const void* p) {
    uint32_t a;
    asm("{ .reg .u64 t; cvta.to.shared.u64 t, %1; cvt.u32.u64 %0, t; }"
        : "=r"(a) : "l"(p));
    return a;
}

__device__ __forceinline__ void mma_f16(float& c0, float& c1, float& c2, float& c3,
                                        uint32_t a0, uint32_t a1, uint32_t a2, uint32_t a3,
                                        uint32_t b0, uint32_t b1) {
    asm volatile(
        "mma.sync.aligned.m16n8k16.row.col.f32.f16.f16.f32 "
        "{%0,%1,%2,%3}, {%4,%5,%6,%7}, {%8,%9}, {%0,%1,%2,%3};"
        : "+f"(c0), "+f"(c1), "+f"(c2), "+f"(c3)
        : "r"(a0), "r"(a1), "r"(a2), "r"(a3), "r"(b0), "r"(b1));
}

__device__ __forceinline__ void ldmatrix_x4(uint32_t* r, uint32_t addr) {
    asm volatile("ldmatrix.sync.aligned.m8n8.x4.shared.b16 {%0,%1,%2,%3}, [%4];"
        : "=r"(r[0]), "=r"(r[1]), "=r"(r[2]), "=r"(r[3]) : "r"(addr));
}

__device__ __forceinline__ void ldmatrix_x2(uint32_t* r, uint32_t addr) {
    asm volatile("ldmatrix.sync.aligned.m8n8.x2.shared.b16 {%0,%1}, [%2];"
        : "=r"(r[0]), "=r"(r[1]) : "r"(addr));
}

__device__ __forceinline__ void cpasync16(uint32_t dst, const void* src) {
    asm volatile("cp.async.cg.shared.global [%0], [%1], 16;" :: "r"(dst), "l"(src));
}
__device__ __forceinline__ void cpasync_commit() {
    asm volatile("cp.async.commit_group;" ::: "memory");
}
__device__ __forceinline__ void cpasync_wait0() {
    asm volatile("cp.async.wait_group 0;" ::: "memory");
}

// pack (x,y) into one fp16x2 word
__device__ __forceinline__ uint32_t pack_h2(float x, float y) {
    __half2 h = __floats2half2_rn(x, y);
    return *reinterpret_cast<uint32_t*>(&h);
}

__device__ __forceinline__ float2 unpack_h2(uint32_t u) {
    __half2 h = *reinterpret_cast<__half2*>(&u);
    return __half22float2(h);
}

// ---------------------------------------------------------------------------
// Weight prep: transpose to K-major fp16. W1[256][512], W2[128][256], W3[64][384].
// ---------------------------------------------------------------------------
__global__ void prep_weights(const float* __restrict__ W1,
                             const float* __restrict__ W2,
                             const float* __restrict__ W3)
{
    int i = blockIdx.x * 256 + threadIdx.x;
    if (i < DK * HH) {
        int k = i >> 8, n = i & 255;
        g_w1[n * DK + k] = __float2half_rn(W1[i]);
        return;
    }
    int j = i - DK * HH;
    if (j < HH * H2) {
        int k = j >> 7, n = j & 127;
        g_w2[n * HH + k] = __float2half_rn(W2[j]);
        return;
    }
    int j2 = j - HH * H2;
    if (j2 < 384 * O3) {
        int k = j2 >> 6, n = j2 & 63;
        g_w3[n * 384 + k] = __float2half_rn(W3[j2]);
    }
}

// ---------------------------------------------------------------------------
// GEMM1 v6 (mma.sync fp16, single pass): hraw(fp16) = X @ W1 + b1, plus stats.
// CTA 64x256, 256 threads, 8 warps (1m x 8n), warp tile 64x32 (2:1 MMA:LDSM).
// Per-column ownership: one warp per 32 columns -> stats via intra-warp shuffle.
// ---------------------------------------------------------------------------
#define AST 72
#define G1_AB  (64 * AST * 2)                 // 9216
#define G1_BB  (256 * AST * 2)                // 36864
#define G1_STAGE (G1_AB + G1_BB)              // 46080
#define G1_DYN   (2 * G1_STAGE)               // 92160

__global__ void __launch_bounds__(256) gemm1_mma(
    const float* __restrict__ x1, const float* __restrict__ x2,
    const float* __restrict__ b1)
{
    extern __shared__ char dyn[];
    const int z    = blockIdx.y;
    const int rb   = blockIdx.x;
    const int row0 = rb * 64;
    const float* __restrict__ X = z ? x2 : x1;

    const int tid  = threadIdx.x;
    const int lane = tid & 31;
    const int wn   = tid >> 5;       // warp id = n-tile 0..7
    const int g    = lane >> 2;      // 0..7
    const int tg   = lane & 3;       // 0..3
    const int ln16 = lane & 15;
    const int lhalf = (lane >> 4) & 1;

    float acc[4][4][4];
#pragma unroll
    for (int t = 0; t < 4; t++)
#pragma unroll
        for (int u = 0; u < 4; u++)
#pragma unroll
            for (int j = 0; j < 4; j++) acc[t][u][j] = 0.0f;

    float4 aNext[4];

#define G1_LDA(c) do { \
        const int kk_ = (c) * 64; \
        _Pragma("unroll") \
        for (int it = 0; it < 4; it++) { \
            int idx = tid + it * 256; \
            int r_  = idx >> 4, c4_ = idx & 15; \
            aNext[it] = *reinterpret_cast<const float4*>( \
                X + (size_t)(row0 + r_) * DK + kk_ + c4_ * 4); \
        } \
    } while (0)

#define G1_STA(stg) do { \
        char* sAh_ = dyn + (stg) * G1_STAGE; \
        _Pragma("unroll") \
        for (int it = 0; it < 4; it++) { \
            int idx = tid + it * 256; \
            int r_  = idx >> 4, c4_ = idx & 15; \
            uint32_t p0 = pack_h2(aNext[it].x, aNext[it].y); \
            uint32_t p1 = pack_h2(aNext[it].z, aNext[it].w); \
            int off = (r_ * AST + c4_ * 4) * 2; \
            *reinterpret_cast<uint2*>(sAh_ + off) = make_uint2(p0, p1); \
        } \
    } while (0)

#define G1_CPB(c, stg) do { \
        const int kk_ = (c) * 64; \
        char* sB_ = dyn + (stg) * G1_STAGE + G1_AB; \
        uint32_t bU = smem_u32(sB_); \
        _Pragma("unroll") \
        for (int it = 0; it < 8; it++) { \
            int idx = tid + it * 256; \
            int n_ = idx >> 3, c8_ = idx & 7; \
            int off = (n_ * AST + c8_ * 8) * 2; \
            cpasync16(bU + off, g_w1 + (size_t)n_ * DK + kk_ + c8_ * 8); \
        } \
        cpasync_commit(); \
    } while (0)

    G1_CPB(0, 0);
    G1_LDA(0);
    G1_STA(0);
    cpasync_wait0();
    __syncthreads();

    const int NC = DK / 64;   // 8
    for (int c = 0; c < NC; c++) {
        const int s = c & 1;
        if (c + 1 < NC) {
            G1_CPB(c + 1, s ^ 1);
            G1_LDA(c + 1);
        }

        {
            char* st = dyn + s * G1_STAGE;
            uint32_t sAhU = smem_u32(st);
            uint32_t sBU  = sAhU + G1_AB;

            const uint32_t aOff = (ln16 * AST + lhalf * 8) * 2;
            const uint32_t bOff = (((wn * 32 + (ln16 & 7)) * AST) + ((ln16 >> 3) * 8)) * 2;

#pragma unroll
            for (int ks = 0; ks < 4; ks++) {
                const uint32_t ko = ks * 32;
                uint32_t Ah[4][4], Bh[4][2];
#pragma unroll
                for (int t = 0; t < 4; t++)
                    ldmatrix_x4(Ah[t], sAhU + aOff + (t * 16 * AST) * 2 + ko);
#pragma unroll
                for (int u = 0; u < 4; u++)
                    ldmatrix_x2(Bh[u], sBU + bOff + (u * 8 * AST) * 2 + ko);
#pragma unroll
                for (int t = 0; t < 4; t++)
#pragma unroll
                    for (int u = 0; u < 4; u++)
                        mma_f16(acc[t][u][0], acc[t][u][1], acc[t][u][2], acc[t][u][3],
                                Ah[t][0], Ah[t][1], Ah[t][2], Ah[t][3],
                                Bh[u][0], Bh[u][1]);
            }
        }

        if (c + 1 < NC) {
            G1_STA(s ^ 1);
            cpasync_wait0();
            __syncthreads();
        }
    }

    // ---- epilogue: bias, store hraw (fp16), column partial stats ----
    // Each warp exclusively owns 32 columns -> pure intra-warp stats reduce.
    float css0[4], css1[4], cqq0[4], cqq1[4];
#pragma unroll
    for (int u = 0; u < 4; u++) {
        const int col = wn * 32 + u * 8 + tg * 2;
        const float bi0 = b1[col], bi1 = b1[col + 1];
        float cs0 = 0.f, cs1 = 0.f, cq0 = 0.f, cq1 = 0.f;
#pragma unroll
        for (int t = 0; t < 4; t++) {
            const int r = row0 + t * 16 + g;
            float v0 = acc[t][u][0] + bi0;
            float v1 = acc[t][u][1] + bi1;
            float v2 = acc[t][u][2] + bi0;
            float v3 = acc[t][u][3] + bi1;
            *reinterpret_cast<uint32_t*>(
                &g_hraw[((size_t)z * NROWS + r) * HH + col])     = pack_h2(v0, v1);
            *reinterpret_cast<uint32_t*>(
                &g_hraw[((size_t)z * NROWS + r + 8) * HH + col]) = pack_h2(v2, v3);
            cs0 += v0 + v2; cs1 += v1 + v3;
            cq0 += v0 * v0 + v2 * v2; cq1 += v1 * v1 + v3 * v3;
        }
        css0[u] = cs0; css1[u] = cs1; cqq0[u] = cq0; cqq1[u] = cq1;
    }
#pragma unroll
    for (int off = 4; off < 32; off <<= 1) {
#pragma unroll
        for (int u = 0; u < 4; u++) {
            css0[u] += __shfl_xor_sync(0xffffffffu, css0[u], off);
            css1[u] += __shfl_xor_sync(0xffffffffu, css1[u], off);
            cqq0[u] += __shfl_xor_sync(0xffffffffu, cqq0[u], off);
            cqq1[u] += __shfl_xor_sync(0xffffffffu, cqq1[u], off);
        }
    }
    if (g == 0) {   // lanes 0..3 hold full 64-row column sums
#pragma unroll
        for (int u = 0; u < 4; u++) {
            const int col = wn * 32 + u * 8 + tg * 2;
            const size_t base = ((size_t)z * NRB1 + rb) * HH + col;
            g_psum[base]     = css0[u];
            g_psum[base + 1] = css1[u];
            g_psq [base]     = cqq0[u];
            g_psq [base + 1] = cqq1[u];
        }
    }
#undef G1_LDA
#undef G1_STA
#undef G1_CPB
}

// ---------------------------------------------------------------------------
// Stats: one block per (z, column); 256 threads reduce 1024 partials.
// ---------------------------------------------------------------------------
__global__ void __launch_bounds__(256) stats_kernel(
    const float* __restrict__ gamma, const float* __restrict__ beta_bn)
{
    const int z = blockIdx.x >> 8;
    const int c = blockIdx.x & 255;
    const int tid = threadIdx.x;

    float s = 0.0f, q = 0.0f;
    for (int i = tid; i < NRB1; i += 256) {
        s += g_psum[((size_t)z * NRB1 + i) * HH + c];
        q += g_psq [((size_t)z * NRB1 + i) * HH + c];
    }
#pragma unroll
    for (int off = 16; off > 0; off >>= 1) {
        s += __shfl_xor_sync(0xffffffffu, s, off);
        q += __shfl_xor_sync(0xffffffffu, q, off);
    }
    __shared__ float rs[8], rq[8];
    if ((tid & 31) == 0) { rs[tid >> 5] = s; rq[tid >> 5] = q; }
    __syncthreads();
    if (tid == 0) {
        float S = 0.f, Q = 0.f;
#pragma unroll
        for (int w = 0; w < 8; w++) { S += rs[w]; Q += rq[w]; }
        const float mean = S / (float)NROWS;
        const float var  = Q / (float)NROWS - mean * mean;
        const float sc   = gamma[c] * rsqrtf(var + 1e-5f);
        g_scale[z * HH + c] = sc;
        g_shift[z * HH + c] = beta_bn[c] - mean * sc;
    }
}

// ---------------------------------------------------------------------------
// FUSED v3 (fp16 single pass): GEMM2 (both z) + cosine + GEMM3 + head -> out.
// Unchanged from Round 9 (passing).
// ---------------------------------------------------------------------------
#define F2_AB   (128 * AST * 2)        // 18432 (single A stage)
#define F2_AREG (2 * F2_AB)            // 36864
#define F2_BB   (128 * AST * 2)        // 18432
#define F2_BREG (2 * F2_BB)            // 36864
#define F2_DYN  (F2_AREG + F2_BREG)    // 73728
#define ST3 136

__global__ void __launch_bounds__(256) fused2(
    const float* __restrict__ b2, const float* __restrict__ b3,
    const float* __restrict__ W4, const float* __restrict__ b4,
    const float* __restrict__ alphap, const float* __restrict__ betap,
    float* __restrict__ out)
{
    extern __shared__ char dyn[];
    __shared__ float s_sc[HH];
    __shared__ float s_sh[HH];
    __shared__ float s_red[4][128][4];

    const int rb   = blockIdx.x;
    const int row0 = rb * 128;
    const int tid  = threadIdx.x;
    const int lane = tid & 31;
    const int wid  = tid >> 5;
    const int wm   = wid >> 2;       // 0..1
    const int wn   = wid & 3;        // 0..3
    const int g    = lane >> 2;
    const int tg   = lane & 3;
    const int ln16 = lane & 15;
    const int lhalf = (lane >> 4) & 1;

    char* Areg = dyn;
    char* Breg = dyn + F2_AREG;

    float acc[4][4][4];
    float h1[4][4][4];
    uint4 aNext[4];

    const uint32_t aOff2 = ((wm * 64 + ln16) * AST + lhalf * 8) * 2;
    const uint32_t bOff2 = (((wn * 32 + (ln16 & 7)) * AST) + ((ln16 >> 3) * 8)) * 2;

#define F2_LDA(zz, c) do { \
        const int kk_ = (c) * 64; \
        _Pragma("unroll") \
        for (int it = 0; it < 4; it++) { \
            int idx = tid + it * 256; \
            int r_  = idx >> 3, c8_ = idx & 7; \
            aNext[it] = *reinterpret_cast<const uint4*>( \
                g_hraw + ((size_t)(zz) * NROWS + row0 + r_) * HH + kk_ + c8_ * 8); \
        } \
    } while (0)

#define F2_STA(c, stg) do { \
        const int kk_ = (c) * 64; \
        char* sA_ = Areg + (stg) * F2_AB; \
        _Pragma("unroll") \
        for (int it = 0; it < 4; it++) { \
            int idx = tid + it * 256; \
            int r_  = idx >> 3, c8_ = idx & 7; \
            const int col_ = kk_ + c8_ * 8; \
            float2 f0 = unpack_h2(aNext[it].x); \
            float2 f1 = unpack_h2(aNext[it].y); \
            float2 f2 = unpack_h2(aNext[it].z); \
            float2 f3 = unpack_h2(aNext[it].w); \
            float a0 = fmaxf(s_sc[col_ + 0] * f0.x + s_sh[col_ + 0], 0.0f); \
            float a1 = fmaxf(s_sc[col_ + 1] * f0.y + s_sh[col_ + 1], 0.0f); \
            float a2 = fmaxf(s_sc[col_ + 2] * f1.x + s_sh[col_ + 2], 0.0f); \
            float a3 = fmaxf(s_sc[col_ + 3] * f1.y + s_sh[col_ + 3], 0.0f); \
            float a4 = fmaxf(s_sc[col_ + 4] * f2.x + s_sh[col_ + 4], 0.0f); \
            float a5 = fmaxf(s_sc[col_ + 5] * f2.y + s_sh[col_ + 5], 0.0f); \
            float a6 = fmaxf(s_sc[col_ + 6] * f3.x + s_sh[col_ + 6], 0.0f); \
            float a7 = fmaxf(s_sc[col_ + 7] * f3.y + s_sh[col_ + 7], 0.0f); \
            int off = (r_ * AST + c8_ * 8) * 2; \
            *reinterpret_cast<uint4*>(sA_ + off) = \
                make_uint4(pack_h2(a0, a1), pack_h2(a2, a3), \
                           pack_h2(a4, a5), pack_h2(a6, a7)); \
        } \
    } while (0)

#define F2_CPB(c, stg) do { \
        const int kk_ = (c) * 64; \
        char* sB_ = Breg + (stg) * F2_BB; \
        uint32_t bU = smem_u32(sB_); \
        _Pragma("unroll") \
        for (int it = 0; it < 4; it++) { \
            int idx = tid + it * 256; \
            int n_ = idx >> 3, c8_ = idx & 7; \
            int off = (n_ * AST + c8_ * 8) * 2; \
            cpasync16(bU + off, g_w2 + (size_t)n_ * HH + kk_ + c8_ * 8); \
        } \
        cpasync_commit(); \
    } while (0)

    // ========================= Phases 1 & 2: GEMM2 x2 =======================
    for (int z = 0; z < 2; z++) {
        __syncthreads();
        s_sc[tid] = g_scale[z * HH + tid];
        s_sh[tid] = g_shift[z * HH + tid];
        __syncthreads();

#pragma unroll
        for (int t = 0; t < 4; t++)
#pragma unroll
            for (int u = 0; u < 4; u++)
#pragma unroll
                for (int j = 0; j < 4; j++) acc[t][u][j] = 0.0f;

        F2_CPB(0, 0);
        F2_LDA(z, 0);
        F2_STA(0, 0);
        cpasync_wait0();
        __syncthreads();

        const int NC = 4;
        for (int c = 0; c < NC; c++) {
            const int s = c & 1;
            if (c + 1 < NC) {
                F2_CPB(c + 1, s ^ 1);
                F2_LDA(z, c + 1);
            }
            {
                uint32_t sAU = smem_u32(Areg + s * F2_AB);
                uint32_t sBU = smem_u32(Breg + s * F2_BB);
#pragma unroll
                for (int ks = 0; ks < 4; ks++) {
                    const uint32_t ko = ks * 32;
                    uint32_t Ah[4][4], Bh[4][2];
#pragma unroll
                    for (int t = 0; t < 4; t++)
                        ldmatrix_x4(Ah[t], sAU + aOff2 + (t * 16 * AST) * 2 + ko);
#pragma unroll
                    for (int u = 0; u < 4; u++)
                        ldmatrix_x2(Bh[u], sBU + bOff2 + (u * 8 * AST) * 2 + ko);
#pragma unroll
                    for (int t = 0; t < 4; t++)
#pragma unroll
                        for (int u = 0; u < 4; u++)
                            mma_f16(acc[t][u][0], acc[t][u][1], acc[t][u][2], acc[t][u][3],
                                    Ah[t][0], Ah[t][1], Ah[t][2], Ah[t][3],
                                    Bh[u][0], Bh[u][1]);
                }
            }
            if (c + 1 < NC) {
                __syncthreads();
                F2_STA(c + 1, s ^ 1);
                cpasync_wait0();
                __syncthreads();
            }
        }

        // epilogue: h = relu(acc + b2); stash into h1 (z=0) or keep in acc (z=1)
#pragma unroll
        for (int u = 0; u < 4; u++) {
            const int col = wn * 32 + u * 8 + tg * 2;
            const float bi0 = b2[col], bi1 = b2[col + 1];
#pragma unroll
            for (int t = 0; t < 4; t++) {
                float v0 = fmaxf(acc[t][u][0] + bi0, 0.0f);
                float v1 = fmaxf(acc[t][u][1] + bi1, 0.0f);
                float v2 = fmaxf(acc[t][u][2] + bi0, 0.0f);
                float v3 = fmaxf(acc[t][u][3] + bi1, 0.0f);
                if (z == 0) {
                    h1[t][u][0] = v0; h1[t][u][1] = v1;
                    h1[t][u][2] = v2; h1[t][u][3] = v3;
                } else {
                    acc[t][u][0] = v0; acc[t][u][1] = v1;
                    acc[t][u][2] = v2; acc[t][u][3] = v3;
                }
            }
        }
    }

    // ================== cosine partials (row-wise) from fragments ==========
    {
        float dotR[8], n1R[8], n2R[8];
#pragma unroll
        for (int ri = 0; ri < 8; ri++) { dotR[ri] = 0.f; n1R[ri] = 0.f; n2R[ri] = 0.f; }
#pragma unroll
        for (int t = 0; t < 4; t++)
#pragma unroll
            for (int u = 0; u < 4; u++)
#pragma unroll
                for (int j = 0; j < 4; j++) {
                    const float a = h1[t][u][j];
                    const float b = acc[t][u][j];
                    const int ri = t * 2 + (j >> 1);
                    dotR[ri] = fmaf(a, b, dotR[ri]);
                    n1R[ri]  = fmaf(a, a, n1R[ri]);
                    n2R[ri]  = fmaf(b, b, n2R[ri]);
                }
#pragma unroll
        for (int off = 1; off < 4; off <<= 1) {
#pragma unroll
            for (int ri = 0; ri < 8; ri++) {
                dotR[ri] += __shfl_xor_sync(0xffffffffu, dotR[ri], off);
                n1R[ri]  += __shfl_xor_sync(0xffffffffu, n1R[ri], off);
                n2R[ri]  += __shfl_xor_sync(0xffffffffu, n2R[ri], off);
            }
        }
        if (tg == 0) {
#pragma unroll
            for (int ri = 0; ri < 8; ri++) {
                const int r = wm * 64 + (ri >> 1) * 16 + g + (ri & 1) * 8;
                s_red[0][r][wn] = dotR[ri];
                s_red[1][r][wn] = n1R[ri];
                s_red[2][r][wn] = n2R[ri];
            }
        }
    }

    // ==================== Phase 3: GEMM3 on tensor cores (1-pass) ===========
    float acc3[4][2][4];
#pragma unroll
    for (int t = 0; t < 4; t++)
#pragma unroll
        for (int u = 0; u < 2; u++)
#pragma unroll
            for (int j = 0; j < 4; j++) acc3[t][u][j] = 0.0f;

    const uint32_t aOff3 = ((wm * 64 + ln16) * ST3 + lhalf * 8) * 2;
    const uint32_t bOff3 = (((wn * 16 + (ln16 & 7)) * ST3) + ((ln16 >> 3) * 8)) * 2;
    char* A3 = Areg;                         // 128*136*2 = 34816 <= 36864
    uint32_t A3U = smem_u32(A3);
    uint32_t B3U = smem_u32(Breg);           // 64*136*2 = 17408 <= 36864

    __syncthreads();   // all warps done with phase-2 stages + s_red written

    for (int f = 0; f < 3; f++) {
        // prefetch W3 chunk f
#pragma unroll
        for (int it = 0; it < 4; it++) {
            int idx = tid + it * 256;
            int n_ = idx >> 4, cc = idx & 15;
            int off = (n_ * ST3 + cc * 8) * 2;
            cpasync16(B3U + off, g_w3 + n_ * 384 + f * 128 + cc * 8);
        }
        cpasync_commit();

        // write combined feature tile into A region (single fp16, stride ST3)
#pragma unroll
        for (int t = 0; t < 4; t++)
#pragma unroll
            for (int u = 0; u < 4; u++) {
                const int col = wn * 32 + u * 8 + tg * 2;
                const int r   = wm * 64 + t * 16 + g;
                float v[4];
#pragma unroll
                for (int j = 0; j < 4; j++) {
                    const float a = h1[t][u][j];
                    const float b = acc[t][u][j];
                    v[j] = (f == 0) ? a * b : (f == 1) ? fabsf(a - b) : a + b;
                }
                *reinterpret_cast<uint32_t*>(A3 + (r * ST3 + col) * 2)       = pack_h2(v[0], v[1]);
                *reinterpret_cast<uint32_t*>(A3 + ((r + 8) * ST3 + col) * 2) = pack_h2(v[2], v[3]);
            }
        cpasync_wait0();
        __syncthreads();

        // MMA over k=128 (8 steps), single pass
#pragma unroll
        for (int ks = 0; ks < 8; ks++) {
            const uint32_t ko = ks * 32;
            uint32_t Ah[4][4], Bh[2][2];
#pragma unroll
            for (int t = 0; t < 4; t++)
                ldmatrix_x4(Ah[t], A3U + aOff3 + (t * 16 * ST3) * 2 + ko);
#pragma unroll
            for (int u = 0; u < 2; u++)
                ldmatrix_x2(Bh[u], B3U + bOff3 + (u * 8 * ST3) * 2 + ko);
#pragma unroll
            for (int t = 0; t < 4; t++)
#pragma unroll
                for (int u = 0; u < 2; u++)
                    mma_f16(acc3[t][u][0], acc3[t][u][1], acc3[t][u][2], acc3[t][u][3],
                            Ah[t][0], Ah[t][1], Ah[t][2], Ah[t][3],
                            Bh[u][0], Bh[u][1]);
        }
        __syncthreads();
    }

    // ==================== Phase 4: relu -> W4 -> head =======================
    {
        float slR[8];
#pragma unroll
        for (int ri = 0; ri < 8; ri++) slR[ri] = 0.0f;
#pragma unroll
        for (int u = 0; u < 2; u++) {
            const int col = wn * 16 + u * 8 + tg * 2;
            const float b30 = b3[col], b31 = b3[col + 1];
            const float w40 = W4[col], w41 = W4[col + 1];
#pragma unroll
            for (int t = 0; t < 4; t++) {
                slR[t * 2 + 0] += fmaxf(acc3[t][u][0] + b30, 0.0f) * w40
                                + fmaxf(acc3[t][u][1] + b31, 0.0f) * w41;
                slR[t * 2 + 1] += fmaxf(acc3[t][u][2] + b30, 0.0f) * w40
                                + fmaxf(acc3[t][u][3] + b31, 0.0f) * w41;
            }
        }
#pragma unroll
        for (int off = 1; off < 4; off <<= 1)
#pragma unroll
            for (int ri = 0; ri < 8; ri++)
                slR[ri] += __shfl_xor_sync(0xffffffffu, slR[ri], off);
        if (tg == 0) {
#pragma unroll
            for (int ri = 0; ri < 8; ri++) {
                const int r = wm * 64 + (ri >> 1) * 16 + g + (ri & 1) * 8;
                s_red[3][r][wn] = slR[ri];
            }
        }
    }
    __syncthreads();

    if (tid < 128) {
        float dot = 0.f, n1v = 0.f, n2v = 0.f, sl = 0.f;
#pragma unroll
        for (int w = 0; w < 4; w++) {
            dot += s_red[0][tid][w];
            n1v += s_red[1][tid][w];
            n2v += s_red[2][tid][w];
            sl  += s_red[3][tid][w];
        }
        const float inv1   = 1.0f / fmaxf(sqrtf(n1v), 1e-15f);
        const float inv2   = 1.0f / fmaxf(sqrtf(n2v), 1e-15f);
        const float s_math = fminf(fmaxf(dot * inv1 * inv2, 0.0f), 1.0f);
        const float sig    = 1.0f / (1.0f + expf(-(sl + b4[0])));
        const float fin    = alphap[0] * s_math + betap[0] * sig;
        out[row0 + tid] = fminf(fmaxf(fin, 0.0f), 1.0f);
    }
#undef F2_LDA
#undef F2_STA
#undef F2_CPB
}

// ---------------------------------------------------------------------------
extern "C" void kernel_launch(void* const* d_in, const int* in_sizes, int n_in,
                              void* d_out, int out_size)
{
    const float* x1      = (const float*)d_in[0];
    const float* x2      = (const float*)d_in[1];
    const float* W1      = (const float*)d_in[2];
    const float* b1      = (const float*)d_in[3];
    const float* gamma   = (const float*)d_in[4];
    const float* beta_bn = (const float*)d_in[5];
    const float* W2      = (const float*)d_in[6];
    const float* b2      = (const float*)d_in[7];
    const float* W3      = (const float*)d_in[8];
    const float* b3      = (const float*)d_in[9];
    const float* W4      = (const float*)d_in[10];
    const float* b4      = (const float*)d_in[11];
    const float* alphap  = (const float*)d_in[12];
    const float* betap   = (const float*)d_in[13];
    float* out = (float*)d_out;

    cudaFuncSetAttribute(gemm1_mma,
                         cudaFuncAttributeMaxDynamicSharedMemorySize, G1_DYN);
    cudaFuncSetAttribute(fused2,
                         cudaFuncAttributeMaxDynamicSharedMemorySize, F2_DYN);

    const int prep_elems = DK * HH + HH * H2 + 384 * O3;
    prep_weights<<<(prep_elems + 255) / 256, 256>>>(W1, W2, W3);

    dim3 g1(NRB1, 2);
    gemm1_mma<<<g1, 256, G1_DYN>>>(x1, x2, b1);

    stats_kernel<<<512, 256>>>(gamma, beta_bn);

    fused2<<<NRB2, 256, F2_DYN>>>(b2, b3, W4, b4, alphap, betap, out);
}

// round 11
// speedup vs baseline: 7.4467x; 1.0167x over previous
#include <cuda_runtime.h>
#include <cuda_bf16.h>
#include <cuda_fp16.h>
#include <cstdint>
#include <math.h>

// ---------------------------------------------------------------------------
// Problem constants
// ---------------------------------------------------------------------------
#define NROWS 65536
#define DK    512
#define HH    256
#define H2    128
#define O3    64
#define NRB1  1024          // gemm1 row blocks of 64
#define NRB2  1024          // fused2 row blocks of 64

// ---------------------------------------------------------------------------
// Scratch (device globals — allocation-free per harness rules)
// ---------------------------------------------------------------------------
__device__ __align__(16) __half g_hraw[2 * NROWS * HH];   // 64 MB fp16 pre-BN
__device__ float g_psum[2 * NRB1 * HH];
__device__ float g_psq [2 * NRB1 * HH];
__device__ float g_scale[2 * HH];
__device__ float g_shift[2 * HH];
// All weights single fp16, transposed K-major [N][K]
__device__ __align__(16) __half g_w1[HH * DK];
__device__ __align__(16) __half g_w2[H2 * HH];
__device__ __align__(16) __half g_w3[O3 * 384];

// ---------------------------------------------------------------------------
// Warp-MMA helpers (base PTX — no sm_103a-only features)
// ---------------------------------------------------------------------------
__device__ __forceinline__ uint32_t smem_u32(const void* p) {
    uint32_t a;
    asm("{ .reg .u64 t; cvta.to.shared.u64 t, %1; cvt.u32.u64 %0, t; }"
        : "=r"(a) : "l"(p));
    return a;
}

__device__ __forceinline__ void mma_f16(float& c0, float& c1, float& c2, float& c3,
                                        uint32_t a0, uint32_t a1, uint32_t a2, uint32_t a3,
                                        uint32_t b0, uint32_t b1) {
    asm volatile(
        "mma.sync.aligned.m16n8k16.row.col.f32.f16.f16.f32 "
        "{%0,%1,%2,%3}, {%4,%5,%6,%7}, {%8,%9}, {%0,%1,%2,%3};"
        : "+f"(c0), "+f"(c1), "+f"(c2), "+f"(c3)
        : "r"(a0), "r"(a1), "r"(a2), "r"(a3), "r"(b0), "r"(b1));
}

__device__ __forceinline__ void ldmatrix_x4(uint32_t* r, uint32_t addr) {
    asm volatile("ldmatrix.sync.aligned.m8n8.x4.shared.b16 {%0,%1,%2,%3}, [%4];"
        : "=r"(r[0]), "=r"(r[1]), "=r"(r[2]), "=r"(r[3]) : "r"(addr));
}

__device__ __forceinline__ void ldmatrix_x2(uint32_t* r, uint32_t addr) {
    asm volatile("ldmatrix.sync.aligned.m8n8.x2.shared.b16 {%0,%1}, [%2];"
        : "=r"(r[0]), "=r"(r[1]) : "r"(addr));
}

__device__ __forceinline__ void cpasync16(uint32_t dst, const void* src) {
    asm volatile("cp.async.cg.shared.global [%0], [%1], 16;" :: "r"(dst), "l"(src));
}
__device__ __forceinline__ void cpasync_commit() {
    asm volatile("cp.async.commit_group;" ::: "memory");
}
__device__ __forceinline__ void cpasync_wait0() {
    asm volatile("cp.async.wait_group 0;" ::: "memory");
}

// pack (x,y) into one fp16x2 word
__device__ __forceinline__ uint32_t pack_h2(float x, float y) {
    __half2 h = __floats2half2_rn(x, y);
    return *reinterpret_cast<uint32_t*>(&h);
}

__device__ __forceinline__ float2 unpack_h2(uint32_t u) {
    __half2 h = *reinterpret_cast<__half2*>(&u);
    return __half22float2(h);
}

// ---------------------------------------------------------------------------
// Weight prep: transpose to K-major fp16. W1[256][512], W2[128][256], W3[64][384].
// ---------------------------------------------------------------------------
__global__ void prep_weights(const float* __restrict__ W1,
                             const float* __restrict__ W2,
                             const float* __restrict__ W3)
{
    int i = blockIdx.x * 256 + threadIdx.x;
    if (i < DK * HH) {
        int k = i >> 8, n = i & 255;
        g_w1[n * DK + k] = __float2half_rn(W1[i]);
        return;
    }
    int j = i - DK * HH;
    if (j < HH * H2) {
        int k = j >> 7, n = j & 127;
        g_w2[n * HH + k] = __float2half_rn(W2[j]);
        return;
    }
    int j2 = j - HH * H2;
    if (j2 < 384 * O3) {
        int k = j2 >> 6, n = j2 & 63;
        g_w3[n * 384 + k] = __float2half_rn(W3[j2]);
    }
}

// ---------------------------------------------------------------------------
// GEMM1 (unchanged from Round 10, passing): hraw(fp16) = X @ W1 + b1 + stats.
// CTA 64x256, 256 threads, 8 warps (1m x 8n), warp tile 64x32.
// ---------------------------------------------------------------------------
#define AST 72
#define G1_AB  (64 * AST * 2)                 // 9216
#define G1_BB  (256 * AST * 2)                // 36864
#define G1_STAGE (G1_AB + G1_BB)              // 46080
#define G1_DYN   (2 * G1_STAGE)               // 92160

__global__ void __launch_bounds__(256) gemm1_mma(
    const float* __restrict__ x1, const float* __restrict__ x2,
    const float* __restrict__ b1)
{
    extern __shared__ char dyn[];
    const int z    = blockIdx.y;
    const int rb   = blockIdx.x;
    const int row0 = rb * 64;
    const float* __restrict__ X = z ? x2 : x1;

    const int tid  = threadIdx.x;
    const int lane = tid & 31;
    const int wn   = tid >> 5;       // warp id = n-tile 0..7
    const int g    = lane >> 2;      // 0..7
    const int tg   = lane & 3;       // 0..3
    const int ln16 = lane & 15;
    const int lhalf = (lane >> 4) & 1;

    float acc[4][4][4];
#pragma unroll
    for (int t = 0; t < 4; t++)
#pragma unroll
        for (int u = 0; u < 4; u++)
#pragma unroll
            for (int j = 0; j < 4; j++) acc[t][u][j] = 0.0f;

    float4 aNext[4];

#define G1_LDA(c) do { \
        const int kk_ = (c) * 64; \
        _Pragma("unroll") \
        for (int it = 0; it < 4; it++) { \
            int idx = tid + it * 256; \
            int r_  = idx >> 4, c4_ = idx & 15; \
            aNext[it] = *reinterpret_cast<const float4*>( \
                X + (size_t)(row0 + r_) * DK + kk_ + c4_ * 4); \
        } \
    } while (0)

#define G1_STA(stg) do { \
        char* sAh_ = dyn + (stg) * G1_STAGE; \
        _Pragma("unroll") \
        for (int it = 0; it < 4; it++) { \
            int idx = tid + it * 256; \
            int r_  = idx >> 4, c4_ = idx & 15; \
            uint32_t p0 = pack_h2(aNext[it].x, aNext[it].y); \
            uint32_t p1 = pack_h2(aNext[it].z, aNext[it].w); \
            int off = (r_ * AST + c4_ * 4) * 2; \
            *reinterpret_cast<uint2*>(sAh_ + off) = make_uint2(p0, p1); \
        } \
    } while (0)

#define G1_CPB(c, stg) do { \
        const int kk_ = (c) * 64; \
        char* sB_ = dyn + (stg) * G1_STAGE + G1_AB; \
        uint32_t bU = smem_u32(sB_); \
        _Pragma("unroll") \
        for (int it = 0; it < 8; it++) { \
            int idx = tid + it * 256; \
            int n_ = idx >> 3, c8_ = idx & 7; \
            int off = (n_ * AST + c8_ * 8) * 2; \
            cpasync16(bU + off, g_w1 + (size_t)n_ * DK + kk_ + c8_ * 8); \
        } \
        cpasync_commit(); \
    } while (0)

    G1_CPB(0, 0);
    G1_LDA(0);
    G1_STA(0);
    cpasync_wait0();
    __syncthreads();

    const int NC = DK / 64;   // 8
    for (int c = 0; c < NC; c++) {
        const int s = c & 1;
        if (c + 1 < NC) {
            G1_CPB(c + 1, s ^ 1);
            G1_LDA(c + 1);
        }

        {
            char* st = dyn + s * G1_STAGE;
            uint32_t sAhU = smem_u32(st);
            uint32_t sBU  = sAhU + G1_AB;

            const uint32_t aOff = (ln16 * AST + lhalf * 8) * 2;
            const uint32_t bOff = (((wn * 32 + (ln16 & 7)) * AST) + ((ln16 >> 3) * 8)) * 2;

#pragma unroll
            for (int ks = 0; ks < 4; ks++) {
                const uint32_t ko = ks * 32;
                uint32_t Ah[4][4], Bh[4][2];
#pragma unroll
                for (int t = 0; t < 4; t++)
                    ldmatrix_x4(Ah[t], sAhU + aOff + (t * 16 * AST) * 2 + ko);
#pragma unroll
                for (int u = 0; u < 4; u++)
                    ldmatrix_x2(Bh[u], sBU + bOff + (u * 8 * AST) * 2 + ko);
#pragma unroll
                for (int t = 0; t < 4; t++)
#pragma unroll
                    for (int u = 0; u < 4; u++)
                        mma_f16(acc[t][u][0], acc[t][u][1], acc[t][u][2], acc[t][u][3],
                                Ah[t][0], Ah[t][1], Ah[t][2], Ah[t][3],
                                Bh[u][0], Bh[u][1]);
            }
        }

        if (c + 1 < NC) {
            G1_STA(s ^ 1);
            cpasync_wait0();
            __syncthreads();
        }
    }

    // ---- epilogue: bias, store hraw (fp16), column partial stats ----
    float css0[4], css1[4], cqq0[4], cqq1[4];
#pragma unroll
    for (int u = 0; u < 4; u++) {
        const int col = wn * 32 + u * 8 + tg * 2;
        const float bi0 = b1[col], bi1 = b1[col + 1];
        float cs0 = 0.f, cs1 = 0.f, cq0 = 0.f, cq1 = 0.f;
#pragma unroll
        for (int t = 0; t < 4; t++) {
            const int r = row0 + t * 16 + g;
            float v0 = acc[t][u][0] + bi0;
            float v1 = acc[t][u][1] + bi1;
            float v2 = acc[t][u][2] + bi0;
            float v3 = acc[t][u][3] + bi1;
            *reinterpret_cast<uint32_t*>(
                &g_hraw[((size_t)z * NROWS + r) * HH + col])     = pack_h2(v0, v1);
            *reinterpret_cast<uint32_t*>(
                &g_hraw[((size_t)z * NROWS + r + 8) * HH + col]) = pack_h2(v2, v3);
            cs0 += v0 + v2; cs1 += v1 + v3;
            cq0 += v0 * v0 + v2 * v2; cq1 += v1 * v1 + v3 * v3;
        }
        css0[u] = cs0; css1[u] = cs1; cqq0[u] = cq0; cqq1[u] = cq1;
    }
#pragma unroll
    for (int off = 4; off < 32; off <<= 1) {
#pragma unroll
        for (int u = 0; u < 4; u++) {
            css0[u] += __shfl_xor_sync(0xffffffffu, css0[u], off);
            css1[u] += __shfl_xor_sync(0xffffffffu, css1[u], off);
            cqq0[u] += __shfl_xor_sync(0xffffffffu, cqq0[u], off);
            cqq1[u] += __shfl_xor_sync(0xffffffffu, cqq1[u], off);
        }
    }
    if (g == 0) {
#pragma unroll
        for (int u = 0; u < 4; u++) {
            const int col = wn * 32 + u * 8 + tg * 2;
            const size_t base = ((size_t)z * NRB1 + rb) * HH + col;
            g_psum[base]     = css0[u];
            g_psum[base + 1] = css1[u];
            g_psq [base]     = cqq0[u];
            g_psq [base + 1] = cqq1[u];
        }
    }
#undef G1_LDA
#undef G1_STA
#undef G1_CPB
}

// ---------------------------------------------------------------------------
// Stats: one block per (z, column); 256 threads reduce 1024 partials.
// ---------------------------------------------------------------------------
__global__ void __launch_bounds__(256) stats_kernel(
    const float* __restrict__ gamma, const float* __restrict__ beta_bn)
{
    const int z = blockIdx.x >> 8;
    const int c = blockIdx.x & 255;
    const int tid = threadIdx.x;

    float s = 0.0f, q = 0.0f;
    for (int i = tid; i < NRB1; i += 256) {
        s += g_psum[((size_t)z * NRB1 + i) * HH + c];
        q += g_psq [((size_t)z * NRB1 + i) * HH + c];
    }
#pragma unroll
    for (int off = 16; off > 0; off >>= 1) {
        s += __shfl_xor_sync(0xffffffffu, s, off);
        q += __shfl_xor_sync(0xffffffffu, q, off);
    }
    __shared__ float rs[8], rq[8];
    if ((tid & 31) == 0) { rs[tid >> 5] = s; rq[tid >> 5] = q; }
    __syncthreads();
    if (tid == 0) {
        float S = 0.f, Q = 0.f;
#pragma unroll
        for (int w = 0; w < 8; w++) { S += rs[w]; Q += rq[w]; }
        const float mean = S / (float)NROWS;
        const float var  = Q / (float)NROWS - mean * mean;
        const float sc   = gamma[c] * rsqrtf(var + 1e-5f);
        g_scale[z * HH + c] = sc;
        g_shift[z * HH + c] = beta_bn[c] - mean * sc;
    }
}

// ---------------------------------------------------------------------------
// FUSED v4: 64-row CTAs, 2 CTAs/SM (launch_bounds(256,2) caps regs at 128).
// 8 warps (2m x 4n): GEMM2 warp tile 32x32, GEMM3 warp tile 32x16.
// smem/CTA: A region 18432 (2 stages x 64x64@72) + B region 36864 = 55296.
// Phase 3 reuse: A3 64x136 (17408 <= 18432), W3 chunk 64x136 (17408 <= 36864).
// ---------------------------------------------------------------------------
#define F2_AB   (64 * AST * 2)         // 9216 (single A stage)
#define F2_AREG (2 * F2_AB)            // 18432
#define F2_BB   (128 * AST * 2)        // 18432
#define F2_BREG (2 * F2_BB)            // 36864
#define F2_DYN  (F2_AREG + F2_BREG)    // 55296
#define ST3 136

__global__ void __launch_bounds__(256, 2) fused2(
    const float* __restrict__ b2, const float* __restrict__ b3,
    const float* __restrict__ W4, const float* __restrict__ b4,
    const float* __restrict__ alphap, const float* __restrict__ betap,
    float* __restrict__ out)
{
    extern __shared__ char dyn[];
    __shared__ float s_sc[HH];
    __shared__ float s_sh[HH];
    __shared__ float s_red[4][64][4];

    const int rb   = blockIdx.x;
    const int row0 = rb * 64;
    const int tid  = threadIdx.x;
    const int lane = tid & 31;
    const int wid  = tid >> 5;
    const int wm   = wid >> 2;       // 0..1
    const int wn   = wid & 3;        // 0..3
    const int g    = lane >> 2;
    const int tg   = lane & 3;
    const int ln16 = lane & 15;
    const int lhalf = (lane >> 4) & 1;

    char* Areg = dyn;
    char* Breg = dyn + F2_AREG;

    float acc[2][4][4];
    float h1[2][4][4];
    uint4 aNext[2];

    const uint32_t aOff2 = ((wm * 32 + ln16) * AST + lhalf * 8) * 2;
    const uint32_t bOff2 = (((wn * 32 + (ln16 & 7)) * AST) + ((ln16 >> 3) * 8)) * 2;

#define F2_LDA(zz, c) do { \
        const int kk_ = (c) * 64; \
        _Pragma("unroll") \
        for (int it = 0; it < 2; it++) { \
            int idx = tid + it * 256; \
            int r_  = idx >> 3, c8_ = idx & 7; \
            aNext[it] = *reinterpret_cast<const uint4*>( \
                g_hraw + ((size_t)(zz) * NROWS + row0 + r_) * HH + kk_ + c8_ * 8); \
        } \
    } while (0)

#define F2_STA(c, stg) do { \
        const int kk_ = (c) * 64; \
        char* sA_ = Areg + (stg) * F2_AB; \
        _Pragma("unroll") \
        for (int it = 0; it < 2; it++) { \
            int idx = tid + it * 256; \
            int r_  = idx >> 3, c8_ = idx & 7; \
            const int col_ = kk_ + c8_ * 8; \
            float2 f0 = unpack_h2(aNext[it].x); \
            float2 f1 = unpack_h2(aNext[it].y); \
            float2 f2 = unpack_h2(aNext[it].z); \
            float2 f3 = unpack_h2(aNext[it].w); \
            float a0 = fmaxf(s_sc[col_ + 0] * f0.x + s_sh[col_ + 0], 0.0f); \
            float a1 = fmaxf(s_sc[col_ + 1] * f0.y + s_sh[col_ + 1], 0.0f); \
            float a2 = fmaxf(s_sc[col_ + 2] * f1.x + s_sh[col_ + 2], 0.0f); \
            float a3 = fmaxf(s_sc[col_ + 3] * f1.y + s_sh[col_ + 3], 0.0f); \
            float a4 = fmaxf(s_sc[col_ + 4] * f2.x + s_sh[col_ + 4], 0.0f); \
            float a5 = fmaxf(s_sc[col_ + 5] * f2.y + s_sh[col_ + 5], 0.0f); \
            float a6 = fmaxf(s_sc[col_ + 6] * f3.x + s_sh[col_ + 6], 0.0f); \
            float a7 = fmaxf(s_sc[col_ + 7] * f3.y + s_sh[col_ + 7], 0.0f); \
            int off = (r_ * AST + c8_ * 8) * 2; \
            *reinterpret_cast<uint4*>(sA_ + off) = \
                make_uint4(pack_h2(a0, a1), pack_h2(a2, a3), \
                           pack_h2(a4, a5), pack_h2(a6, a7)); \
        } \
    } while (0)

#define F2_CPB(c, stg) do { \
        const int kk_ = (c) * 64; \
        char* sB_ = Breg + (stg) * F2_BB; \
        uint32_t bU = smem_u32(sB_); \
        _Pragma("unroll") \
        for (int it = 0; it < 4; it++) { \
            int idx = tid + it * 256; \
            int n_ = idx >> 3, c8_ = idx & 7; \
            int off = (n_ * AST + c8_ * 8) * 2; \
            cpasync16(bU + off, g_w2 + (size_t)n_ * HH + kk_ + c8_ * 8); \
        } \
        cpasync_commit(); \
    } while (0)

    // ========================= Phases 1 & 2: GEMM2 x2 =======================
    for (int z = 0; z < 2; z++) {
        __syncthreads();
        s_sc[tid] = g_scale[z * HH + tid];
        s_sh[tid] = g_shift[z * HH + tid];
        __syncthreads();

#pragma unroll
        for (int t = 0; t < 2; t++)
#pragma unroll
            for (int u = 0; u < 4; u++)
#pragma unroll
                for (int j = 0; j < 4; j++) acc[t][u][j] = 0.0f;

        F2_CPB(0, 0);
        F2_LDA(z, 0);
        F2_STA(0, 0);
        cpasync_wait0();
        __syncthreads();

        const int NC = 4;
        for (int c = 0; c < NC; c++) {
            const int s = c & 1;
            if (c + 1 < NC) {
                F2_CPB(c + 1, s ^ 1);
                F2_LDA(z, c + 1);
            }
            {
                uint32_t sAU = smem_u32(Areg + s * F2_AB);
                uint32_t sBU = smem_u32(Breg + s * F2_BB);
#pragma unroll
                for (int ks = 0; ks < 4; ks++) {
                    const uint32_t ko = ks * 32;
                    uint32_t Ah[2][4], Bh[4][2];
#pragma unroll
                    for (int t = 0; t < 2; t++)
                        ldmatrix_x4(Ah[t], sAU + aOff2 + (t * 16 * AST) * 2 + ko);
#pragma unroll
                    for (int u = 0; u < 4; u++)
                        ldmatrix_x2(Bh[u], sBU + bOff2 + (u * 8 * AST) * 2 + ko);
#pragma unroll
                    for (int t = 0; t < 2; t++)
#pragma unroll
                        for (int u = 0; u < 4; u++)
                            mma_f16(acc[t][u][0], acc[t][u][1], acc[t][u][2], acc[t][u][3],
                                    Ah[t][0], Ah[t][1], Ah[t][2], Ah[t][3],
                                    Bh[u][0], Bh[u][1]);
                }
            }
            if (c + 1 < NC) {
                __syncthreads();
                F2_STA(c + 1, s ^ 1);
                cpasync_wait0();
                __syncthreads();
            }
        }

        // epilogue: h = relu(acc + b2); stash into h1 (z=0) or keep in acc (z=1)
#pragma unroll
        for (int u = 0; u < 4; u++) {
            const int col = wn * 32 + u * 8 + tg * 2;
            const float bi0 = b2[col], bi1 = b2[col + 1];
#pragma unroll
            for (int t = 0; t < 2; t++) {
                float v0 = fmaxf(acc[t][u][0] + bi0, 0.0f);
                float v1 = fmaxf(acc[t][u][1] + bi1, 0.0f);
                float v2 = fmaxf(acc[t][u][2] + bi0, 0.0f);
                float v3 = fmaxf(acc[t][u][3] + bi1, 0.0f);
                if (z == 0) {
                    h1[t][u][0] = v0; h1[t][u][1] = v1;
                    h1[t][u][2] = v2; h1[t][u][3] = v3;
                } else {
                    acc[t][u][0] = v0; acc[t][u][1] = v1;
                    acc[t][u][2] = v2; acc[t][u][3] = v3;
                }
            }
        }
    }

    // ================== cosine partials (row-wise) from fragments ==========
    {
        float dotR[4], n1R[4], n2R[4];
#pragma unroll
        for (int ri = 0; ri < 4; ri++) { dotR[ri] = 0.f; n1R[ri] = 0.f; n2R[ri] = 0.f; }
#pragma unroll
        for (int t = 0; t < 2; t++)
#pragma unroll
            for (int u = 0; u < 4; u++)
#pragma unroll
                for (int j = 0; j < 4; j++) {
                    const float a = h1[t][u][j];
                    const float b = acc[t][u][j];
                    const int ri = t * 2 + (j >> 1);
                    dotR[ri] = fmaf(a, b, dotR[ri]);
                    n1R[ri]  = fmaf(a, a, n1R[ri]);
                    n2R[ri]  = fmaf(b, b, n2R[ri]);
                }
#pragma unroll
        for (int off = 1; off < 4; off <<= 1) {
#pragma unroll
            for (int ri = 0; ri < 4; ri++) {
                dotR[ri] += __shfl_xor_sync(0xffffffffu, dotR[ri], off);
                n1R[ri]  += __shfl_xor_sync(0xffffffffu, n1R[ri], off);
                n2R[ri]  += __shfl_xor_sync(0xffffffffu, n2R[ri], off);
            }
        }
        if (tg == 0) {
#pragma unroll
            for (int ri = 0; ri < 4; ri++) {
                const int r = wm * 32 + (ri >> 1) * 16 + g + (ri & 1) * 8;
                s_red[0][r][wn] = dotR[ri];
                s_red[1][r][wn] = n1R[ri];
                s_red[2][r][wn] = n2R[ri];
            }
        }
    }

    // ==================== Phase 3: GEMM3 on tensor cores (1-pass) ===========
    float acc3[2][2][4];
#pragma unroll
    for (int t = 0; t < 2; t++)
#pragma unroll
        for (int u = 0; u < 2; u++)
#pragma unroll
            for (int j = 0; j < 4; j++) acc3[t][u][j] = 0.0f;

    const uint32_t aOff3 = ((wm * 32 + ln16) * ST3 + lhalf * 8) * 2;
    const uint32_t bOff3 = (((wn * 16 + (ln16 & 7)) * ST3) + ((ln16 >> 3) * 8)) * 2;
    char* A3 = Areg;                         // 64*136*2 = 17408 <= 18432
    uint32_t A3U = smem_u32(A3);
    uint32_t B3U = smem_u32(Breg);           // 64*136*2 = 17408 <= 36864

    __syncthreads();   // all warps done with phase-2 stages + s_red written

    for (int f = 0; f < 3; f++) {
        // prefetch W3 chunk f (64 x 128 halves)
#pragma unroll
        for (int it = 0; it < 4; it++) {
            int idx = tid + it * 256;
            int n_ = idx >> 4, cc = idx & 15;
            int off = (n_ * ST3 + cc * 8) * 2;
            cpasync16(B3U + off, g_w3 + n_ * 384 + f * 128 + cc * 8);
        }
        cpasync_commit();

        // write combined feature tile into A region (single fp16, stride ST3)
#pragma unroll
        for (int t = 0; t < 2; t++)
#pragma unroll
            for (int u = 0; u < 4; u++) {
                const int col = wn * 32 + u * 8 + tg * 2;
                const int r   = wm * 32 + t * 16 + g;
                float v[4];
#pragma unroll
                for (int j = 0; j < 4; j++) {
                    const float a = h1[t][u][j];
                    const float b = acc[t][u][j];
                    v[j] = (f == 0) ? a * b : (f == 1) ? fabsf(a - b) : a + b;
                }
                *reinterpret_cast<uint32_t*>(A3 + (r * ST3 + col) * 2)       = pack_h2(v[0], v[1]);
                *reinterpret_cast<uint32_t*>(A3 + ((r + 8) * ST3 + col) * 2) = pack_h2(v[2], v[3]);
            }
        cpasync_wait0();
        __syncthreads();

        // MMA over k=128 (8 steps), single pass
#pragma unroll
        for (int ks = 0; ks < 8; ks++) {
            const uint32_t ko = ks * 32;
            uint32_t Ah[2][4], Bh[2][2];
#pragma unroll
            for (int t = 0; t < 2; t++)
                ldmatrix_x4(Ah[t], A3U + aOff3 + (t * 16 * ST3) * 2 + ko);
#pragma unroll
            for (int u = 0; u < 2; u++)
                ldmatrix_x2(Bh[u], B3U + bOff3 + (u * 8 * ST3) * 2 + ko);
#pragma unroll
            for (int t = 0; t < 2; t++)
#pragma unroll
                for (int u = 0; u < 2; u++)
                    mma_f16(acc3[t][u][0], acc3[t][u][1], acc3[t][u][2], acc3[t][u][3],
                            Ah[t][0], Ah[t][1], Ah[t][2], Ah[t][3],
                            Bh[u][0], Bh[u][1]);
        }
        __syncthreads();
    }

    // ==================== Phase 4: relu -> W4 -> head =======================
    {
        float slR[4];
#pragma unroll
        for (int ri = 0; ri < 4; ri++) slR[ri] = 0.0f;
#pragma unroll
        for (int u = 0; u < 2; u++) {
            const int col = wn * 16 + u * 8 + tg * 2;
            const float b30 = b3[col], b31 = b3[col + 1];
            const float w40 = W4[col], w41 = W4[col + 1];
#pragma unroll
            for (int t = 0; t < 2; t++) {
                slR[t * 2 + 0] += fmaxf(acc3[t][u][0] + b30, 0.0f) * w40
                                + fmaxf(acc3[t][u][1] + b31, 0.0f) * w41;
                slR[t * 2 + 1] += fmaxf(acc3[t][u][2] + b30, 0.0f) * w40
                                + fmaxf(acc3[t][u][3] + b31, 0.0f) * w41;
            }
        }
#pragma unroll
        for (int off = 1; off < 4; off <<= 1)
#pragma unroll
            for (int ri = 0; ri < 4; ri++)
                slR[ri] += __shfl_xor_sync(0xffffffffu, slR[ri], off);
        if (tg == 0) {
#pragma unroll
            for (int ri = 0; ri < 4; ri++) {
                const int r = wm * 32 + (ri >> 1) * 16 + g + (ri & 1) * 8;
                s_red[3][r][wn] = slR[ri];
            }
        }
    }
    __syncthreads();

    if (tid < 64) {
        float dot = 0.f, n1v = 0.f, n2v = 0.f, sl = 0.f;
#pragma unroll
        for (int w = 0; w < 4; w++) {
            dot += s_red[0][tid][w];
            n1v += s_red[1][tid][w];
            n2v += s_red[2][tid][w];
            sl  += s_red[3][tid][w];
        }
        const float inv1   = 1.0f / fmaxf(sqrtf(n1v), 1e-15f);
        const float inv2   = 1.0f / fmaxf(sqrtf(n2v), 1e-15f);
        const float s_math = fminf(fmaxf(dot * inv1 * inv2, 0.0f), 1.0f);
        const float sig    = 1.0f / (1.0f + expf(-(sl + b4[0])));
        const float fin    = alphap[0] * s_math + betap[0] * sig;
        out[row0 + tid] = fminf(fmaxf(fin, 0.0f), 1.0f);
    }
#undef F2_LDA
#undef F2_STA
#undef F2_CPB
}

// ---------------------------------------------------------------------------
extern "C" void kernel_launch(void* const* d_in, const int* in_sizes, int n_in,
                              void* d_out, int out_size)
{
    const float* x1      = (const float*)d_in[0];
    const float* x2      = (const float*)d_in[1];
    const float* W1      = (const float*)d_in[2];
    const float* b1      = (const float*)d_in[3];
    const float* gamma   = (const float*)d_in[4];
    const float* beta_bn = (const float*)d_in[5];
    const float* W2      = (const float*)d_in[6];
    const float* b2      = (const float*)d_in[7];
    const float* W3      = (const float*)d_in[8];
    const float* b3      = (const float*)d_in[9];
    const float* W4      = (const float*)d_in[10];
    const float* b4      = (const float*)d_in[11];
    const float* alphap  = (const float*)d_in[12];
    const float* betap   = (const float*)d_in[13];
    float* out = (float*)d_out;

    cudaFuncSetAttribute(gemm1_mma,
                         cudaFuncAttributeMaxDynamicSharedMemorySize, G1_DYN);
    cudaFuncSetAttribute(fused2,
                         cudaFuncAttributeMaxDynamicSharedMemorySize, F2_DYN);

    const int prep_elems = DK * HH + HH * H2 + 384 * O3;
    prep_weights<<<(prep_elems + 255) / 256, 256>>>(W1, W2, W3);

    dim3 g1(NRB1, 2);
    gemm1_mma<<<g1, 256, G1_DYN>>>(x1, x2, b1);

    stats_kernel<<<512, 256>>>(gamma, beta_bn);

    fused2<<<NRB2, 256, F2_DYN>>>(b2, b3, W4, b4, alphap, betap, out);
}